// round 11
// baseline (speedup 1.0000x reference)
#include <cuda_runtime.h>
#include <cuda_bf16.h>
#include <math.h>
#include <stdint.h>

// ---------------- problem constants ----------------
#define B_    2
#define L_    2048
#define DM    1024
#define DI    2048
#define NH    32
#define HD    64
#define DS    128
#define CONVD 2304
#define DPROJ 4384
#define NCH   8
#define CH    256
#define ROWS  4096
#define NBID  (B_ * NCH * NH)   // 512

// ---------------- scratch (device globals) ----------------
__device__ float g_zx[(size_t)ROWS * DPROJ];
__device__ float g_xbc[(size_t)ROWS * CONVD];
__device__ float g_dt[ROWS * NH];
__device__ float g_acs[B_ * NH * NCH * CH];
__device__ float g_states[(size_t)B_ * NCH * NH * HD * DS];
__device__ float g_init[(size_t)B_ * NCH * NH * HD * DS];
__device__ float g_cb[(size_t)B_ * NCH * CH * CH];
__device__ float g_y[(size_t)ROWS * DI];

// packed bf16x2 hi/lo operand arrays
__device__ uint32_t g_uh[ROWS * DM / 2];
__device__ uint32_t g_ul[ROWS * DM / 2];
__device__ uint32_t g_yh[(size_t)ROWS * DI / 2];
__device__ uint32_t g_yl[(size_t)ROWS * DI / 2];
__device__ uint32_t g_wih[(size_t)DPROJ * DM / 2];
__device__ uint32_t g_wil[(size_t)DPROJ * DM / 2];
__device__ uint32_t g_woh[(size_t)DM * DI / 2];
__device__ uint32_t g_wol[(size_t)DM * DI / 2];

// SSD precomputed operands (bf16x2 packed)
__device__ uint32_t g_xdp_h[(size_t)NBID * HD * (CH / 2)];
__device__ uint32_t g_xdp_l[(size_t)NBID * HD * (CH / 2)];
__device__ uint32_t g_xds_h[(size_t)NBID * HD * (CH / 2)];
__device__ uint32_t g_xds_l[(size_t)NBID * HD * (CH / 2)];
__device__ uint32_t g_bmt_h[(size_t)B_ * NCH * DS * (CH / 2)];
__device__ uint32_t g_bmt_l[(size_t)B_ * NCH * DS * (CH / 2)];

// ---------------- helpers ----------------
__device__ __forceinline__ float blockReduceSum256(float v) {
    __shared__ float ws[8];
    __shared__ float tot;
    int lane = threadIdx.x & 31, wid = threadIdx.x >> 5;
#pragma unroll
    for (int o = 16; o; o >>= 1) v += __shfl_xor_sync(0xffffffffu, v, o);
    if (lane == 0) ws[wid] = v;
    __syncthreads();
    if (threadIdx.x == 0) {
        float s = 0.f;
#pragma unroll
        for (int i = 0; i < 8; i++) s += ws[i];
        tot = s;
    }
    __syncthreads();
    return tot;
}

__device__ __forceinline__ uint32_t pack_bf16(float a, float b) {
    __nv_bfloat162 h = __floats2bfloat162_rn(a, b);
    return *(uint32_t*)&h;
}

__device__ __forceinline__ float bf16r(float v) {
    return __bfloat162float(__float2bfloat16(v));
}

__device__ __forceinline__ uint32_t smem_u32(const void* p) {
    uint32_t a;
    asm("{ .reg .u64 t; cvta.to.shared.u64 t, %1; cvt.u32.u64 %0, t; }"
        : "=r"(a) : "l"(p));
    return a;
}

__device__ __forceinline__ void mma_bf16(float* d, const uint32_t* a, const uint32_t* b) {
    asm volatile(
        "mma.sync.aligned.m16n8k16.row.col.f32.bf16.bf16.f32 "
        "{%0,%1,%2,%3}, {%4,%5,%6,%7}, {%8,%9}, {%0,%1,%2,%3};"
        : "+f"(d[0]), "+f"(d[1]), "+f"(d[2]), "+f"(d[3])
        : "r"(a[0]), "r"(a[1]), "r"(a[2]), "r"(a[3]), "r"(b[0]), "r"(b[1]));
}

__device__ __forceinline__ void ldsm4(uint32_t* r, uint32_t addr) {
    asm volatile("ldmatrix.sync.aligned.m8n8.x4.shared.b16 {%0,%1,%2,%3}, [%4];"
                 : "=r"(r[0]), "=r"(r[1]), "=r"(r[2]), "=r"(r[3]) : "r"(addr));
}

__device__ __forceinline__ void cp16(uint32_t dst, const void* src, bool ok) {
    if (ok)
        asm volatile("cp.async.cg.shared.global [%0], [%1], 16;"
                     :: "r"(dst), "l"(src) : "memory");
    else
        asm volatile("cp.async.cg.shared.global [%0], [%1], 16, 0;"
                     :: "r"(dst), "l"(src) : "memory");
}

// ---------------- K0: split fp32 pairs -> bf16 hi/lo packed ----------
__global__ void cvt_pairs_kernel(const float* __restrict__ W,
                                 uint32_t* __restrict__ Wh,
                                 uint32_t* __restrict__ Wl, int npairs) {
    int i = blockIdx.x * blockDim.x + threadIdx.x;
    if (i < npairs) {
        float2 v = ((const float2*)W)[i];
        Wh[i] = pack_bf16(v.x, v.y);
        Wl[i] = pack_bf16(v.x - bf16r(v.x), v.y - bf16r(v.y));
    }
}

// ---------------- K1: rmsnorm(x) -> bf16 hi/lo ----------------
__global__ void rmsnorm_x_kernel(const float* __restrict__ x,
                                 const float* __restrict__ w) {
    int row = blockIdx.x, tid = threadIdx.x;
    const float4 v = ((const float4*)(x + (size_t)row * DM))[tid];
    const float4 wv = ((const float4*)w)[tid];
    float local = v.x * v.x + v.y * v.y + v.z * v.z + v.w * v.w;
    float tot = blockReduceSum256(local);
    float r = rsqrtf(tot / (float)DM + 1e-5f);
    float u0 = v.x * r * wv.x, u1 = v.y * r * wv.y;
    float u2 = v.z * r * wv.z, u3 = v.w * r * wv.w;
    int o = row * (DM / 2) + tid * 2;
    g_uh[o] = pack_bf16(u0, u1);
    g_uh[o + 1] = pack_bf16(u2, u3);
    g_ul[o] = pack_bf16(u0 - bf16r(u0), u1 - bf16r(u1));
    g_ul[o + 1] = pack_bf16(u2 - bf16r(u2), u3 - bf16r(u3));
}

// ------- tensor-core NT GEMM, preconverted bf16 hi/lo, cp.async 2-stage -------
// Term loop hoisted outermost: each acc tile revisited only after 16
// independent mmas (hides HMMA accumulator RAW latency).
#define UPS   (4 * 128 * 20)
#define GSMEM (2 * UPS * 4)
__global__ __launch_bounds__(256) void mma_nt_pre(const uint32_t* __restrict__ Ahg,
                                                  const uint32_t* __restrict__ Alg,
                                                  const uint32_t* __restrict__ Bhg,
                                                  const uint32_t* __restrict__ Blg,
                                                  float* __restrict__ C,
                                                  const float* __restrict__ resid,
                                                  int M, int N, int K, int addRes) {
    extern __shared__ __align__(16) uint32_t S[];
    uint32_t sbase = smem_u32(S);
    int tid = threadIdx.x;
    int warp = tid >> 5, lane = tid & 31;
    int wm = warp & 1, wn = warp >> 1;
    int bm = blockIdx.y * 128, bn = blockIdx.x * 128;
    int g = lane >> 2, tg = lane & 3;
    int K2 = K >> 1;

    int lrow = tid >> 1, lhalf = tid & 1;
    const uint32_t* pA[2] = {Ahg + (size_t)(bm + lrow) * K2 + lhalf * 8,
                             Alg + (size_t)(bm + lrow) * K2 + lhalf * 8};
    bool okB = (bn + lrow) < N;
    int brow = okB ? (bn + lrow) : 0;
    const uint32_t* pB[2] = {Bhg + (size_t)brow * K2 + lhalf * 8,
                             Blg + (size_t)brow * K2 + lhalf * 8};
    uint32_t dto = (uint32_t)(lrow * 20 + lhalf * 8) * 4;

    int mat = lane >> 3, mrow = lane & 7;
    uint32_t a_ad[4], b_ad[2];
#pragma unroll
    for (int mt = 0; mt < 4; mt++) {
        int r = wm * 64 + mt * 16 + (mat & 1) * 8 + mrow;
        a_ad[mt] = sbase + (uint32_t)(r * 20 + (mat >> 1) * 4) * 4;
    }
#pragma unroll
    for (int p = 0; p < 2; p++) {
        int n = wn * 32 + p * 16 + (mat >> 1) * 8 + mrow;
        b_ad[p] = sbase + (uint32_t)(n * 20 + (mat & 1) * 4) * 4;
    }

    float acc[4][4][4];
#pragma unroll
    for (int mt = 0; mt < 4; mt++)
#pragma unroll
        for (int nt = 0; nt < 4; nt++)
#pragma unroll
            for (int q = 0; q < 4; q++) acc[mt][nt][q] = 0.f;

    int nslab = K >> 5;

    auto issue = [&](int st, int sl) {
        int ko = sl * 16;
        uint32_t db = sbase + (uint32_t)(st * UPS) * 4 + dto;
#pragma unroll
        for (int t = 0; t < 2; t++) {
            cp16(db + (uint32_t)(t * 2560 * 4), pA[t] + ko, true);
            cp16(db + (uint32_t)(t * 2560 * 4) + 16, pA[t] + ko + 4, true);
            cp16(db + (uint32_t)((2 + t) * 2560 * 4), pB[t] + ko, okB);
            cp16(db + (uint32_t)((2 + t) * 2560 * 4) + 16, pB[t] + ko + 4, okB);
        }
        asm volatile("cp.async.commit_group;" ::: "memory");
    };

    issue(0, 0);
    int st = 0;
    for (int i = 0; i < nslab; i++) {
        if (i + 1 < nslab) {
            issue(st ^ 1, i + 1);
            asm volatile("cp.async.wait_group 1;" ::: "memory");
        } else {
            asm volatile("cp.async.wait_group 0;" ::: "memory");
        }
        __syncthreads();
        uint32_t so = (uint32_t)(st * UPS) * 4;
#pragma unroll
        for (int kk = 0; kk < 2; kk++) {
            uint32_t kb = so + kk * 32;
            uint32_t ahi[4][4], alo[4][4];
#pragma unroll
            for (int mt = 0; mt < 4; mt++) {
                ldsm4(ahi[mt], a_ad[mt] + kb);
                ldsm4(alo[mt], a_ad[mt] + kb + 2560 * 4);
            }
            uint32_t bhi[4][2], blo[4][2];
#pragma unroll
            for (int p = 0; p < 2; p++) {
                uint32_t t4[4];
                ldsm4(t4, b_ad[p] + kb + 2 * 2560 * 4);
                bhi[p * 2][0] = t4[0]; bhi[p * 2][1] = t4[1];
                bhi[p * 2 + 1][0] = t4[2]; bhi[p * 2 + 1][1] = t4[3];
                ldsm4(t4, b_ad[p] + kb + 3 * 2560 * 4);
                blo[p * 2][0] = t4[0]; blo[p * 2][1] = t4[1];
                blo[p * 2 + 1][0] = t4[2]; blo[p * 2 + 1][1] = t4[3];
            }
            // term-major: 16 independent mmas between accumulator reuses
#pragma unroll
            for (int mt = 0; mt < 4; mt++)
#pragma unroll
                for (int nt = 0; nt < 4; nt++)
                    mma_bf16(acc[mt][nt], ahi[mt], bhi[nt]);
#pragma unroll
            for (int mt = 0; mt < 4; mt++)
#pragma unroll
                for (int nt = 0; nt < 4; nt++)
                    mma_bf16(acc[mt][nt], ahi[mt], blo[nt]);
#pragma unroll
            for (int mt = 0; mt < 4; mt++)
#pragma unroll
                for (int nt = 0; nt < 4; nt++)
                    mma_bf16(acc[mt][nt], alo[mt], bhi[nt]);
        }
        __syncthreads();
        st ^= 1;
    }

#pragma unroll
    for (int mt = 0; mt < 4; mt++) {
        int row = bm + wm * 64 + mt * 16 + g;
#pragma unroll
        for (int nt = 0; nt < 4; nt++) {
            int col = bn + wn * 32 + nt * 8 + tg * 2;
            if (col < N) {
                float* a = acc[mt][nt];
                size_t i0 = (size_t)row * N + col;
                size_t i1 = (size_t)(row + 8) * N + col;
                if (addRes) {
                    a[0] += resid[i0]; a[1] += resid[i0 + 1];
                    a[2] += resid[i1]; a[3] += resid[i1 + 1];
                }
                C[i0] = a[0]; C[i0 + 1] = a[1];
                C[i1] = a[2]; C[i1 + 1] = a[3];
            }
        }
    }
}

// ---------------- K3: depthwise causal conv (width 4) + bias + silu ----------
__global__ void conv_silu_kernel(const float* __restrict__ conv_w,
                                 const float* __restrict__ conv_b) {
    int idx = blockIdx.x * blockDim.x + threadIdx.x;
    int c = idx % CONVD;
    int row = idx / CONVD;
    int l = row & (L_ - 1);
    const float* w = conv_w + c * 4;
    float acc = conv_b[c];
#pragma unroll
    for (int j = 0; j < 4; j++) {
        int ls = l - 3 + j;
        if (ls >= 0)
            acc += w[j] * g_zx[(size_t)(row - 3 + j) * DPROJ + DI + c];
    }
    float s = acc / (1.f + __expf(-acc));
    g_xbc[(size_t)row * CONVD + c] = s;
}

// ---------------- K4: dt = softplus(dt_raw + dt_bias) ----------
__global__ void dt_kernel(const float* __restrict__ dt_bias) {
    int idx = blockIdx.x * blockDim.x + threadIdx.x;
    int h = idx & (NH - 1);
    int row = idx >> 5;
    float v = g_zx[(size_t)row * DPROJ + (DI + CONVD) + h] + dt_bias[h];
    float sp = (v > 20.f) ? v : log1pf(__expf(v));
    g_dt[row * NH + h] = sp;
}

// ---------------- K5: per-chunk cumsum of a = dt * A ----------
__global__ void acs_kernel(const float* __restrict__ A_log) {
    int bid = blockIdx.x;
    int b = bid >> 8, h = (bid >> 3) & 31, c = bid & 7;
    int l = threadIdx.x;
    int row = b * L_ + c * CH + l;
    float A = -__expf(A_log[h]);
    __shared__ float s[CH];
    s[l] = g_dt[row * NH + h] * A;
    __syncthreads();
#pragma unroll
    for (int off = 1; off < CH; off <<= 1) {
        float v = (l >= off) ? s[l - off] : 0.f;
        __syncthreads();
        s[l] += v;
        __syncthreads();
    }
    g_acs[bid * CH + l] = s[l];
}

// ----- K5b: xdT precompute -----
#define XDT_SMEM (256 * 68 * 4)
__global__ __launch_bounds__(256) void xdt_kernel() {
    extern __shared__ float sx[];
    __shared__ float sdt[CH], sdec[CH];
    int bid = blockIdx.x;
    int b = bid >> 8, c = (bid >> 5) & 7, h = bid & 31;
    int tid = threadIdx.x;
    int rowbase = b * L_ + c * CH;
    int base = ((b * NH + h) * NCH + c) * CH;
    float acs255 = g_acs[base + CH - 1];
    {
        int l = tid, row = rowbase + l;
        const float* xr = &g_xbc[(size_t)row * CONVD + h * HD];
#pragma unroll
        for (int p4 = 0; p4 < 16; p4++) {
            float4 v = ((const float4*)xr)[p4];
            *(float4*)&sx[l * 68 + p4 * 4] = v;
        }
        sdt[l] = g_dt[row * NH + h];
        sdec[l] = __expf(acs255 - g_acs[base + l]);
    }
    __syncthreads();
    int warp = tid >> 5, lane = tid & 31;
    size_t ob = (size_t)bid * HD * (CH / 2);
#pragma unroll
    for (int pp = 0; pp < 8; pp++) {
        int p = warp * 8 + pp;
        uint32_t oh[4], ol[4], osh[4], osl[4];
#pragma unroll
        for (int k = 0; k < 4; k++) {
            int cu = lane * 4 + k;
            int l = cu * 2;
            float va = sx[l * 68 + p] * sdt[l];
            float vb = sx[(l + 1) * 68 + p] * sdt[l + 1];
            oh[k] = pack_bf16(va, vb);
            ol[k] = pack_bf16(va - bf16r(va), vb - bf16r(vb));
            float wa = va * sdec[l], wb = vb * sdec[l + 1];
            osh[k] = pack_bf16(wa, wb);
            osl[k] = pack_bf16(wa - bf16r(wa), wb - bf16r(wb));
        }
        size_t o = ob + (size_t)p * (CH / 2) + lane * 4;
        *(uint4*)&g_xdp_h[o] = *(uint4*)oh;
        *(uint4*)&g_xdp_l[o] = *(uint4*)ol;
        *(uint4*)&g_xds_h[o] = *(uint4*)osh;
        *(uint4*)&g_xds_l[o] = *(uint4*)osl;
    }
}

// ----- K5c: Bm^T precompute -----
#define BMT_SMEM (128 * 132 * 4)
__global__ __launch_bounds__(256) void bmt_kernel() {
    extern __shared__ float sx[];
    int z = blockIdx.y, pass = blockIdx.x;
    int b = z >> 3, c = z & 7;
    int tid = threadIdx.x;
    int rowbase = b * L_ + c * CH + pass * 128;
    {
        int l = tid & 127, half = tid >> 7;
        const float* br = &g_xbc[(size_t)(rowbase + l) * CONVD + DI + half * 64];
#pragma unroll
        for (int k4 = 0; k4 < 16; k4++) {
            float4 v = ((const float4*)br)[k4];
            *(float4*)&sx[l * 132 + half * 64 + k4 * 4] = v;
        }
    }
    __syncthreads();
    int warp = tid >> 5, lane = tid & 31;
#pragma unroll
    for (int nn = 0; nn < 16; nn++) {
        int n = warp * 16 + nn;
        uint32_t h2[2], l2[2];
#pragma unroll
        for (int k = 0; k < 2; k++) {
            int cu = lane * 2 + k;
            float va = sx[(2 * cu) * 132 + n];
            float vb = sx[(2 * cu + 1) * 132 + n];
            h2[k] = pack_bf16(va, vb);
            l2[k] = pack_bf16(va - bf16r(va), vb - bf16r(vb));
        }
        size_t o = ((size_t)z * DS + n) * (CH / 2) + pass * 64 + lane * 2;
        *(uint2*)&g_bmt_h[o] = *(uint2*)h2;
        *(uint2*)&g_bmt_l[o] = *(uint2*)l2;
    }
}

// ------ K6 (tensorized): states[n,p] ------
#define SSW 20
#define S_AH 0
#define S_AL (128 * SSW)
#define S_BH (2 * 128 * SSW)
#define S_BL (2 * 128 * SSW + 64 * SSW)
__global__ __launch_bounds__(256) void states_tc_kernel() {
    __shared__ __align__(16) uint32_t S[2 * 128 * SSW + 2 * 64 * SSW];
    uint32_t sb = smem_u32(S);
    int bid = blockIdx.x;
    int b = bid >> 8, c = (bid >> 5) & 7;
    int z = b * NCH + c;
    int tid = threadIdx.x, warp = tid >> 5, lane = tid & 31;
    int wm = warp & 3, wn = warp >> 2;
    int g = lane >> 2, tg = lane & 3;
    int mat = lane >> 3, mrow = lane & 7;

    uint32_t a_adh[2], a_adl[2], b_adh[2], b_adl[2];
#pragma unroll
    for (int mt = 0; mt < 2; mt++) {
        int r = wm * 32 + mt * 16 + (mat & 1) * 8 + mrow;
        uint32_t off = (uint32_t)(r * SSW + (mat >> 1) * 4) * 4;
        a_adh[mt] = sb + S_AH * 4 + off;
        a_adl[mt] = sb + S_AL * 4 + off;
    }
#pragma unroll
    for (int p = 0; p < 2; p++) {
        int n = wn * 32 + p * 16 + (mat >> 1) * 8 + mrow;
        uint32_t off = (uint32_t)(n * SSW + (mat & 1) * 4) * 4;
        b_adh[p] = sb + S_BH * 4 + off;
        b_adl[p] = sb + S_BL * 4 + off;
    }

    float acc[2][4][4];
#pragma unroll
    for (int mt = 0; mt < 2; mt++)
#pragma unroll
        for (int nt = 0; nt < 4; nt++)
#pragma unroll
            for (int q = 0; q < 4; q++) acc[mt][nt][q] = 0.f;

    for (int j = 0; j < 8; j++) {
        __syncthreads();
        {
            int n = tid >> 1, half = tid & 1;
            size_t src = ((size_t)z * DS + n) * (CH / 2) + j * 16 + half * 8;
            uint32_t d = sb + (uint32_t)(S_AH + n * SSW + half * 8) * 4;
            cp16(d, &g_bmt_h[src], true);
            cp16(d + 16, &g_bmt_h[src + 4], true);
            uint32_t d2 = sb + (uint32_t)(S_AL + n * SSW + half * 8) * 4;
            cp16(d2, &g_bmt_l[src], true);
            cp16(d2 + 16, &g_bmt_l[src + 4], true);
        }
        {
            int p = tid >> 2, q = tid & 3;
            size_t src = ((size_t)bid * HD + p) * (CH / 2) + j * 16 + q * 4;
            cp16(sb + (uint32_t)(S_BH + p * SSW + q * 4) * 4, &g_xds_h[src], true);
            cp16(sb + (uint32_t)(S_BL + p * SSW + q * 4) * 4, &g_xds_l[src], true);
        }
        asm volatile("cp.async.commit_group;" ::: "memory");
        asm volatile("cp.async.wait_group 0;" ::: "memory");
        __syncthreads();
#pragma unroll
        for (int kk = 0; kk < 2; kk++) {
            uint32_t kb = kk * 32;
            uint32_t ahi[2][4], alo[2][4];
#pragma unroll
            for (int mt = 0; mt < 2; mt++) {
                ldsm4(ahi[mt], a_adh[mt] + kb);
                ldsm4(alo[mt], a_adl[mt] + kb);
            }
            uint32_t bhi[4][2], blo[4][2];
#pragma unroll
            for (int p = 0; p < 2; p++) {
                uint32_t t4[4];
                ldsm4(t4, b_adh[p] + kb);
                bhi[p * 2][0] = t4[0]; bhi[p * 2][1] = t4[1];
                bhi[p * 2 + 1][0] = t4[2]; bhi[p * 2 + 1][1] = t4[3];
                ldsm4(t4, b_adl[p] + kb);
                blo[p * 2][0] = t4[0]; blo[p * 2][1] = t4[1];
                blo[p * 2 + 1][0] = t4[2]; blo[p * 2 + 1][1] = t4[3];
            }
            // term-major ordering
#pragma unroll
            for (int mt = 0; mt < 2; mt++)
#pragma unroll
                for (int nt = 0; nt < 4; nt++)
                    mma_bf16(acc[mt][nt], ahi[mt], bhi[nt]);
#pragma unroll
            for (int mt = 0; mt < 2; mt++)
#pragma unroll
                for (int nt = 0; nt < 4; nt++)
                    mma_bf16(acc[mt][nt], ahi[mt], blo[nt]);
#pragma unroll
            for (int mt = 0; mt < 2; mt++)
#pragma unroll
                for (int nt = 0; nt < 4; nt++)
                    mma_bf16(acc[mt][nt], alo[mt], bhi[nt]);
        }
    }

    size_t out = (size_t)bid * HD * DS;
#pragma unroll
    for (int mt = 0; mt < 2; mt++) {
#pragma unroll
        for (int nt = 0; nt < 4; nt++) {
            float* a = acc[mt][nt];
#pragma unroll
            for (int q = 0; q < 4; q++) {
                int n = wm * 32 + mt * 16 + g + (q >> 1) * 8;
                int p = wn * 32 + nt * 8 + tg * 2 + (q & 1);
                g_states[out + (size_t)p * DS + n] = a[q];
            }
        }
    }
}

// ---------------- K7: chunk recurrence ----------
__global__ void recur_kernel() {
    int idx = blockIdx.x * blockDim.x + threadIdx.x;
    int n = idx & 127;
    int p = (idx >> 7) & 63;
    int h = (idx >> 13) & 31;
    int b = idx >> 18;
    float run = 0.f;
#pragma unroll
    for (int c = 0; c < NCH; c++) {
        size_t sidx = ((size_t)((b * NCH + c) * NH + h) * HD + p) * DS + n;
        g_init[sidx] = run;
        float cs = g_acs[((b * NH + h) * NCH + c) * CH + CH - 1];
        run = run * __expf(cs) + g_states[sidx];
    }
}

// ---------------- K8: CB[l,s] = Cm[l]·Bm[s] per (b,c) ----------
__global__ __launch_bounds__(256) void cb_kernel() {
    int z = blockIdx.z;
    int b = z >> 3, c = z & 7;
    int l0 = blockIdx.y * 64, s0 = blockIdx.x * 64;
    int tid = threadIdx.x;
    int tx = tid & 15, ty = tid >> 4;
    __shared__ float ct[16][64];
    __shared__ float bt[16][64];
    int rowbase = b * L_ + c * CH;
    float acc[4][4];
#pragma unroll
    for (int i = 0; i < 4; i++)
#pragma unroll
        for (int j = 0; j < 4; j++) acc[i][j] = 0.f;

    for (int k0 = 0; k0 < DS; k0 += 16) {
        __syncthreads();
#pragma unroll
        for (int e = tid; e < 1024; e += 256) {
            int kk = e & 15, i = e >> 4;
            ct[kk][i] = g_xbc[(size_t)(rowbase + l0 + i) * CONVD + DI + DS + k0 + kk];
            bt[kk][i] = g_xbc[(size_t)(rowbase + s0 + i) * CONVD + DI + k0 + kk];
        }
        __syncthreads();
#pragma unroll
        for (int kk = 0; kk < 16; kk++) {
            float4 a4 = *(const float4*)&ct[kk][ty * 4];
            float4 b4 = *(const float4*)&bt[kk][tx * 4];
            float a[4] = {a4.x, a4.y, a4.z, a4.w};
            float bb[4] = {b4.x, b4.y, b4.z, b4.w};
#pragma unroll
            for (int i = 0; i < 4; i++)
#pragma unroll
                for (int j = 0; j < 4; j++) acc[i][j] += a[i] * bb[j];
        }
    }
#pragma unroll
    for (int i = 0; i < 4; i++)
#pragma unroll
        for (int j = 0; j < 4; j++)
            g_cb[((size_t)z * CH + l0 + ty * 4 + i) * CH + s0 + tx * 4 + j] = acc[i][j];
}

// ------ K9 (tensorized, coalesced fills): Y[256,64] ------
#define YW 20
#define YA_H 0
#define YA_L (256 * YW)
#define YB_H (2 * 256 * YW)
#define YB_L (2 * 256 * YW + 64 * YW)
#define YACS (2 * 256 * YW + 2 * 64 * YW)
#define YCF  (YACS + 256)
#define YRF  (YCF + 256)
#define YSMEM ((YRF + 8 * 256) * 4)
__global__ __launch_bounds__(256) void y_tc_kernel(const float* __restrict__ Dvec) {
    extern __shared__ __align__(16) uint32_t S[];
    uint32_t* Ah = S + YA_H;
    uint32_t* Al = S + YA_L;
    uint32_t* Bh = S + YB_H;
    uint32_t* Bl = S + YB_L;
    float* acs_s = (float*)(S + YACS);
    float* cf_s = (float*)(S + YCF);
    float* rfv = (float*)(S + YRF);
    uint32_t sb = smem_u32(S);

    int bid = blockIdx.x;
    int b = bid >> 8, c = (bid >> 5) & 7, h = bid & 31;
    int z = b * NCH + c;
    int tid = threadIdx.x, warp = tid >> 5, lane = tid & 31;
    int wm = warp & 3, wn = warp >> 2;
    int g = lane >> 2, tg = lane & 3;
    int base = ((b * NH + h) * NCH + c) * CH;
    acs_s[tid] = g_acs[base + tid];
    int rowbase = b * L_ + c * CH;
    size_t initbase = (size_t)bid * HD * DS;
    int lr = tid >> 3, cg = tid & 7;

    int mat = lane >> 3, mrow = lane & 7;
    uint32_t a_adh[4], a_adl[4], b_adh[2], b_adl[2];
#pragma unroll
    for (int mt = 0; mt < 4; mt++) {
        int r = wm * 64 + mt * 16 + (mat & 1) * 8 + mrow;
        uint32_t off = (uint32_t)(r * YW + (mat >> 1) * 4) * 4;
        a_adh[mt] = sb + YA_H * 4 + off;
        a_adl[mt] = sb + YA_L * 4 + off;
    }
#pragma unroll
    for (int p = 0; p < 2; p++) {
        int n = wn * 32 + p * 16 + (mat >> 1) * 8 + mrow;
        uint32_t off = (uint32_t)(n * YW + (mat & 1) * 4) * 4;
        b_adh[p] = sb + YB_H * 4 + off;
        b_adl[p] = sb + YB_L * 4 + off;
    }

    float acc[4][4][4];
#pragma unroll
    for (int mt = 0; mt < 4; mt++)
#pragma unroll
        for (int nt = 0; nt < 4; nt++)
#pragma unroll
            for (int q = 0; q < 4; q++) acc[mt][nt][q] = 0.f;

    auto do_mma = [&](void) {
#pragma unroll
        for (int kk = 0; kk < 2; kk++) {
            uint32_t kb = kk * 32;
            uint32_t ahi[4][4], alo[4][4];
#pragma unroll
            for (int mt = 0; mt < 4; mt++) {
                ldsm4(ahi[mt], a_adh[mt] + kb);
                ldsm4(alo[mt], a_adl[mt] + kb);
            }
            uint32_t bhi[4][2], blo[4][2];
#pragma unroll
            for (int p = 0; p < 2; p++) {
                uint32_t t4[4];
                ldsm4(t4, b_adh[p] + kb);
                bhi[p * 2][0] = t4[0]; bhi[p * 2][1] = t4[1];
                bhi[p * 2 + 1][0] = t4[2]; bhi[p * 2 + 1][1] = t4[3];
                ldsm4(t4, b_adl[p] + kb);
                blo[p * 2][0] = t4[0]; blo[p * 2][1] = t4[1];
                blo[p * 2 + 1][0] = t4[2]; blo[p * 2 + 1][1] = t4[3];
            }
            // term-major ordering
#pragma unroll
            for (int mt = 0; mt < 4; mt++)
#pragma unroll
                for (int nt = 0; nt < 4; nt++)
                    mma_bf16(acc[mt][nt], ahi[mt], bhi[nt]);
#pragma unroll
            for (int mt = 0; mt < 4; mt++)
#pragma unroll
                for (int nt = 0; nt < 4; nt++)
                    mma_bf16(acc[mt][nt], ahi[mt], blo[nt]);
#pragma unroll
            for (int mt = 0; mt < 4; mt++)
#pragma unroll
                for (int nt = 0; nt < 4; nt++)
                    mma_bf16(acc[mt][nt], alo[mt], bhi[nt]);
        }
    };

    // ---------------- Phase 1: Cm @ init^T (coalesced fills) ----------
    for (int ks = 0; ks < 4; ks++) {
        __syncthreads();
        {
#pragma unroll
            for (int it = 0; it < 8; it++) {
                int l = it * 32 + lr;
                float4 v = *(const float4*)&g_xbc[(size_t)(rowbase + l) * CONVD +
                                                  DI + DS + ks * 32 + cg * 4];
                uint32_t* dah = &Ah[l * YW + cg * 2];
                uint32_t* dal = &Al[l * YW + cg * 2];
                dah[0] = pack_bf16(v.x, v.y);
                dah[1] = pack_bf16(v.z, v.w);
                dal[0] = pack_bf16(v.x - bf16r(v.x), v.y - bf16r(v.y));
                dal[1] = pack_bf16(v.z - bf16r(v.z), v.w - bf16r(v.w));
            }
        }
        {
            int p = tid >> 2, q0 = tid & 3;
            const float* ir = &g_init[initbase + (size_t)p * DS + ks * 32 + q0 * 8];
            float4 v0 = ((const float4*)ir)[0];
            float4 v1 = ((const float4*)ir)[1];
            uint32_t* dbh = &Bh[p * YW + q0 * 4];
            uint32_t* dbl = &Bl[p * YW + q0 * 4];
            dbh[0] = pack_bf16(v0.x, v0.y);
            dbh[1] = pack_bf16(v0.z, v0.w);
            dbh[2] = pack_bf16(v1.x, v1.y);
            dbh[3] = pack_bf16(v1.z, v1.w);
            dbl[0] = pack_bf16(v0.x - bf16r(v0.x), v0.y - bf16r(v0.y));
            dbl[1] = pack_bf16(v0.z - bf16r(v0.z), v0.w - bf16r(v0.w));
            dbl[2] = pack_bf16(v1.x - bf16r(v1.x), v1.y - bf16r(v1.y));
            dbl[3] = pack_bf16(v1.z - bf16r(v1.z), v1.w - bf16r(v1.w));
        }
        __syncthreads();
        do_mma();
    }

#pragma unroll
    for (int mt = 0; mt < 4; mt++) {
        int r0 = wm * 64 + mt * 16 + g;
        float e0 = __expf(acs_s[r0]);
        float e1 = __expf(acs_s[r0 + 8]);
#pragma unroll
        for (int nt = 0; nt < 4; nt++) {
            acc[mt][nt][0] *= e0; acc[mt][nt][1] *= e0;
            acc[mt][nt][2] *= e1; acc[mt][nt][3] *= e1;
        }
    }

    cf_s[tid] = __expf(acs_s[tid | 31] - acs_s[tid]);
#pragma unroll
    for (int ss = 0; ss < 8; ss++) {
        float v = 0.f;
        if (tid >= ss * 32 + 32) v = __expf(acs_s[tid] - acs_s[ss * 32 + 31]);
        rfv[ss * 256 + tid] = v;
    }

    // ---------------- Phase 2: (CB ∘ L) @ xd^T ----------
    int wlast = wm * 64 + 63;
    for (int ss = 0; ss < 8; ss++) {
        int s0 = ss * 32;
        __syncthreads();
        {
            int p = tid >> 2, q = tid & 3;
            size_t src = ((size_t)bid * HD + p) * (CH / 2) + ss * 16 + q * 4;
            cp16(sb + (uint32_t)(YB_H + p * YW + q * 4) * 4, &g_xdp_h[src], true);
            cp16(sb + (uint32_t)(YB_L + p * YW + q * 4) * 4, &g_xdp_l[src], true);
            asm volatile("cp.async.commit_group;" ::: "memory");
        }
        {
            const float* rfs = &rfv[ss * 256];
#pragma unroll
            for (int it = 0; it < 8; it++) {
                int l = it * 32 + lr;
                uint32_t* dah = &Ah[l * YW + cg * 2];
                uint32_t* dal = &Al[l * YW + cg * 2];
                if (l < s0) {
                    dah[0] = 0u; dah[1] = 0u; dal[0] = 0u; dal[1] = 0u;
                    continue;
                }
                float4 cb4 = *(const float4*)&g_cb[((size_t)z * CH + l) * CH + s0 + cg * 4];
                float va, vb, vc, vd;
                int s = s0 + cg * 4;
                if (l < s0 + 32) {
                    float al = acs_s[l];
                    va = (s <= l) ? cb4.x * __expf(al - acs_s[s]) : 0.f;
                    vb = (s + 1 <= l) ? cb4.y * __expf(al - acs_s[s + 1]) : 0.f;
                    vc = (s + 2 <= l) ? cb4.z * __expf(al - acs_s[s + 2]) : 0.f;
                    vd = (s + 3 <= l) ? cb4.w * __expf(al - acs_s[s + 3]) : 0.f;
                } else {
                    float rf = rfs[l];
                    va = cb4.x * (rf * cf_s[s]);
                    vb = cb4.y * (rf * cf_s[s + 1]);
                    vc = cb4.z * (rf * cf_s[s + 2]);
                    vd = cb4.w * (rf * cf_s[s + 3]);
                }
                dah[0] = pack_bf16(va, vb);
                dah[1] = pack_bf16(vc, vd);
                dal[0] = pack_bf16(va - bf16r(va), vb - bf16r(vb));
                dal[1] = pack_bf16(vc - bf16r(vc), vd - bf16r(vd));
            }
        }
        asm volatile("cp.async.wait_group 0;" ::: "memory");
        __syncthreads();
        if (s0 <= wlast) do_mma();
    }

    // epilogue: + D*xh, write y (fp32)
    float Dh = Dvec[h];
#pragma unroll
    for (int mt = 0; mt < 4; mt++) {
        int r = wm * 64 + mt * 16 + g;
#pragma unroll
        for (int nt = 0; nt < 4; nt++) {
            int p = wn * 32 + nt * 8 + tg * 2;
            float* a = acc[mt][nt];
#pragma unroll
            for (int q = 0; q < 4; q++) {
                int row = rowbase + r + (q >> 1) * 8;
                int pp = p + (q & 1);
                float xh = g_xbc[(size_t)row * CONVD + h * HD + pp];
                g_y[(size_t)row * DI + h * HD + pp] = a[q] + Dh * xh;
            }
        }
    }
}

// -------- K10: gated rmsnorm -> bf16 hi/lo --------
__global__ void gated_norm_kernel(const float* __restrict__ gw) {
    int row = blockIdx.x, tid = threadIdx.x;
    int d0 = tid * 8;
    const float* zr = &g_zx[(size_t)row * DPROJ + d0];
    const float* yr = &g_y[(size_t)row * DI + d0];
    float v[8];
    float local = 0.f;
#pragma unroll
    for (int q = 0; q < 2; q++) {
        float4 z4 = *(const float4*)(zr + q * 4);
        float4 y4 = *(const float4*)(yr + q * 4);
        float zz[4] = {z4.x, z4.y, z4.z, z4.w};
        float yy[4] = {y4.x, y4.y, y4.z, y4.w};
#pragma unroll
        for (int j = 0; j < 4; j++) {
            float t = yy[j] * (zz[j] / (1.f + __expf(-zz[j])));
            v[q * 4 + j] = t;
            local += t * t;
        }
    }
    float tot = blockReduceSum256(local);
    float r = rsqrtf(tot / (float)DI + 1e-5f);
    int o = row * (DI / 2) + tid * 4;
#pragma unroll
    for (int j = 0; j < 4; j++) {
        float a = v[2 * j] * r * gw[d0 + 2 * j];
        float b = v[2 * j + 1] * r * gw[d0 + 2 * j + 1];
        g_yh[o + j] = pack_bf16(a, b);
        g_yl[o + j] = pack_bf16(a - bf16r(a), b - bf16r(b));
    }
}

// ---------------- launch ----------------
extern "C" void kernel_launch(void* const* d_in, const int* in_sizes, int n_in,
                              void* d_out, int out_size) {
    const float* x         = (const float*)d_in[0];
    const float* norm_w    = (const float*)d_in[1];
    const float* in_proj_w = (const float*)d_in[2];
    const float* conv_w    = (const float*)d_in[3];
    const float* conv_b    = (const float*)d_in[4];
    const float* dt_bias   = (const float*)d_in[5];
    const float* A_log     = (const float*)d_in[6];
    const float* Dv        = (const float*)d_in[7];
    const float* gnorm_w   = (const float*)d_in[8];
    const float* out_proj_w= (const float*)d_in[9];
    float* out = (float*)d_out;

    float *pzx;
    uint32_t *puh, *pul, *pyh, *pyl, *pwih, *pwil, *pwoh, *pwol;
    cudaGetSymbolAddress((void**)&pzx, g_zx);
    cudaGetSymbolAddress((void**)&puh, g_uh);
    cudaGetSymbolAddress((void**)&pul, g_ul);
    cudaGetSymbolAddress((void**)&pyh, g_yh);
    cudaGetSymbolAddress((void**)&pyl, g_yl);
    cudaGetSymbolAddress((void**)&pwih, g_wih);
    cudaGetSymbolAddress((void**)&pwil, g_wil);
    cudaGetSymbolAddress((void**)&pwoh, g_woh);
    cudaGetSymbolAddress((void**)&pwol, g_wol);

    cudaFuncSetAttribute(mma_nt_pre, cudaFuncAttributeMaxDynamicSharedMemorySize, GSMEM);
    cudaFuncSetAttribute(y_tc_kernel, cudaFuncAttributeMaxDynamicSharedMemorySize, YSMEM);
    cudaFuncSetAttribute(xdt_kernel, cudaFuncAttributeMaxDynamicSharedMemorySize, XDT_SMEM);
    cudaFuncSetAttribute(bmt_kernel, cudaFuncAttributeMaxDynamicSharedMemorySize, BMT_SMEM);

    cvt_pairs_kernel<<<(DPROJ * DM / 2 + 255) / 256, 256>>>(in_proj_w, pwih, pwil,
                                                            DPROJ * DM / 2);
    cvt_pairs_kernel<<<(DM * DI / 2 + 255) / 256, 256>>>(out_proj_w, pwoh, pwol,
                                                         DM * DI / 2);

    rmsnorm_x_kernel<<<ROWS, 256>>>(x, norm_w);
    mma_nt_pre<<<dim3((DPROJ + 127) / 128, ROWS / 128), 256, GSMEM>>>(
        puh, pul, pwih, pwil, pzx, nullptr, ROWS, DPROJ, DM, 0);
    conv_silu_kernel<<<(ROWS * CONVD) / 256, 256>>>(conv_w, conv_b);
    dt_kernel<<<(ROWS * NH) / 256, 256>>>(dt_bias);
    acs_kernel<<<B_ * NH * NCH, 256>>>(A_log);
    xdt_kernel<<<NBID, 256, XDT_SMEM>>>();
    bmt_kernel<<<dim3(2, B_ * NCH), 256, BMT_SMEM>>>();
    states_tc_kernel<<<NBID, 256>>>();
    recur_kernel<<<(B_ * NH * HD * DS) / 256, 256>>>();
    cb_kernel<<<dim3(4, 4, B_ * NCH), 256>>>();
    y_tc_kernel<<<NBID, 256, YSMEM>>>(Dv);
    gated_norm_kernel<<<ROWS, 256>>>(gnorm_w);
    mma_nt_pre<<<dim3(DM / 128, ROWS / 128), 256, GSMEM>>>(
        pyh, pyl, pwoh, pwol, out, x, ROWS, DM, DI, 1);
}

// round 12
// speedup vs baseline: 1.0336x; 1.0336x over previous
#include <cuda_runtime.h>
#include <cuda_bf16.h>
#include <math.h>
#include <stdint.h>

// ---------------- problem constants ----------------
#define B_    2
#define L_    2048
#define DM    1024
#define DI    2048
#define NH    32
#define HD    64
#define DS    128
#define CONVD 2304
#define DPROJ 4384
#define NCH   8
#define CH    256
#define ROWS  4096
#define NBID  (B_ * NCH * NH)   // 512

// ---------------- scratch (device globals) ----------------
__device__ float g_zx[(size_t)ROWS * DPROJ];
__device__ float g_xbc[(size_t)ROWS * CONVD];
__device__ float g_dt[ROWS * NH];
__device__ float g_acs[B_ * NH * NCH * CH];
__device__ float g_states[(size_t)B_ * NCH * NH * HD * DS];
__device__ float g_init[(size_t)B_ * NCH * NH * HD * DS];
__device__ float g_cb[(size_t)B_ * NCH * CH * CH];
__device__ float g_y[(size_t)ROWS * DI];

// packed bf16x2 hi/lo operand arrays
__device__ uint32_t g_uh[ROWS * DM / 2];
__device__ uint32_t g_ul[ROWS * DM / 2];
__device__ uint32_t g_yh[(size_t)ROWS * DI / 2];
__device__ uint32_t g_yl[(size_t)ROWS * DI / 2];
__device__ uint32_t g_wih[(size_t)DPROJ * DM / 2];
__device__ uint32_t g_wil[(size_t)DPROJ * DM / 2];
__device__ uint32_t g_woh[(size_t)DM * DI / 2];
__device__ uint32_t g_wol[(size_t)DM * DI / 2];

// SSD precomputed operands (bf16x2 packed)
__device__ uint32_t g_xdp_h[(size_t)NBID * HD * (CH / 2)];
__device__ uint32_t g_xdp_l[(size_t)NBID * HD * (CH / 2)];
__device__ uint32_t g_xds_h[(size_t)NBID * HD * (CH / 2)];
__device__ uint32_t g_xds_l[(size_t)NBID * HD * (CH / 2)];
__device__ uint32_t g_bmt_h[(size_t)B_ * NCH * DS * (CH / 2)];
__device__ uint32_t g_bmt_l[(size_t)B_ * NCH * DS * (CH / 2)];
// row-major Bm/Cm bf16 hi/lo for CB gemm: [row][n/2]
__device__ uint32_t g_bm2_h[(size_t)ROWS * 64];
__device__ uint32_t g_bm2_l[(size_t)ROWS * 64];
__device__ uint32_t g_cm2_h[(size_t)ROWS * 64];
__device__ uint32_t g_cm2_l[(size_t)ROWS * 64];

// ---------------- helpers ----------------
__device__ __forceinline__ float blockReduceSum256(float v) {
    __shared__ float ws[8];
    __shared__ float tot;
    int lane = threadIdx.x & 31, wid = threadIdx.x >> 5;
#pragma unroll
    for (int o = 16; o; o >>= 1) v += __shfl_xor_sync(0xffffffffu, v, o);
    if (lane == 0) ws[wid] = v;
    __syncthreads();
    if (threadIdx.x == 0) {
        float s = 0.f;
#pragma unroll
        for (int i = 0; i < 8; i++) s += ws[i];
        tot = s;
    }
    __syncthreads();
    return tot;
}

__device__ __forceinline__ uint32_t pack_bf16(float a, float b) {
    __nv_bfloat162 h = __floats2bfloat162_rn(a, b);
    return *(uint32_t*)&h;
}

__device__ __forceinline__ float bf16r(float v) {
    return __bfloat162float(__float2bfloat16(v));
}

__device__ __forceinline__ uint32_t smem_u32(const void* p) {
    uint32_t a;
    asm("{ .reg .u64 t; cvta.to.shared.u64 t, %1; cvt.u32.u64 %0, t; }"
        : "=r"(a) : "l"(p));
    return a;
}

__device__ __forceinline__ void mma_bf16(float* d, const uint32_t* a, const uint32_t* b) {
    asm volatile(
        "mma.sync.aligned.m16n8k16.row.col.f32.bf16.bf16.f32 "
        "{%0,%1,%2,%3}, {%4,%5,%6,%7}, {%8,%9}, {%0,%1,%2,%3};"
        : "+f"(d[0]), "+f"(d[1]), "+f"(d[2]), "+f"(d[3])
        : "r"(a[0]), "r"(a[1]), "r"(a[2]), "r"(a[3]), "r"(b[0]), "r"(b[1]));
}

__device__ __forceinline__ void ldsm4(uint32_t* r, uint32_t addr) {
    asm volatile("ldmatrix.sync.aligned.m8n8.x4.shared.b16 {%0,%1,%2,%3}, [%4];"
                 : "=r"(r[0]), "=r"(r[1]), "=r"(r[2]), "=r"(r[3]) : "r"(addr));
}

__device__ __forceinline__ void cp16(uint32_t dst, const void* src, bool ok) {
    if (ok)
        asm volatile("cp.async.cg.shared.global [%0], [%1], 16;"
                     :: "r"(dst), "l"(src) : "memory");
    else
        asm volatile("cp.async.cg.shared.global [%0], [%1], 16, 0;"
                     :: "r"(dst), "l"(src) : "memory");
}

// ---------------- K0: split fp32 pairs -> bf16 hi/lo packed ----------
__global__ void cvt_pairs_kernel(const float* __restrict__ W,
                                 uint32_t* __restrict__ Wh,
                                 uint32_t* __restrict__ Wl, int npairs) {
    int i = blockIdx.x * blockDim.x + threadIdx.x;
    if (i < npairs) {
        float2 v = ((const float2*)W)[i];
        Wh[i] = pack_bf16(v.x, v.y);
        Wl[i] = pack_bf16(v.x - bf16r(v.x), v.y - bf16r(v.y));
    }
}

// ---------------- K1: rmsnorm(x) -> bf16 hi/lo ----------------
__global__ void rmsnorm_x_kernel(const float* __restrict__ x,
                                 const float* __restrict__ w) {
    int row = blockIdx.x, tid = threadIdx.x;
    const float4 v = ((const float4*)(x + (size_t)row * DM))[tid];
    const float4 wv = ((const float4*)w)[tid];
    float local = v.x * v.x + v.y * v.y + v.z * v.z + v.w * v.w;
    float tot = blockReduceSum256(local);
    float r = rsqrtf(tot / (float)DM + 1e-5f);
    float u0 = v.x * r * wv.x, u1 = v.y * r * wv.y;
    float u2 = v.z * r * wv.z, u3 = v.w * r * wv.w;
    int o = row * (DM / 2) + tid * 2;
    g_uh[o] = pack_bf16(u0, u1);
    g_uh[o + 1] = pack_bf16(u2, u3);
    g_ul[o] = pack_bf16(u0 - bf16r(u0), u1 - bf16r(u1));
    g_ul[o + 1] = pack_bf16(u2 - bf16r(u2), u3 - bf16r(u3));
}

// ------- tensor-core NT GEMM, preconverted bf16 hi/lo, cp.async 2-stage -------
#define UPS   (4 * 128 * 20)
#define GSMEM (2 * UPS * 4)
__global__ __launch_bounds__(256) void mma_nt_pre(const uint32_t* __restrict__ Ahg,
                                                  const uint32_t* __restrict__ Alg,
                                                  const uint32_t* __restrict__ Bhg,
                                                  const uint32_t* __restrict__ Blg,
                                                  float* __restrict__ C,
                                                  const float* __restrict__ resid,
                                                  int M, int N, int K, int addRes) {
    extern __shared__ __align__(16) uint32_t S[];
    uint32_t sbase = smem_u32(S);
    int tid = threadIdx.x;
    int warp = tid >> 5, lane = tid & 31;
    int wm = warp & 1, wn = warp >> 1;
    int bm = blockIdx.y * 128, bn = blockIdx.x * 128;
    int g = lane >> 2, tg = lane & 3;
    int K2 = K >> 1;

    int lrow = tid >> 1, lhalf = tid & 1;
    const uint32_t* pA[2] = {Ahg + (size_t)(bm + lrow) * K2 + lhalf * 8,
                             Alg + (size_t)(bm + lrow) * K2 + lhalf * 8};
    bool okB = (bn + lrow) < N;
    int brow = okB ? (bn + lrow) : 0;
    const uint32_t* pB[2] = {Bhg + (size_t)brow * K2 + lhalf * 8,
                             Blg + (size_t)brow * K2 + lhalf * 8};
    uint32_t dto = (uint32_t)(lrow * 20 + lhalf * 8) * 4;

    int mat = lane >> 3, mrow = lane & 7;
    uint32_t a_ad[4], b_ad[2];
#pragma unroll
    for (int mt = 0; mt < 4; mt++) {
        int r = wm * 64 + mt * 16 + (mat & 1) * 8 + mrow;
        a_ad[mt] = sbase + (uint32_t)(r * 20 + (mat >> 1) * 4) * 4;
    }
#pragma unroll
    for (int p = 0; p < 2; p++) {
        int n = wn * 32 + p * 16 + (mat >> 1) * 8 + mrow;
        b_ad[p] = sbase + (uint32_t)(n * 20 + (mat & 1) * 4) * 4;
    }

    float acc[4][4][4];
#pragma unroll
    for (int mt = 0; mt < 4; mt++)
#pragma unroll
        for (int nt = 0; nt < 4; nt++)
#pragma unroll
            for (int q = 0; q < 4; q++) acc[mt][nt][q] = 0.f;

    int nslab = K >> 5;

    auto issue = [&](int st, int sl) {
        int ko = sl * 16;
        uint32_t db = sbase + (uint32_t)(st * UPS) * 4 + dto;
#pragma unroll
        for (int t = 0; t < 2; t++) {
            cp16(db + (uint32_t)(t * 2560 * 4), pA[t] + ko, true);
            cp16(db + (uint32_t)(t * 2560 * 4) + 16, pA[t] + ko + 4, true);
            cp16(db + (uint32_t)((2 + t) * 2560 * 4), pB[t] + ko, okB);
            cp16(db + (uint32_t)((2 + t) * 2560 * 4) + 16, pB[t] + ko + 4, okB);
        }
        asm volatile("cp.async.commit_group;" ::: "memory");
    };

    issue(0, 0);
    int st = 0;
    for (int i = 0; i < nslab; i++) {
        if (i + 1 < nslab) {
            issue(st ^ 1, i + 1);
            asm volatile("cp.async.wait_group 1;" ::: "memory");
        } else {
            asm volatile("cp.async.wait_group 0;" ::: "memory");
        }
        __syncthreads();
        uint32_t so = (uint32_t)(st * UPS) * 4;
#pragma unroll
        for (int kk = 0; kk < 2; kk++) {
            uint32_t kb = so + kk * 32;
            uint32_t ahi[4][4], alo[4][4];
#pragma unroll
            for (int mt = 0; mt < 4; mt++) {
                ldsm4(ahi[mt], a_ad[mt] + kb);
                ldsm4(alo[mt], a_ad[mt] + kb + 2560 * 4);
            }
            uint32_t bhi[4][2], blo[4][2];
#pragma unroll
            for (int p = 0; p < 2; p++) {
                uint32_t t4[4];
                ldsm4(t4, b_ad[p] + kb + 2 * 2560 * 4);
                bhi[p * 2][0] = t4[0]; bhi[p * 2][1] = t4[1];
                bhi[p * 2 + 1][0] = t4[2]; bhi[p * 2 + 1][1] = t4[3];
                ldsm4(t4, b_ad[p] + kb + 3 * 2560 * 4);
                blo[p * 2][0] = t4[0]; blo[p * 2][1] = t4[1];
                blo[p * 2 + 1][0] = t4[2]; blo[p * 2 + 1][1] = t4[3];
            }
#pragma unroll
            for (int mt = 0; mt < 4; mt++)
#pragma unroll
                for (int nt = 0; nt < 4; nt++) {
                    mma_bf16(acc[mt][nt], ahi[mt], bhi[nt]);
                    mma_bf16(acc[mt][nt], ahi[mt], blo[nt]);
                    mma_bf16(acc[mt][nt], alo[mt], bhi[nt]);
                }
        }
        __syncthreads();
        st ^= 1;
    }

#pragma unroll
    for (int mt = 0; mt < 4; mt++) {
        int row = bm + wm * 64 + mt * 16 + g;
#pragma unroll
        for (int nt = 0; nt < 4; nt++) {
            int col = bn + wn * 32 + nt * 8 + tg * 2;
            if (col < N) {
                float* a = acc[mt][nt];
                size_t i0 = (size_t)row * N + col;
                size_t i1 = (size_t)(row + 8) * N + col;
                if (addRes) {
                    a[0] += resid[i0]; a[1] += resid[i0 + 1];
                    a[2] += resid[i1]; a[3] += resid[i1 + 1];
                }
                C[i0] = a[0]; C[i0 + 1] = a[1];
                C[i1] = a[2]; C[i1 + 1] = a[3];
            }
        }
    }
}

// ---------------- K3: depthwise causal conv (width 4) + bias + silu ----------
__global__ void conv_silu_kernel(const float* __restrict__ conv_w,
                                 const float* __restrict__ conv_b) {
    int idx = blockIdx.x * blockDim.x + threadIdx.x;
    int c = idx % CONVD;
    int row = idx / CONVD;
    int l = row & (L_ - 1);
    const float* w = conv_w + c * 4;
    float acc = conv_b[c];
#pragma unroll
    for (int j = 0; j < 4; j++) {
        int ls = l - 3 + j;
        if (ls >= 0)
            acc += w[j] * g_zx[(size_t)(row - 3 + j) * DPROJ + DI + c];
    }
    float s = acc / (1.f + __expf(-acc));
    g_xbc[(size_t)row * CONVD + c] = s;
}

// ---------------- K4: dt = softplus(dt_raw + dt_bias) ----------
__global__ void dt_kernel(const float* __restrict__ dt_bias) {
    int idx = blockIdx.x * blockDim.x + threadIdx.x;
    int h = idx & (NH - 1);
    int row = idx >> 5;
    float v = g_zx[(size_t)row * DPROJ + (DI + CONVD) + h] + dt_bias[h];
    float sp = (v > 20.f) ? v : log1pf(__expf(v));
    g_dt[row * NH + h] = sp;
}

// ---------------- K5: per-chunk cumsum of a = dt * A ----------
__global__ void acs_kernel(const float* __restrict__ A_log) {
    int bid = blockIdx.x;
    int b = bid >> 8, h = (bid >> 3) & 31, c = bid & 7;
    int l = threadIdx.x;
    int row = b * L_ + c * CH + l;
    float A = -__expf(A_log[h]);
    __shared__ float s[CH];
    s[l] = g_dt[row * NH + h] * A;
    __syncthreads();
#pragma unroll
    for (int off = 1; off < CH; off <<= 1) {
        float v = (l >= off) ? s[l - off] : 0.f;
        __syncthreads();
        s[l] += v;
        __syncthreads();
    }
    g_acs[bid * CH + l] = s[l];
}

// ----- K5b: xdT precompute -----
#define XDT_SMEM (256 * 68 * 4)
__global__ __launch_bounds__(256) void xdt_kernel() {
    extern __shared__ float sx[];
    __shared__ float sdt[CH], sdec[CH];
    int bid = blockIdx.x;
    int b = bid >> 8, c = (bid >> 5) & 7, h = bid & 31;
    int tid = threadIdx.x;
    int rowbase = b * L_ + c * CH;
    int base = ((b * NH + h) * NCH + c) * CH;
    float acs255 = g_acs[base + CH - 1];
    {
        int l = tid, row = rowbase + l;
        const float* xr = &g_xbc[(size_t)row * CONVD + h * HD];
#pragma unroll
        for (int p4 = 0; p4 < 16; p4++) {
            float4 v = ((const float4*)xr)[p4];
            *(float4*)&sx[l * 68 + p4 * 4] = v;
        }
        sdt[l] = g_dt[row * NH + h];
        sdec[l] = __expf(acs255 - g_acs[base + l]);
    }
    __syncthreads();
    int warp = tid >> 5, lane = tid & 31;
    size_t ob = (size_t)bid * HD * (CH / 2);
#pragma unroll
    for (int pp = 0; pp < 8; pp++) {
        int p = warp * 8 + pp;
        uint32_t oh[4], ol[4], osh[4], osl[4];
#pragma unroll
        for (int k = 0; k < 4; k++) {
            int cu = lane * 4 + k;
            int l = cu * 2;
            float va = sx[l * 68 + p] * sdt[l];
            float vb = sx[(l + 1) * 68 + p] * sdt[l + 1];
            oh[k] = pack_bf16(va, vb);
            ol[k] = pack_bf16(va - bf16r(va), vb - bf16r(vb));
            float wa = va * sdec[l], wb = vb * sdec[l + 1];
            osh[k] = pack_bf16(wa, wb);
            osl[k] = pack_bf16(wa - bf16r(wa), wb - bf16r(wb));
        }
        size_t o = ob + (size_t)p * (CH / 2) + lane * 4;
        *(uint4*)&g_xdp_h[o] = *(uint4*)oh;
        *(uint4*)&g_xdp_l[o] = *(uint4*)ol;
        *(uint4*)&g_xds_h[o] = *(uint4*)osh;
        *(uint4*)&g_xds_l[o] = *(uint4*)osl;
    }
}

// ----- K5c: Bm^T precompute -----
#define BMT_SMEM (128 * 132 * 4)
__global__ __launch_bounds__(256) void bmt_kernel() {
    extern __shared__ float sx[];
    int z = blockIdx.y, pass = blockIdx.x;
    int b = z >> 3, c = z & 7;
    int tid = threadIdx.x;
    int rowbase = b * L_ + c * CH + pass * 128;
    {
        int l = tid & 127, half = tid >> 7;
        const float* br = &g_xbc[(size_t)(rowbase + l) * CONVD + DI + half * 64];
#pragma unroll
        for (int k4 = 0; k4 < 16; k4++) {
            float4 v = ((const float4*)br)[k4];
            *(float4*)&sx[l * 132 + half * 64 + k4 * 4] = v;
        }
    }
    __syncthreads();
    int warp = tid >> 5, lane = tid & 31;
#pragma unroll
    for (int nn = 0; nn < 16; nn++) {
        int n = warp * 16 + nn;
        uint32_t h2[2], l2[2];
#pragma unroll
        for (int k = 0; k < 2; k++) {
            int cu = lane * 2 + k;
            float va = sx[(2 * cu) * 132 + n];
            float vb = sx[(2 * cu + 1) * 132 + n];
            h2[k] = pack_bf16(va, vb);
            l2[k] = pack_bf16(va - bf16r(va), vb - bf16r(vb));
        }
        size_t o = ((size_t)z * DS + n) * (CH / 2) + pass * 64 + lane * 2;
        *(uint2*)&g_bmt_h[o] = *(uint2*)h2;
        *(uint2*)&g_bmt_l[o] = *(uint2*)l2;
    }
}

// ----- K5d: row-major Bm/Cm bf16 hi/lo (for CB gemm) -----
__global__ void cvt_bc_kernel() {
    int row = blockIdx.x;
    int tid = threadIdx.x;  // 128
    int which = tid >> 6, n2 = tid & 63;
    float2 v = *(const float2*)&g_xbc[(size_t)row * CONVD + DI + which * DS + n2 * 2];
    uint32_t hh = pack_bf16(v.x, v.y);
    uint32_t ll = pack_bf16(v.x - bf16r(v.x), v.y - bf16r(v.y));
    size_t o = (size_t)row * 64 + n2;
    if (which == 0) { g_bm2_h[o] = hh; g_bm2_l[o] = ll; }
    else            { g_cm2_h[o] = hh; g_cm2_l[o] = ll; }
}

// ------ K6 (tensorized): states[n,p] ------
#define SSW 20
#define S_AH 0
#define S_AL (128 * SSW)
#define S_BH (2 * 128 * SSW)
#define S_BL (2 * 128 * SSW + 64 * SSW)
__global__ __launch_bounds__(256) void states_tc_kernel() {
    __shared__ __align__(16) uint32_t S[2 * 128 * SSW + 2 * 64 * SSW];
    uint32_t sb = smem_u32(S);
    int bid = blockIdx.x;
    int b = bid >> 8, c = (bid >> 5) & 7;
    int z = b * NCH + c;
    int tid = threadIdx.x, warp = tid >> 5, lane = tid & 31;
    int wm = warp & 3, wn = warp >> 2;
    int g = lane >> 2, tg = lane & 3;
    int mat = lane >> 3, mrow = lane & 7;

    uint32_t a_adh[2], a_adl[2], b_adh[2], b_adl[2];
#pragma unroll
    for (int mt = 0; mt < 2; mt++) {
        int r = wm * 32 + mt * 16 + (mat & 1) * 8 + mrow;
        uint32_t off = (uint32_t)(r * SSW + (mat >> 1) * 4) * 4;
        a_adh[mt] = sb + S_AH * 4 + off;
        a_adl[mt] = sb + S_AL * 4 + off;
    }
#pragma unroll
    for (int p = 0; p < 2; p++) {
        int n = wn * 32 + p * 16 + (mat >> 1) * 8 + mrow;
        uint32_t off = (uint32_t)(n * SSW + (mat & 1) * 4) * 4;
        b_adh[p] = sb + S_BH * 4 + off;
        b_adl[p] = sb + S_BL * 4 + off;
    }

    float acc[2][4][4];
#pragma unroll
    for (int mt = 0; mt < 2; mt++)
#pragma unroll
        for (int nt = 0; nt < 4; nt++)
#pragma unroll
            for (int q = 0; q < 4; q++) acc[mt][nt][q] = 0.f;

    for (int j = 0; j < 8; j++) {
        __syncthreads();
        {
            int n = tid >> 1, half = tid & 1;
            size_t src = ((size_t)z * DS + n) * (CH / 2) + j * 16 + half * 8;
            uint32_t d = sb + (uint32_t)(S_AH + n * SSW + half * 8) * 4;
            cp16(d, &g_bmt_h[src], true);
            cp16(d + 16, &g_bmt_h[src + 4], true);
            uint32_t d2 = sb + (uint32_t)(S_AL + n * SSW + half * 8) * 4;
            cp16(d2, &g_bmt_l[src], true);
            cp16(d2 + 16, &g_bmt_l[src + 4], true);
        }
        {
            int p = tid >> 2, q = tid & 3;
            size_t src = ((size_t)bid * HD + p) * (CH / 2) + j * 16 + q * 4;
            cp16(sb + (uint32_t)(S_BH + p * SSW + q * 4) * 4, &g_xds_h[src], true);
            cp16(sb + (uint32_t)(S_BL + p * SSW + q * 4) * 4, &g_xds_l[src], true);
        }
        asm volatile("cp.async.commit_group;" ::: "memory");
        asm volatile("cp.async.wait_group 0;" ::: "memory");
        __syncthreads();
#pragma unroll
        for (int kk = 0; kk < 2; kk++) {
            uint32_t kb = kk * 32;
            uint32_t ahi[2][4], alo[2][4];
#pragma unroll
            for (int mt = 0; mt < 2; mt++) {
                ldsm4(ahi[mt], a_adh[mt] + kb);
                ldsm4(alo[mt], a_adl[mt] + kb);
            }
            uint32_t bhi[4][2], blo[4][2];
#pragma unroll
            for (int p = 0; p < 2; p++) {
                uint32_t t4[4];
                ldsm4(t4, b_adh[p] + kb);
                bhi[p * 2][0] = t4[0]; bhi[p * 2][1] = t4[1];
                bhi[p * 2 + 1][0] = t4[2]; bhi[p * 2 + 1][1] = t4[3];
                ldsm4(t4, b_adl[p] + kb);
                blo[p * 2][0] = t4[0]; blo[p * 2][1] = t4[1];
                blo[p * 2 + 1][0] = t4[2]; blo[p * 2 + 1][1] = t4[3];
            }
#pragma unroll
            for (int mt = 0; mt < 2; mt++)
#pragma unroll
                for (int nt = 0; nt < 4; nt++) {
                    mma_bf16(acc[mt][nt], ahi[mt], bhi[nt]);
                    mma_bf16(acc[mt][nt], ahi[mt], blo[nt]);
                    mma_bf16(acc[mt][nt], alo[mt], bhi[nt]);
                }
        }
    }

    size_t out = (size_t)bid * HD * DS;
#pragma unroll
    for (int mt = 0; mt < 2; mt++) {
#pragma unroll
        for (int nt = 0; nt < 4; nt++) {
            float* a = acc[mt][nt];
#pragma unroll
            for (int q = 0; q < 4; q++) {
                int n = wm * 32 + mt * 16 + g + (q >> 1) * 8;
                int p = wn * 32 + nt * 8 + tg * 2 + (q & 1);
                g_states[out + (size_t)p * DS + n] = a[q];
            }
        }
    }
}

// ---------------- K7: chunk recurrence ----------
__global__ void recur_kernel() {
    int idx = blockIdx.x * blockDim.x + threadIdx.x;
    int n = idx & 127;
    int p = (idx >> 7) & 63;
    int h = (idx >> 13) & 31;
    int b = idx >> 18;
    float run = 0.f;
#pragma unroll
    for (int c = 0; c < NCH; c++) {
        size_t sidx = ((size_t)((b * NCH + c) * NH + h) * HD + p) * DS + n;
        g_init[sidx] = run;
        float cs = g_acs[((b * NH + h) * NCH + c) * CH + CH - 1];
        run = run * __expf(cs) + g_states[sidx];
    }
}

// ------ K8 (tensorized): CB[l,s] = Cm[l]·Bm[s], 128x128x128 tiles ------
#define CBW 20
#define C_AH 0
#define C_AL (128 * CBW)
#define C_BH (2 * 128 * CBW)
#define C_BL (3 * 128 * CBW)
__global__ __launch_bounds__(256) void cb_tc_kernel() {
    __shared__ __align__(16) uint32_t S[4 * 128 * CBW];
    uint32_t sb = smem_u32(S);
    int z = blockIdx.z;
    int b = z >> 3, c = z & 7;
    int l0 = blockIdx.y * 128, s0 = blockIdx.x * 128;
    int rowbase = b * L_ + c * CH;
    int tid = threadIdx.x, warp = tid >> 5, lane = tid & 31;
    int wm = warp & 1, wn = warp >> 1;
    int g = lane >> 2, tg = lane & 3;
    int mat = lane >> 3, mrow = lane & 7;

    uint32_t a_adh[4], a_adl[4], b_adh[2], b_adl[2];
#pragma unroll
    for (int mt = 0; mt < 4; mt++) {
        int r = wm * 64 + mt * 16 + (mat & 1) * 8 + mrow;
        uint32_t off = (uint32_t)(r * CBW + (mat >> 1) * 4) * 4;
        a_adh[mt] = sb + C_AH * 4 + off;
        a_adl[mt] = sb + C_AL * 4 + off;
    }
#pragma unroll
    for (int p = 0; p < 2; p++) {
        int n = wn * 32 + p * 16 + (mat >> 1) * 8 + mrow;
        uint32_t off = (uint32_t)(n * CBW + (mat & 1) * 4) * 4;
        b_adh[p] = sb + C_BH * 4 + off;
        b_adl[p] = sb + C_BL * 4 + off;
    }

    float acc[4][4][4];
#pragma unroll
    for (int mt = 0; mt < 4; mt++)
#pragma unroll
        for (int nt = 0; nt < 4; nt++)
#pragma unroll
            for (int q = 0; q < 4; q++) acc[mt][nt][q] = 0.f;

    for (int ks = 0; ks < 4; ks++) {
        __syncthreads();
        {
            int r = tid >> 1, half = tid & 1;
            size_t asrc = (size_t)(rowbase + l0 + r) * 64 + ks * 16 + half * 8;
            uint32_t d = sb + (uint32_t)(C_AH + r * CBW + half * 8) * 4;
            cp16(d, &g_cm2_h[asrc], true);
            cp16(d + 16, &g_cm2_h[asrc + 4], true);
            uint32_t d2 = sb + (uint32_t)(C_AL + r * CBW + half * 8) * 4;
            cp16(d2, &g_cm2_l[asrc], true);
            cp16(d2 + 16, &g_cm2_l[asrc + 4], true);
            size_t bsrc = (size_t)(rowbase + s0 + r) * 64 + ks * 16 + half * 8;
            uint32_t d3 = sb + (uint32_t)(C_BH + r * CBW + half * 8) * 4;
            cp16(d3, &g_bm2_h[bsrc], true);
            cp16(d3 + 16, &g_bm2_h[bsrc + 4], true);
            uint32_t d4 = sb + (uint32_t)(C_BL + r * CBW + half * 8) * 4;
            cp16(d4, &g_bm2_l[bsrc], true);
            cp16(d4 + 16, &g_bm2_l[bsrc + 4], true);
        }
        asm volatile("cp.async.commit_group;" ::: "memory");
        asm volatile("cp.async.wait_group 0;" ::: "memory");
        __syncthreads();
#pragma unroll
        for (int kk = 0; kk < 2; kk++) {
            uint32_t kb = kk * 32;
            uint32_t ahi[4][4], alo[4][4];
#pragma unroll
            for (int mt = 0; mt < 4; mt++) {
                ldsm4(ahi[mt], a_adh[mt] + kb);
                ldsm4(alo[mt], a_adl[mt] + kb);
            }
            uint32_t bhi[4][2], blo[4][2];
#pragma unroll
            for (int p = 0; p < 2; p++) {
                uint32_t t4[4];
                ldsm4(t4, b_adh[p] + kb);
                bhi[p * 2][0] = t4[0]; bhi[p * 2][1] = t4[1];
                bhi[p * 2 + 1][0] = t4[2]; bhi[p * 2 + 1][1] = t4[3];
                ldsm4(t4, b_adl[p] + kb);
                blo[p * 2][0] = t4[0]; blo[p * 2][1] = t4[1];
                blo[p * 2 + 1][0] = t4[2]; blo[p * 2 + 1][1] = t4[3];
            }
#pragma unroll
            for (int mt = 0; mt < 4; mt++)
#pragma unroll
                for (int nt = 0; nt < 4; nt++) {
                    mma_bf16(acc[mt][nt], ahi[mt], bhi[nt]);
                    mma_bf16(acc[mt][nt], ahi[mt], blo[nt]);
                    mma_bf16(acc[mt][nt], alo[mt], bhi[nt]);
                }
        }
    }

#pragma unroll
    for (int mt = 0; mt < 4; mt++) {
        int row = l0 + wm * 64 + mt * 16 + g;
#pragma unroll
        for (int nt = 0; nt < 4; nt++) {
            int col = s0 + wn * 32 + nt * 8 + tg * 2;
            float* a = acc[mt][nt];
            size_t i0 = ((size_t)z * CH + row) * CH + col;
            size_t i1 = ((size_t)z * CH + row + 8) * CH + col;
            g_cb[i0] = a[0]; g_cb[i0 + 1] = a[1];
            g_cb[i1] = a[2]; g_cb[i1 + 1] = a[3];
        }
    }
}

// ------ K9 (tensorized, coalesced fills): Y[256,64] ------
#define YW 20
#define YA_H 0
#define YA_L (256 * YW)
#define YB_H (2 * 256 * YW)
#define YB_L (2 * 256 * YW + 64 * YW)
#define YACS (2 * 256 * YW + 2 * 64 * YW)
#define YCF  (YACS + 256)
#define YRF  (YCF + 256)
#define YSMEM ((YRF + 8 * 256) * 4)
__global__ __launch_bounds__(256) void y_tc_kernel(const float* __restrict__ Dvec) {
    extern __shared__ __align__(16) uint32_t S[];
    uint32_t* Ah = S + YA_H;
    uint32_t* Al = S + YA_L;
    uint32_t* Bh = S + YB_H;
    uint32_t* Bl = S + YB_L;
    float* acs_s = (float*)(S + YACS);
    float* cf_s = (float*)(S + YCF);
    float* rfv = (float*)(S + YRF);
    uint32_t sb = smem_u32(S);

    int bid = blockIdx.x;
    int b = bid >> 8, c = (bid >> 5) & 7, h = bid & 31;
    int z = b * NCH + c;
    int tid = threadIdx.x, warp = tid >> 5, lane = tid & 31;
    int wm = warp & 3, wn = warp >> 2;
    int g = lane >> 2, tg = lane & 3;
    int base = ((b * NH + h) * NCH + c) * CH;
    acs_s[tid] = g_acs[base + tid];
    int rowbase = b * L_ + c * CH;
    size_t initbase = (size_t)bid * HD * DS;
    int lr = tid >> 3, cg = tid & 7;

    int mat = lane >> 3, mrow = lane & 7;
    uint32_t a_adh[4], a_adl[4], b_adh[2], b_adl[2];
#pragma unroll
    for (int mt = 0; mt < 4; mt++) {
        int r = wm * 64 + mt * 16 + (mat & 1) * 8 + mrow;
        uint32_t off = (uint32_t)(r * YW + (mat >> 1) * 4) * 4;
        a_adh[mt] = sb + YA_H * 4 + off;
        a_adl[mt] = sb + YA_L * 4 + off;
    }
#pragma unroll
    for (int p = 0; p < 2; p++) {
        int n = wn * 32 + p * 16 + (mat >> 1) * 8 + mrow;
        uint32_t off = (uint32_t)(n * YW + (mat & 1) * 4) * 4;
        b_adh[p] = sb + YB_H * 4 + off;
        b_adl[p] = sb + YB_L * 4 + off;
    }

    float acc[4][4][4];
#pragma unroll
    for (int mt = 0; mt < 4; mt++)
#pragma unroll
        for (int nt = 0; nt < 4; nt++)
#pragma unroll
            for (int q = 0; q < 4; q++) acc[mt][nt][q] = 0.f;

    auto do_mma = [&](void) {
#pragma unroll
        for (int kk = 0; kk < 2; kk++) {
            uint32_t kb = kk * 32;
            uint32_t ahi[4][4], alo[4][4];
#pragma unroll
            for (int mt = 0; mt < 4; mt++) {
                ldsm4(ahi[mt], a_adh[mt] + kb);
                ldsm4(alo[mt], a_adl[mt] + kb);
            }
            uint32_t bhi[4][2], blo[4][2];
#pragma unroll
            for (int p = 0; p < 2; p++) {
                uint32_t t4[4];
                ldsm4(t4, b_adh[p] + kb);
                bhi[p * 2][0] = t4[0]; bhi[p * 2][1] = t4[1];
                bhi[p * 2 + 1][0] = t4[2]; bhi[p * 2 + 1][1] = t4[3];
                ldsm4(t4, b_adl[p] + kb);
                blo[p * 2][0] = t4[0]; blo[p * 2][1] = t4[1];
                blo[p * 2 + 1][0] = t4[2]; blo[p * 2 + 1][1] = t4[3];
            }
#pragma unroll
            for (int mt = 0; mt < 4; mt++)
#pragma unroll
                for (int nt = 0; nt < 4; nt++) {
                    mma_bf16(acc[mt][nt], ahi[mt], bhi[nt]);
                    mma_bf16(acc[mt][nt], ahi[mt], blo[nt]);
                    mma_bf16(acc[mt][nt], alo[mt], bhi[nt]);
                }
        }
    };

    // ---------------- Phase 1: Cm @ init^T (coalesced fills) ----------
    for (int ks = 0; ks < 4; ks++) {
        __syncthreads();
        {
#pragma unroll
            for (int it = 0; it < 8; it++) {
                int l = it * 32 + lr;
                float4 v = *(const float4*)&g_xbc[(size_t)(rowbase + l) * CONVD +
                                                  DI + DS + ks * 32 + cg * 4];
                uint32_t* dah = &Ah[l * YW + cg * 2];
                uint32_t* dal = &Al[l * YW + cg * 2];
                dah[0] = pack_bf16(v.x, v.y);
                dah[1] = pack_bf16(v.z, v.w);
                dal[0] = pack_bf16(v.x - bf16r(v.x), v.y - bf16r(v.y));
                dal[1] = pack_bf16(v.z - bf16r(v.z), v.w - bf16r(v.w));
            }
        }
        {
            int p = tid >> 2, q0 = tid & 3;
            const float* ir = &g_init[initbase + (size_t)p * DS + ks * 32 + q0 * 8];
            float4 v0 = ((const float4*)ir)[0];
            float4 v1 = ((const float4*)ir)[1];
            uint32_t* dbh = &Bh[p * YW + q0 * 4];
            uint32_t* dbl = &Bl[p * YW + q0 * 4];
            dbh[0] = pack_bf16(v0.x, v0.y);
            dbh[1] = pack_bf16(v0.z, v0.w);
            dbh[2] = pack_bf16(v1.x, v1.y);
            dbh[3] = pack_bf16(v1.z, v1.w);
            dbl[0] = pack_bf16(v0.x - bf16r(v0.x), v0.y - bf16r(v0.y));
            dbl[1] = pack_bf16(v0.z - bf16r(v0.z), v0.w - bf16r(v0.w));
            dbl[2] = pack_bf16(v1.x - bf16r(v1.x), v1.y - bf16r(v1.y));
            dbl[3] = pack_bf16(v1.z - bf16r(v1.z), v1.w - bf16r(v1.w));
        }
        __syncthreads();
        do_mma();
    }

#pragma unroll
    for (int mt = 0; mt < 4; mt++) {
        int r0 = wm * 64 + mt * 16 + g;
        float e0 = __expf(acs_s[r0]);
        float e1 = __expf(acs_s[r0 + 8]);
#pragma unroll
        for (int nt = 0; nt < 4; nt++) {
            acc[mt][nt][0] *= e0; acc[mt][nt][1] *= e0;
            acc[mt][nt][2] *= e1; acc[mt][nt][3] *= e1;
        }
    }

    cf_s[tid] = __expf(acs_s[tid | 31] - acs_s[tid]);
#pragma unroll
    for (int ss = 0; ss < 8; ss++) {
        float v = 0.f;
        if (tid >= ss * 32 + 32) v = __expf(acs_s[tid] - acs_s[ss * 32 + 31]);
        rfv[ss * 256 + tid] = v;
    }

    // ---------------- Phase 2: (CB ∘ L) @ xd^T ----------
    int wlast = wm * 64 + 63;
    for (int ss = 0; ss < 8; ss++) {
        int s0 = ss * 32;
        __syncthreads();
        {
            int p = tid >> 2, q = tid & 3;
            size_t src = ((size_t)bid * HD + p) * (CH / 2) + ss * 16 + q * 4;
            cp16(sb + (uint32_t)(YB_H + p * YW + q * 4) * 4, &g_xdp_h[src], true);
            cp16(sb + (uint32_t)(YB_L + p * YW + q * 4) * 4, &g_xdp_l[src], true);
            asm volatile("cp.async.commit_group;" ::: "memory");
        }
        {
            const float* rfs = &rfv[ss * 256];
#pragma unroll
            for (int it = 0; it < 8; it++) {
                int l = it * 32 + lr;
                uint32_t* dah = &Ah[l * YW + cg * 2];
                uint32_t* dal = &Al[l * YW + cg * 2];
                if (l < s0) {
                    dah[0] = 0u; dah[1] = 0u; dal[0] = 0u; dal[1] = 0u;
                    continue;
                }
                float4 cb4 = *(const float4*)&g_cb[((size_t)z * CH + l) * CH + s0 + cg * 4];
                float va, vb, vc, vd;
                int s = s0 + cg * 4;
                if (l < s0 + 32) {
                    float al = acs_s[l];
                    va = (s <= l) ? cb4.x * __expf(al - acs_s[s]) : 0.f;
                    vb = (s + 1 <= l) ? cb4.y * __expf(al - acs_s[s + 1]) : 0.f;
                    vc = (s + 2 <= l) ? cb4.z * __expf(al - acs_s[s + 2]) : 0.f;
                    vd = (s + 3 <= l) ? cb4.w * __expf(al - acs_s[s + 3]) : 0.f;
                } else {
                    float rf = rfs[l];
                    va = cb4.x * (rf * cf_s[s]);
                    vb = cb4.y * (rf * cf_s[s + 1]);
                    vc = cb4.z * (rf * cf_s[s + 2]);
                    vd = cb4.w * (rf * cf_s[s + 3]);
                }
                dah[0] = pack_bf16(va, vb);
                dah[1] = pack_bf16(vc, vd);
                dal[0] = pack_bf16(va - bf16r(va), vb - bf16r(vb));
                dal[1] = pack_bf16(vc - bf16r(vc), vd - bf16r(vd));
            }
        }
        asm volatile("cp.async.wait_group 0;" ::: "memory");
        __syncthreads();
        if (s0 <= wlast) do_mma();
    }

    // epilogue: + D*xh, write y (fp32)
    float Dh = Dvec[h];
#pragma unroll
    for (int mt = 0; mt < 4; mt++) {
        int r = wm * 64 + mt * 16 + g;
#pragma unroll
        for (int nt = 0; nt < 4; nt++) {
            int p = wn * 32 + nt * 8 + tg * 2;
            float* a = acc[mt][nt];
#pragma unroll
            for (int q = 0; q < 4; q++) {
                int row = rowbase + r + (q >> 1) * 8;
                int pp = p + (q & 1);
                float xh = g_xbc[(size_t)row * CONVD + h * HD + pp];
                g_y[(size_t)row * DI + h * HD + pp] = a[q] + Dh * xh;
            }
        }
    }
}

// -------- K10: gated rmsnorm -> bf16 hi/lo --------
__global__ void gated_norm_kernel(const float* __restrict__ gw) {
    int row = blockIdx.x, tid = threadIdx.x;
    int d0 = tid * 8;
    const float* zr = &g_zx[(size_t)row * DPROJ + d0];
    const float* yr = &g_y[(size_t)row * DI + d0];
    float v[8];
    float local = 0.f;
#pragma unroll
    for (int q = 0; q < 2; q++) {
        float4 z4 = *(const float4*)(zr + q * 4);
        float4 y4 = *(const float4*)(yr + q * 4);
        float zz[4] = {z4.x, z4.y, z4.z, z4.w};
        float yy[4] = {y4.x, y4.y, y4.z, y4.w};
#pragma unroll
        for (int j = 0; j < 4; j++) {
            float t = yy[j] * (zz[j] / (1.f + __expf(-zz[j])));
            v[q * 4 + j] = t;
            local += t * t;
        }
    }
    float tot = blockReduceSum256(local);
    float r = rsqrtf(tot / (float)DI + 1e-5f);
    int o = row * (DI / 2) + tid * 4;
#pragma unroll
    for (int j = 0; j < 4; j++) {
        float a = v[2 * j] * r * gw[d0 + 2 * j];
        float b = v[2 * j + 1] * r * gw[d0 + 2 * j + 1];
        g_yh[o + j] = pack_bf16(a, b);
        g_yl[o + j] = pack_bf16(a - bf16r(a), b - bf16r(b));
    }
}

// ---------------- launch ----------------
extern "C" void kernel_launch(void* const* d_in, const int* in_sizes, int n_in,
                              void* d_out, int out_size) {
    const float* x         = (const float*)d_in[0];
    const float* norm_w    = (const float*)d_in[1];
    const float* in_proj_w = (const float*)d_in[2];
    const float* conv_w    = (const float*)d_in[3];
    const float* conv_b    = (const float*)d_in[4];
    const float* dt_bias   = (const float*)d_in[5];
    const float* A_log     = (const float*)d_in[6];
    const float* Dv        = (const float*)d_in[7];
    const float* gnorm_w   = (const float*)d_in[8];
    const float* out_proj_w= (const float*)d_in[9];
    float* out = (float*)d_out;

    float *pzx;
    uint32_t *puh, *pul, *pyh, *pyl, *pwih, *pwil, *pwoh, *pwol;
    cudaGetSymbolAddress((void**)&pzx, g_zx);
    cudaGetSymbolAddress((void**)&puh, g_uh);
    cudaGetSymbolAddress((void**)&pul, g_ul);
    cudaGetSymbolAddress((void**)&pyh, g_yh);
    cudaGetSymbolAddress((void**)&pyl, g_yl);
    cudaGetSymbolAddress((void**)&pwih, g_wih);
    cudaGetSymbolAddress((void**)&pwil, g_wil);
    cudaGetSymbolAddress((void**)&pwoh, g_woh);
    cudaGetSymbolAddress((void**)&pwol, g_wol);

    cudaFuncSetAttribute(mma_nt_pre, cudaFuncAttributeMaxDynamicSharedMemorySize, GSMEM);
    cudaFuncSetAttribute(y_tc_kernel, cudaFuncAttributeMaxDynamicSharedMemorySize, YSMEM);
    cudaFuncSetAttribute(xdt_kernel, cudaFuncAttributeMaxDynamicSharedMemorySize, XDT_SMEM);
    cudaFuncSetAttribute(bmt_kernel, cudaFuncAttributeMaxDynamicSharedMemorySize, BMT_SMEM);

    cvt_pairs_kernel<<<(DPROJ * DM / 2 + 255) / 256, 256>>>(in_proj_w, pwih, pwil,
                                                            DPROJ * DM / 2);
    cvt_pairs_kernel<<<(DM * DI / 2 + 255) / 256, 256>>>(out_proj_w, pwoh, pwol,
                                                         DM * DI / 2);

    rmsnorm_x_kernel<<<ROWS, 256>>>(x, norm_w);
    mma_nt_pre<<<dim3((DPROJ + 127) / 128, ROWS / 128), 256, GSMEM>>>(
        puh, pul, pwih, pwil, pzx, nullptr, ROWS, DPROJ, DM, 0);
    conv_silu_kernel<<<(ROWS * CONVD) / 256, 256>>>(conv_w, conv_b);
    dt_kernel<<<(ROWS * NH) / 256, 256>>>(dt_bias);
    acs_kernel<<<B_ * NH * NCH, 256>>>(A_log);
    cvt_bc_kernel<<<ROWS, 128>>>();
    xdt_kernel<<<NBID, 256, XDT_SMEM>>>();
    bmt_kernel<<<dim3(2, B_ * NCH), 256, BMT_SMEM>>>();
    states_tc_kernel<<<NBID, 256>>>();
    recur_kernel<<<(B_ * NH * HD * DS) / 256, 256>>>();
    cb_tc_kernel<<<dim3(2, 2, B_ * NCH), 256>>>();
    y_tc_kernel<<<NBID, 256, YSMEM>>>(Dv);
    gated_norm_kernel<<<ROWS, 256>>>(gnorm_w);
    mma_nt_pre<<<dim3(DM / 128, ROWS / 128), 256, GSMEM>>>(
        pyh, pyl, pwoh, pwol, out, x, ROWS, DM, DI, 1);
}

// round 13
// speedup vs baseline: 1.0336x; 1.0001x over previous
#include <cuda_runtime.h>
#include <cuda_bf16.h>
#include <math.h>
#include <stdint.h>

// ---------------- problem constants ----------------
#define B_    2
#define L_    2048
#define DM    1024
#define DI    2048
#define NH    32
#define HD    64
#define DS    128
#define CONVD 2304
#define DPROJ 4384
#define NCH   8
#define CH    256
#define ROWS  4096
#define NBID  (B_ * NCH * NH)   // 512

// ---------------- scratch (device globals) ----------------
__device__ float g_zx[(size_t)ROWS * DPROJ];
__device__ float g_xbc[(size_t)ROWS * CONVD];
__device__ float g_dt[ROWS * NH];
__device__ float g_acs[B_ * NH * NCH * CH];
__device__ float g_states[(size_t)B_ * NCH * NH * HD * DS];
__device__ float g_init[(size_t)B_ * NCH * NH * HD * DS];
__device__ float g_cb[(size_t)B_ * NCH * CH * CH];
__device__ float g_y[(size_t)ROWS * DI];

// packed bf16x2 hi/lo operand arrays
__device__ uint32_t g_uh[ROWS * DM / 2];
__device__ uint32_t g_ul[ROWS * DM / 2];
__device__ uint32_t g_yh[(size_t)ROWS * DI / 2];
__device__ uint32_t g_yl[(size_t)ROWS * DI / 2];
__device__ uint32_t g_wih[(size_t)DPROJ * DM / 2];
__device__ uint32_t g_wil[(size_t)DPROJ * DM / 2];
__device__ uint32_t g_woh[(size_t)DM * DI / 2];
__device__ uint32_t g_wol[(size_t)DM * DI / 2];

// SSD precomputed operands (bf16x2 packed)
__device__ uint32_t g_xdp_h[(size_t)NBID * HD * (CH / 2)];
__device__ uint32_t g_xdp_l[(size_t)NBID * HD * (CH / 2)];
__device__ uint32_t g_xds_h[(size_t)NBID * HD * (CH / 2)];
__device__ uint32_t g_xds_l[(size_t)NBID * HD * (CH / 2)];
__device__ uint32_t g_bmt_h[(size_t)B_ * NCH * DS * (CH / 2)];
__device__ uint32_t g_bmt_l[(size_t)B_ * NCH * DS * (CH / 2)];
// row-major Bm/Cm bf16 hi/lo for CB gemm: [row][n/2]
__device__ uint32_t g_bm2_h[(size_t)ROWS * 64];
__device__ uint32_t g_bm2_l[(size_t)ROWS * 64];
__device__ uint32_t g_cm2_h[(size_t)ROWS * 64];
__device__ uint32_t g_cm2_l[(size_t)ROWS * 64];

// ---------------- helpers ----------------
__device__ __forceinline__ float blockReduceSum256(float v) {
    __shared__ float ws[8];
    __shared__ float tot;
    int lane = threadIdx.x & 31, wid = threadIdx.x >> 5;
#pragma unroll
    for (int o = 16; o; o >>= 1) v += __shfl_xor_sync(0xffffffffu, v, o);
    if (lane == 0) ws[wid] = v;
    __syncthreads();
    if (threadIdx.x == 0) {
        float s = 0.f;
#pragma unroll
        for (int i = 0; i < 8; i++) s += ws[i];
        tot = s;
    }
    __syncthreads();
    return tot;
}

__device__ __forceinline__ uint32_t pack_bf16(float a, float b) {
    __nv_bfloat162 h = __floats2bfloat162_rn(a, b);
    return *(uint32_t*)&h;
}

__device__ __forceinline__ float bf16r(float v) {
    return __bfloat162float(__float2bfloat16(v));
}

__device__ __forceinline__ uint32_t smem_u32(const void* p) {
    uint32_t a;
    asm("{ .reg .u64 t; cvta.to.shared.u64 t, %1; cvt.u32.u64 %0, t; }"
        : "=r"(a) : "l"(p));
    return a;
}

__device__ __forceinline__ void mma_bf16(float* d, const uint32_t* a, const uint32_t* b) {
    asm volatile(
        "mma.sync.aligned.m16n8k16.row.col.f32.bf16.bf16.f32 "
        "{%0,%1,%2,%3}, {%4,%5,%6,%7}, {%8,%9}, {%0,%1,%2,%3};"
        : "+f"(d[0]), "+f"(d[1]), "+f"(d[2]), "+f"(d[3])
        : "r"(a[0]), "r"(a[1]), "r"(a[2]), "r"(a[3]), "r"(b[0]), "r"(b[1]));
}

__device__ __forceinline__ void ldsm4(uint32_t* r, uint32_t addr) {
    asm volatile("ldmatrix.sync.aligned.m8n8.x4.shared.b16 {%0,%1,%2,%3}, [%4];"
                 : "=r"(r[0]), "=r"(r[1]), "=r"(r[2]), "=r"(r[3]) : "r"(addr));
}

__device__ __forceinline__ void cp16(uint32_t dst, const void* src, bool ok) {
    if (ok)
        asm volatile("cp.async.cg.shared.global [%0], [%1], 16;"
                     :: "r"(dst), "l"(src) : "memory");
    else
        asm volatile("cp.async.cg.shared.global [%0], [%1], 16, 0;"
                     :: "r"(dst), "l"(src) : "memory");
}

// ---------------- K0: split fp32 pairs -> bf16 hi/lo packed ----------
__global__ void cvt_pairs_kernel(const float* __restrict__ W,
                                 uint32_t* __restrict__ Wh,
                                 uint32_t* __restrict__ Wl, int npairs) {
    int i = blockIdx.x * blockDim.x + threadIdx.x;
    if (i < npairs) {
        float2 v = ((const float2*)W)[i];
        Wh[i] = pack_bf16(v.x, v.y);
        Wl[i] = pack_bf16(v.x - bf16r(v.x), v.y - bf16r(v.y));
    }
}

// ---------------- K1: rmsnorm(x) -> bf16 hi/lo ----------------
__global__ void rmsnorm_x_kernel(const float* __restrict__ x,
                                 const float* __restrict__ w) {
    int row = blockIdx.x, tid = threadIdx.x;
    const float4 v = ((const float4*)(x + (size_t)row * DM))[tid];
    const float4 wv = ((const float4*)w)[tid];
    float local = v.x * v.x + v.y * v.y + v.z * v.z + v.w * v.w;
    float tot = blockReduceSum256(local);
    float r = rsqrtf(tot / (float)DM + 1e-5f);
    float u0 = v.x * r * wv.x, u1 = v.y * r * wv.y;
    float u2 = v.z * r * wv.z, u3 = v.w * r * wv.w;
    int o = row * (DM / 2) + tid * 2;
    g_uh[o] = pack_bf16(u0, u1);
    g_uh[o + 1] = pack_bf16(u2, u3);
    g_ul[o] = pack_bf16(u0 - bf16r(u0), u1 - bf16r(u1));
    g_ul[o + 1] = pack_bf16(u2 - bf16r(u2), u3 - bf16r(u3));
}

// ------- tensor-core NT GEMM, preconverted bf16 hi/lo, cp.async 2-stage -------
#define UPS   (4 * 128 * 20)
#define GSMEM (2 * UPS * 4)
__global__ __launch_bounds__(256) void mma_nt_pre(const uint32_t* __restrict__ Ahg,
                                                  const uint32_t* __restrict__ Alg,
                                                  const uint32_t* __restrict__ Bhg,
                                                  const uint32_t* __restrict__ Blg,
                                                  float* __restrict__ C,
                                                  const float* __restrict__ resid,
                                                  int M, int N, int K, int addRes) {
    extern __shared__ __align__(16) uint32_t S[];
    uint32_t sbase = smem_u32(S);
    int tid = threadIdx.x;
    int warp = tid >> 5, lane = tid & 31;
    int wm = warp & 1, wn = warp >> 1;
    int bm = blockIdx.y * 128, bn = blockIdx.x * 128;
    int g = lane >> 2, tg = lane & 3;
    int K2 = K >> 1;

    int lrow = tid >> 1, lhalf = tid & 1;
    const uint32_t* pA[2] = {Ahg + (size_t)(bm + lrow) * K2 + lhalf * 8,
                             Alg + (size_t)(bm + lrow) * K2 + lhalf * 8};
    bool okB = (bn + lrow) < N;
    int brow = okB ? (bn + lrow) : 0;
    const uint32_t* pB[2] = {Bhg + (size_t)brow * K2 + lhalf * 8,
                             Blg + (size_t)brow * K2 + lhalf * 8};
    uint32_t dto = (uint32_t)(lrow * 20 + lhalf * 8) * 4;

    int mat = lane >> 3, mrow = lane & 7;
    uint32_t a_ad[4], b_ad[2];
#pragma unroll
    for (int mt = 0; mt < 4; mt++) {
        int r = wm * 64 + mt * 16 + (mat & 1) * 8 + mrow;
        a_ad[mt] = sbase + (uint32_t)(r * 20 + (mat >> 1) * 4) * 4;
    }
#pragma unroll
    for (int p = 0; p < 2; p++) {
        int n = wn * 32 + p * 16 + (mat >> 1) * 8 + mrow;
        b_ad[p] = sbase + (uint32_t)(n * 20 + (mat & 1) * 4) * 4;
    }

    float acc[4][4][4];
#pragma unroll
    for (int mt = 0; mt < 4; mt++)
#pragma unroll
        for (int nt = 0; nt < 4; nt++)
#pragma unroll
            for (int q = 0; q < 4; q++) acc[mt][nt][q] = 0.f;

    int nslab = K >> 5;

    auto issue = [&](int st, int sl) {
        int ko = sl * 16;
        uint32_t db = sbase + (uint32_t)(st * UPS) * 4 + dto;
#pragma unroll
        for (int t = 0; t < 2; t++) {
            cp16(db + (uint32_t)(t * 2560 * 4), pA[t] + ko, true);
            cp16(db + (uint32_t)(t * 2560 * 4) + 16, pA[t] + ko + 4, true);
            cp16(db + (uint32_t)((2 + t) * 2560 * 4), pB[t] + ko, okB);
            cp16(db + (uint32_t)((2 + t) * 2560 * 4) + 16, pB[t] + ko + 4, okB);
        }
        asm volatile("cp.async.commit_group;" ::: "memory");
    };

    issue(0, 0);
    int st = 0;
    for (int i = 0; i < nslab; i++) {
        if (i + 1 < nslab) {
            issue(st ^ 1, i + 1);
            asm volatile("cp.async.wait_group 1;" ::: "memory");
        } else {
            asm volatile("cp.async.wait_group 0;" ::: "memory");
        }
        __syncthreads();
        uint32_t so = (uint32_t)(st * UPS) * 4;
#pragma unroll
        for (int kk = 0; kk < 2; kk++) {
            uint32_t kb = so + kk * 32;
            uint32_t ahi[4][4], alo[4][4];
#pragma unroll
            for (int mt = 0; mt < 4; mt++) {
                ldsm4(ahi[mt], a_ad[mt] + kb);
                ldsm4(alo[mt], a_ad[mt] + kb + 2560 * 4);
            }
            uint32_t bhi[4][2], blo[4][2];
#pragma unroll
            for (int p = 0; p < 2; p++) {
                uint32_t t4[4];
                ldsm4(t4, b_ad[p] + kb + 2 * 2560 * 4);
                bhi[p * 2][0] = t4[0]; bhi[p * 2][1] = t4[1];
                bhi[p * 2 + 1][0] = t4[2]; bhi[p * 2 + 1][1] = t4[3];
                ldsm4(t4, b_ad[p] + kb + 3 * 2560 * 4);
                blo[p * 2][0] = t4[0]; blo[p * 2][1] = t4[1];
                blo[p * 2 + 1][0] = t4[2]; blo[p * 2 + 1][1] = t4[3];
            }
#pragma unroll
            for (int mt = 0; mt < 4; mt++)
#pragma unroll
                for (int nt = 0; nt < 4; nt++) {
                    mma_bf16(acc[mt][nt], ahi[mt], bhi[nt]);
                    mma_bf16(acc[mt][nt], ahi[mt], blo[nt]);
                    mma_bf16(acc[mt][nt], alo[mt], bhi[nt]);
                }
        }
        __syncthreads();
        st ^= 1;
    }

#pragma unroll
    for (int mt = 0; mt < 4; mt++) {
        int row = bm + wm * 64 + mt * 16 + g;
#pragma unroll
        for (int nt = 0; nt < 4; nt++) {
            int col = bn + wn * 32 + nt * 8 + tg * 2;
            if (col < N) {
                float* a = acc[mt][nt];
                size_t i0 = (size_t)row * N + col;
                size_t i1 = (size_t)(row + 8) * N + col;
                if (addRes) {
                    a[0] += resid[i0]; a[1] += resid[i0 + 1];
                    a[2] += resid[i1]; a[3] += resid[i1 + 1];
                }
                C[i0] = a[0]; C[i0 + 1] = a[1];
                C[i1] = a[2]; C[i1 + 1] = a[3];
            }
        }
    }
}

// ------ K3+K4 fused: depthwise conv+silu AND dt softplus ------
__global__ void conv_dt_kernel(const float* __restrict__ conv_w,
                               const float* __restrict__ conv_b,
                               const float* __restrict__ dt_bias) {
    int idx = blockIdx.x * blockDim.x + threadIdx.x;
    if (idx < ROWS * CONVD) {
        int c = idx % CONVD;
        int row = idx / CONVD;
        int l = row & (L_ - 1);
        const float* w = conv_w + c * 4;
        float acc = conv_b[c];
#pragma unroll
        for (int j = 0; j < 4; j++) {
            int ls = l - 3 + j;
            if (ls >= 0)
                acc += w[j] * g_zx[(size_t)(row - 3 + j) * DPROJ + DI + c];
        }
        float s = acc / (1.f + __expf(-acc));
        g_xbc[(size_t)row * CONVD + c] = s;
    } else {
        int j = idx - ROWS * CONVD;  // < ROWS*NH
        int h = j & (NH - 1);
        int row = j >> 5;
        float v = g_zx[(size_t)row * DPROJ + (DI + CONVD) + h] + dt_bias[h];
        float sp = (v > 20.f) ? v : log1pf(__expf(v));
        g_dt[row * NH + h] = sp;
    }
}

// ---------------- K5: per-chunk cumsum of a = dt * A ----------
__global__ void acs_kernel(const float* __restrict__ A_log) {
    int bid = blockIdx.x;
    int b = bid >> 8, h = (bid >> 3) & 31, c = bid & 7;
    int l = threadIdx.x;
    int row = b * L_ + c * CH + l;
    float A = -__expf(A_log[h]);
    __shared__ float s[CH];
    s[l] = g_dt[row * NH + h] * A;
    __syncthreads();
#pragma unroll
    for (int off = 1; off < CH; off <<= 1) {
        float v = (l >= off) ? s[l - off] : 0.f;
        __syncthreads();
        s[l] += v;
        __syncthreads();
    }
    g_acs[bid * CH + l] = s[l];
}

// ----- K5b: xdT precompute -----
#define XDT_SMEM (256 * 68 * 4)
__global__ __launch_bounds__(256) void xdt_kernel() {
    extern __shared__ float sx[];
    __shared__ float sdt[CH], sdec[CH];
    int bid = blockIdx.x;
    int b = bid >> 8, c = (bid >> 5) & 7, h = bid & 31;
    int tid = threadIdx.x;
    int rowbase = b * L_ + c * CH;
    int base = ((b * NH + h) * NCH + c) * CH;
    float acs255 = g_acs[base + CH - 1];
    {
        int l = tid, row = rowbase + l;
        const float* xr = &g_xbc[(size_t)row * CONVD + h * HD];
#pragma unroll
        for (int p4 = 0; p4 < 16; p4++) {
            float4 v = ((const float4*)xr)[p4];
            *(float4*)&sx[l * 68 + p4 * 4] = v;
        }
        sdt[l] = g_dt[row * NH + h];
        sdec[l] = __expf(acs255 - g_acs[base + l]);
    }
    __syncthreads();
    int warp = tid >> 5, lane = tid & 31;
    size_t ob = (size_t)bid * HD * (CH / 2);
#pragma unroll
    for (int pp = 0; pp < 8; pp++) {
        int p = warp * 8 + pp;
        uint32_t oh[4], ol[4], osh[4], osl[4];
#pragma unroll
        for (int k = 0; k < 4; k++) {
            int cu = lane * 4 + k;
            int l = cu * 2;
            float va = sx[l * 68 + p] * sdt[l];
            float vb = sx[(l + 1) * 68 + p] * sdt[l + 1];
            oh[k] = pack_bf16(va, vb);
            ol[k] = pack_bf16(va - bf16r(va), vb - bf16r(vb));
            float wa = va * sdec[l], wb = vb * sdec[l + 1];
            osh[k] = pack_bf16(wa, wb);
            osl[k] = pack_bf16(wa - bf16r(wa), wb - bf16r(wb));
        }
        size_t o = ob + (size_t)p * (CH / 2) + lane * 4;
        *(uint4*)&g_xdp_h[o] = *(uint4*)oh;
        *(uint4*)&g_xdp_l[o] = *(uint4*)ol;
        *(uint4*)&g_xds_h[o] = *(uint4*)osh;
        *(uint4*)&g_xds_l[o] = *(uint4*)osl;
    }
}

// ----- K5c: Bm^T precompute -----
#define BMT_SMEM (128 * 132 * 4)
__global__ __launch_bounds__(256) void bmt_kernel() {
    extern __shared__ float sx[];
    int z = blockIdx.y, pass = blockIdx.x;
    int b = z >> 3, c = z & 7;
    int tid = threadIdx.x;
    int rowbase = b * L_ + c * CH + pass * 128;
    {
        int l = tid & 127, half = tid >> 7;
        const float* br = &g_xbc[(size_t)(rowbase + l) * CONVD + DI + half * 64];
#pragma unroll
        for (int k4 = 0; k4 < 16; k4++) {
            float4 v = ((const float4*)br)[k4];
            *(float4*)&sx[l * 132 + half * 64 + k4 * 4] = v;
        }
    }
    __syncthreads();
    int warp = tid >> 5, lane = tid & 31;
#pragma unroll
    for (int nn = 0; nn < 16; nn++) {
        int n = warp * 16 + nn;
        uint32_t h2[2], l2[2];
#pragma unroll
        for (int k = 0; k < 2; k++) {
            int cu = lane * 2 + k;
            float va = sx[(2 * cu) * 132 + n];
            float vb = sx[(2 * cu + 1) * 132 + n];
            h2[k] = pack_bf16(va, vb);
            l2[k] = pack_bf16(va - bf16r(va), vb - bf16r(vb));
        }
        size_t o = ((size_t)z * DS + n) * (CH / 2) + pass * 64 + lane * 2;
        *(uint2*)&g_bmt_h[o] = *(uint2*)h2;
        *(uint2*)&g_bmt_l[o] = *(uint2*)l2;
    }
}

// ----- K5d: row-major Bm/Cm bf16 hi/lo (for CB gemm) -----
__global__ void cvt_bc_kernel() {
    int row = blockIdx.x;
    int tid = threadIdx.x;  // 128
    int which = tid >> 6, n2 = tid & 63;
    float2 v = *(const float2*)&g_xbc[(size_t)row * CONVD + DI + which * DS + n2 * 2];
    uint32_t hh = pack_bf16(v.x, v.y);
    uint32_t ll = pack_bf16(v.x - bf16r(v.x), v.y - bf16r(v.y));
    size_t o = (size_t)row * 64 + n2;
    if (which == 0) { g_bm2_h[o] = hh; g_bm2_l[o] = ll; }
    else            { g_cm2_h[o] = hh; g_cm2_l[o] = ll; }
}

// ------ K6 (tensorized): states[n,p] ------
#define SSW 20
#define S_AH 0
#define S_AL (128 * SSW)
#define S_BH (2 * 128 * SSW)
#define S_BL (2 * 128 * SSW + 64 * SSW)
__global__ __launch_bounds__(256) void states_tc_kernel() {
    __shared__ __align__(16) uint32_t S[2 * 128 * SSW + 2 * 64 * SSW];
    uint32_t sb = smem_u32(S);
    int bid = blockIdx.x;
    int b = bid >> 8, c = (bid >> 5) & 7;
    int z = b * NCH + c;
    int tid = threadIdx.x, warp = tid >> 5, lane = tid & 31;
    int wm = warp & 3, wn = warp >> 2;
    int g = lane >> 2, tg = lane & 3;
    int mat = lane >> 3, mrow = lane & 7;

    uint32_t a_adh[2], a_adl[2], b_adh[2], b_adl[2];
#pragma unroll
    for (int mt = 0; mt < 2; mt++) {
        int r = wm * 32 + mt * 16 + (mat & 1) * 8 + mrow;
        uint32_t off = (uint32_t)(r * SSW + (mat >> 1) * 4) * 4;
        a_adh[mt] = sb + S_AH * 4 + off;
        a_adl[mt] = sb + S_AL * 4 + off;
    }
#pragma unroll
    for (int p = 0; p < 2; p++) {
        int n = wn * 32 + p * 16 + (mat >> 1) * 8 + mrow;
        uint32_t off = (uint32_t)(n * SSW + (mat & 1) * 4) * 4;
        b_adh[p] = sb + S_BH * 4 + off;
        b_adl[p] = sb + S_BL * 4 + off;
    }

    float acc[2][4][4];
#pragma unroll
    for (int mt = 0; mt < 2; mt++)
#pragma unroll
        for (int nt = 0; nt < 4; nt++)
#pragma unroll
            for (int q = 0; q < 4; q++) acc[mt][nt][q] = 0.f;

    for (int j = 0; j < 8; j++) {
        __syncthreads();
        {
            int n = tid >> 1, half = tid & 1;
            size_t src = ((size_t)z * DS + n) * (CH / 2) + j * 16 + half * 8;
            uint32_t d = sb + (uint32_t)(S_AH + n * SSW + half * 8) * 4;
            cp16(d, &g_bmt_h[src], true);
            cp16(d + 16, &g_bmt_h[src + 4], true);
            uint32_t d2 = sb + (uint32_t)(S_AL + n * SSW + half * 8) * 4;
            cp16(d2, &g_bmt_l[src], true);
            cp16(d2 + 16, &g_bmt_l[src + 4], true);
        }
        {
            int p = tid >> 2, q = tid & 3;
            size_t src = ((size_t)bid * HD + p) * (CH / 2) + j * 16 + q * 4;
            cp16(sb + (uint32_t)(S_BH + p * SSW + q * 4) * 4, &g_xds_h[src], true);
            cp16(sb + (uint32_t)(S_BL + p * SSW + q * 4) * 4, &g_xds_l[src], true);
        }
        asm volatile("cp.async.commit_group;" ::: "memory");
        asm volatile("cp.async.wait_group 0;" ::: "memory");
        __syncthreads();
#pragma unroll
        for (int kk = 0; kk < 2; kk++) {
            uint32_t kb = kk * 32;
            uint32_t ahi[2][4], alo[2][4];
#pragma unroll
            for (int mt = 0; mt < 2; mt++) {
                ldsm4(ahi[mt], a_adh[mt] + kb);
                ldsm4(alo[mt], a_adl[mt] + kb);
            }
            uint32_t bhi[4][2], blo[4][2];
#pragma unroll
            for (int p = 0; p < 2; p++) {
                uint32_t t4[4];
                ldsm4(t4, b_adh[p] + kb);
                bhi[p * 2][0] = t4[0]; bhi[p * 2][1] = t4[1];
                bhi[p * 2 + 1][0] = t4[2]; bhi[p * 2 + 1][1] = t4[3];
                ldsm4(t4, b_adl[p] + kb);
                blo[p * 2][0] = t4[0]; blo[p * 2][1] = t4[1];
                blo[p * 2 + 1][0] = t4[2]; blo[p * 2 + 1][1] = t4[3];
            }
#pragma unroll
            for (int mt = 0; mt < 2; mt++)
#pragma unroll
                for (int nt = 0; nt < 4; nt++) {
                    mma_bf16(acc[mt][nt], ahi[mt], bhi[nt]);
                    mma_bf16(acc[mt][nt], ahi[mt], blo[nt]);
                    mma_bf16(acc[mt][nt], alo[mt], bhi[nt]);
                }
        }
    }

    size_t out = (size_t)bid * HD * DS;
#pragma unroll
    for (int mt = 0; mt < 2; mt++) {
#pragma unroll
        for (int nt = 0; nt < 4; nt++) {
            float* a = acc[mt][nt];
#pragma unroll
            for (int q = 0; q < 4; q++) {
                int n = wm * 32 + mt * 16 + g + (q >> 1) * 8;
                int p = wn * 32 + nt * 8 + tg * 2 + (q & 1);
                g_states[out + (size_t)p * DS + n] = a[q];
            }
        }
    }
}

// ---------------- K7: chunk recurrence ----------
__global__ void recur_kernel() {
    int idx = blockIdx.x * blockDim.x + threadIdx.x;
    int n = idx & 127;
    int p = (idx >> 7) & 63;
    int h = (idx >> 13) & 31;
    int b = idx >> 18;
    float run = 0.f;
#pragma unroll
    for (int c = 0; c < NCH; c++) {
        size_t sidx = ((size_t)((b * NCH + c) * NH + h) * HD + p) * DS + n;
        g_init[sidx] = run;
        float cs = g_acs[((b * NH + h) * NCH + c) * CH + CH - 1];
        run = run * __expf(cs) + g_states[sidx];
    }
}

// ------ K8 (tensorized): CB[l,s] = Cm[l]·Bm[s], 128x128x128 tiles ------
#define CBW 20
#define C_AH 0
#define C_AL (128 * CBW)
#define C_BH (2 * 128 * CBW)
#define C_BL (3 * 128 * CBW)
__global__ __launch_bounds__(256) void cb_tc_kernel() {
    __shared__ __align__(16) uint32_t S[4 * 128 * CBW];
    uint32_t sb = smem_u32(S);
    int z = blockIdx.z;
    int b = z >> 3, c = z & 7;
    int l0 = blockIdx.y * 128, s0 = blockIdx.x * 128;
    int rowbase = b * L_ + c * CH;
    int tid = threadIdx.x, warp = tid >> 5, lane = tid & 31;
    int wm = warp & 1, wn = warp >> 1;
    int g = lane >> 2, tg = lane & 3;
    int mat = lane >> 3, mrow = lane & 7;

    uint32_t a_adh[4], a_adl[4], b_adh[2], b_adl[2];
#pragma unroll
    for (int mt = 0; mt < 4; mt++) {
        int r = wm * 64 + mt * 16 + (mat & 1) * 8 + mrow;
        uint32_t off = (uint32_t)(r * CBW + (mat >> 1) * 4) * 4;
        a_adh[mt] = sb + C_AH * 4 + off;
        a_adl[mt] = sb + C_AL * 4 + off;
    }
#pragma unroll
    for (int p = 0; p < 2; p++) {
        int n = wn * 32 + p * 16 + (mat >> 1) * 8 + mrow;
        uint32_t off = (uint32_t)(n * CBW + (mat & 1) * 4) * 4;
        b_adh[p] = sb + C_BH * 4 + off;
        b_adl[p] = sb + C_BL * 4 + off;
    }

    float acc[4][4][4];
#pragma unroll
    for (int mt = 0; mt < 4; mt++)
#pragma unroll
        for (int nt = 0; nt < 4; nt++)
#pragma unroll
            for (int q = 0; q < 4; q++) acc[mt][nt][q] = 0.f;

    for (int ks = 0; ks < 4; ks++) {
        __syncthreads();
        {
            int r = tid >> 1, half = tid & 1;
            size_t asrc = (size_t)(rowbase + l0 + r) * 64 + ks * 16 + half * 8;
            uint32_t d = sb + (uint32_t)(C_AH + r * CBW + half * 8) * 4;
            cp16(d, &g_cm2_h[asrc], true);
            cp16(d + 16, &g_cm2_h[asrc + 4], true);
            uint32_t d2 = sb + (uint32_t)(C_AL + r * CBW + half * 8) * 4;
            cp16(d2, &g_cm2_l[asrc], true);
            cp16(d2 + 16, &g_cm2_l[asrc + 4], true);
            size_t bsrc = (size_t)(rowbase + s0 + r) * 64 + ks * 16 + half * 8;
            uint32_t d3 = sb + (uint32_t)(C_BH + r * CBW + half * 8) * 4;
            cp16(d3, &g_bm2_h[bsrc], true);
            cp16(d3 + 16, &g_bm2_h[bsrc + 4], true);
            uint32_t d4 = sb + (uint32_t)(C_BL + r * CBW + half * 8) * 4;
            cp16(d4, &g_bm2_l[bsrc], true);
            cp16(d4 + 16, &g_bm2_l[bsrc + 4], true);
        }
        asm volatile("cp.async.commit_group;" ::: "memory");
        asm volatile("cp.async.wait_group 0;" ::: "memory");
        __syncthreads();
#pragma unroll
        for (int kk = 0; kk < 2; kk++) {
            uint32_t kb = kk * 32;
            uint32_t ahi[4][4], alo[4][4];
#pragma unroll
            for (int mt = 0; mt < 4; mt++) {
                ldsm4(ahi[mt], a_adh[mt] + kb);
                ldsm4(alo[mt], a_adl[mt] + kb);
            }
            uint32_t bhi[4][2], blo[4][2];
#pragma unroll
            for (int p = 0; p < 2; p++) {
                uint32_t t4[4];
                ldsm4(t4, b_adh[p] + kb);
                bhi[p * 2][0] = t4[0]; bhi[p * 2][1] = t4[1];
                bhi[p * 2 + 1][0] = t4[2]; bhi[p * 2 + 1][1] = t4[3];
                ldsm4(t4, b_adl[p] + kb);
                blo[p * 2][0] = t4[0]; blo[p * 2][1] = t4[1];
                blo[p * 2 + 1][0] = t4[2]; blo[p * 2 + 1][1] = t4[3];
            }
#pragma unroll
            for (int mt = 0; mt < 4; mt++)
#pragma unroll
                for (int nt = 0; nt < 4; nt++) {
                    mma_bf16(acc[mt][nt], ahi[mt], bhi[nt]);
                    mma_bf16(acc[mt][nt], ahi[mt], blo[nt]);
                    mma_bf16(acc[mt][nt], alo[mt], bhi[nt]);
                }
        }
    }

#pragma unroll
    for (int mt = 0; mt < 4; mt++) {
        int row = l0 + wm * 64 + mt * 16 + g;
#pragma unroll
        for (int nt = 0; nt < 4; nt++) {
            int col = s0 + wn * 32 + nt * 8 + tg * 2;
            float* a = acc[mt][nt];
            size_t i0 = ((size_t)z * CH + row) * CH + col;
            size_t i1 = ((size_t)z * CH + row + 8) * CH + col;
            g_cb[i0] = a[0]; g_cb[i0 + 1] = a[1];
            g_cb[i1] = a[2]; g_cb[i1 + 1] = a[3];
        }
    }
}

// ------ K9: Y[256,64]; interleaved causal tile mapping (row = wm*16 + mt*64) --
#define YW 20
#define YA_H 0
#define YA_L (256 * YW)
#define YB_H (2 * 256 * YW)
#define YB_L (2 * 256 * YW + 64 * YW)
#define YACS (2 * 256 * YW + 2 * 64 * YW)
#define YCF  (YACS + 256)
#define YRF  (YCF + 256)
#define YSMEM ((YRF + 8 * 256) * 4)
__global__ __launch_bounds__(256) void y_tc_kernel(const float* __restrict__ Dvec) {
    extern __shared__ __align__(16) uint32_t S[];
    uint32_t* Ah = S + YA_H;
    uint32_t* Al = S + YA_L;
    uint32_t* Bh = S + YB_H;
    uint32_t* Bl = S + YB_L;
    float* acs_s = (float*)(S + YACS);
    float* cf_s = (float*)(S + YCF);
    float* rfv = (float*)(S + YRF);
    uint32_t sb = smem_u32(S);

    int bid = blockIdx.x;
    int b = bid >> 8, c = (bid >> 5) & 7, h = bid & 31;
    int z = b * NCH + c;
    int tid = threadIdx.x, warp = tid >> 5, lane = tid & 31;
    int wm = warp & 3, wn = warp >> 2;
    int g = lane >> 2, tg = lane & 3;
    int base = ((b * NH + h) * NCH + c) * CH;
    acs_s[tid] = g_acs[base + tid];
    int rowbase = b * L_ + c * CH;
    size_t initbase = (size_t)bid * HD * DS;
    int lr = tid >> 3, cg = tid & 7;

    int mat = lane >> 3, mrow = lane & 7;
    uint32_t a_adh[4], a_adl[4], b_adh[2], b_adl[2];
#pragma unroll
    for (int mt = 0; mt < 4; mt++) {
        int r = wm * 16 + mt * 64 + (mat & 1) * 8 + mrow;   // interleaved
        uint32_t off = (uint32_t)(r * YW + (mat >> 1) * 4) * 4;
        a_adh[mt] = sb + YA_H * 4 + off;
        a_adl[mt] = sb + YA_L * 4 + off;
    }
#pragma unroll
    for (int p = 0; p < 2; p++) {
        int n = wn * 32 + p * 16 + (mat >> 1) * 8 + mrow;
        uint32_t off = (uint32_t)(n * YW + (mat & 1) * 4) * 4;
        b_adh[p] = sb + YB_H * 4 + off;
        b_adl[p] = sb + YB_L * 4 + off;
    }

    float acc[4][4][4];
#pragma unroll
    for (int mt = 0; mt < 4; mt++)
#pragma unroll
        for (int nt = 0; nt < 4; nt++)
#pragma unroll
            for (int q = 0; q < 4; q++) acc[mt][nt][q] = 0.f;

    // tile mt active for slab origin s0 iff its max row >= s0
    auto do_mma = [&](int s0) {
        bool act[4];
#pragma unroll
        for (int mt = 0; mt < 4; mt++) act[mt] = (wm * 16 + mt * 64 + 15 >= s0);
        if (!act[3]) return;
#pragma unroll
        for (int kk = 0; kk < 2; kk++) {
            uint32_t kb = kk * 32;
            uint32_t ahi[4][4], alo[4][4];
#pragma unroll
            for (int mt = 0; mt < 4; mt++)
                if (act[mt]) {
                    ldsm4(ahi[mt], a_adh[mt] + kb);
                    ldsm4(alo[mt], a_adl[mt] + kb);
                }
            uint32_t bhi[4][2], blo[4][2];
#pragma unroll
            for (int p = 0; p < 2; p++) {
                uint32_t t4[4];
                ldsm4(t4, b_adh[p] + kb);
                bhi[p * 2][0] = t4[0]; bhi[p * 2][1] = t4[1];
                bhi[p * 2 + 1][0] = t4[2]; bhi[p * 2 + 1][1] = t4[3];
                ldsm4(t4, b_adl[p] + kb);
                blo[p * 2][0] = t4[0]; blo[p * 2][1] = t4[1];
                blo[p * 2 + 1][0] = t4[2]; blo[p * 2 + 1][1] = t4[3];
            }
#pragma unroll
            for (int mt = 0; mt < 4; mt++)
                if (act[mt])
#pragma unroll
                    for (int nt = 0; nt < 4; nt++) {
                        mma_bf16(acc[mt][nt], ahi[mt], bhi[nt]);
                        mma_bf16(acc[mt][nt], ahi[mt], blo[nt]);
                        mma_bf16(acc[mt][nt], alo[mt], bhi[nt]);
                    }
        }
    };

    // ---------------- Phase 1: Cm @ init^T (coalesced fills) ----------
    for (int ks = 0; ks < 4; ks++) {
        __syncthreads();
        {
#pragma unroll
            for (int it = 0; it < 8; it++) {
                int l = it * 32 + lr;
                float4 v = *(const float4*)&g_xbc[(size_t)(rowbase + l) * CONVD +
                                                  DI + DS + ks * 32 + cg * 4];
                uint32_t* dah = &Ah[l * YW + cg * 2];
                uint32_t* dal = &Al[l * YW + cg * 2];
                dah[0] = pack_bf16(v.x, v.y);
                dah[1] = pack_bf16(v.z, v.w);
                dal[0] = pack_bf16(v.x - bf16r(v.x), v.y - bf16r(v.y));
                dal[1] = pack_bf16(v.z - bf16r(v.z), v.w - bf16r(v.w));
            }
        }
        {
            int p = tid >> 2, q0 = tid & 3;
            const float* ir = &g_init[initbase + (size_t)p * DS + ks * 32 + q0 * 8];
            float4 v0 = ((const float4*)ir)[0];
            float4 v1 = ((const float4*)ir)[1];
            uint32_t* dbh = &Bh[p * YW + q0 * 4];
            uint32_t* dbl = &Bl[p * YW + q0 * 4];
            dbh[0] = pack_bf16(v0.x, v0.y);
            dbh[1] = pack_bf16(v0.z, v0.w);
            dbh[2] = pack_bf16(v1.x, v1.y);
            dbh[3] = pack_bf16(v1.z, v1.w);
            dbl[0] = pack_bf16(v0.x - bf16r(v0.x), v0.y - bf16r(v0.y));
            dbl[1] = pack_bf16(v0.z - bf16r(v0.z), v0.w - bf16r(v0.w));
            dbl[2] = pack_bf16(v1.x - bf16r(v1.x), v1.y - bf16r(v1.y));
            dbl[3] = pack_bf16(v1.z - bf16r(v1.z), v1.w - bf16r(v1.w));
        }
        __syncthreads();
        do_mma(0);
    }

#pragma unroll
    for (int mt = 0; mt < 4; mt++) {
        int r0 = wm * 16 + mt * 64 + g;
        float e0 = __expf(acs_s[r0]);
        float e1 = __expf(acs_s[r0 + 8]);
#pragma unroll
        for (int nt = 0; nt < 4; nt++) {
            acc[mt][nt][0] *= e0; acc[mt][nt][1] *= e0;
            acc[mt][nt][2] *= e1; acc[mt][nt][3] *= e1;
        }
    }

    cf_s[tid] = __expf(acs_s[tid | 31] - acs_s[tid]);
#pragma unroll
    for (int ss = 0; ss < 8; ss++) {
        float v = 0.f;
        if (tid >= ss * 32 + 32) v = __expf(acs_s[tid] - acs_s[ss * 32 + 31]);
        rfv[ss * 256 + tid] = v;
    }

    // ---------------- Phase 2: (CB ∘ L) @ xd^T ----------
    for (int ss = 0; ss < 8; ss++) {
        int s0 = ss * 32;
        __syncthreads();
        {
            int p = tid >> 2, q = tid & 3;
            size_t src = ((size_t)bid * HD + p) * (CH / 2) + ss * 16 + q * 4;
            cp16(sb + (uint32_t)(YB_H + p * YW + q * 4) * 4, &g_xdp_h[src], true);
            cp16(sb + (uint32_t)(YB_L + p * YW + q * 4) * 4, &g_xdp_l[src], true);
            asm volatile("cp.async.commit_group;" ::: "memory");
        }
        {
            const float* rfs = &rfv[ss * 256];
#pragma unroll
            for (int it = 0; it < 8; it++) {
                int l = it * 32 + lr;
                uint32_t* dah = &Ah[l * YW + cg * 2];
                uint32_t* dal = &Al[l * YW + cg * 2];
                if (l < s0) {
                    dah[0] = 0u; dah[1] = 0u; dal[0] = 0u; dal[1] = 0u;
                    continue;
                }
                float4 cb4 = *(const float4*)&g_cb[((size_t)z * CH + l) * CH + s0 + cg * 4];
                float va, vb, vc, vd;
                int s = s0 + cg * 4;
                if (l < s0 + 32) {
                    float al = acs_s[l];
                    va = (s <= l) ? cb4.x * __expf(al - acs_s[s]) : 0.f;
                    vb = (s + 1 <= l) ? cb4.y * __expf(al - acs_s[s + 1]) : 0.f;
                    vc = (s + 2 <= l) ? cb4.z * __expf(al - acs_s[s + 2]) : 0.f;
                    vd = (s + 3 <= l) ? cb4.w * __expf(al - acs_s[s + 3]) : 0.f;
                } else {
                    float rf = rfs[l];
                    va = cb4.x * (rf * cf_s[s]);
                    vb = cb4.y * (rf * cf_s[s + 1]);
                    vc = cb4.z * (rf * cf_s[s + 2]);
                    vd = cb4.w * (rf * cf_s[s + 3]);
                }
                dah[0] = pack_bf16(va, vb);
                dah[1] = pack_bf16(vc, vd);
                dal[0] = pack_bf16(va - bf16r(va), vb - bf16r(vb));
                dal[1] = pack_bf16(vc - bf16r(vc), vd - bf16r(vd));
            }
        }
        asm volatile("cp.async.wait_group 0;" ::: "memory");
        __syncthreads();
        do_mma(s0);
    }

    // epilogue: + D*xh, write y (fp32)
    float Dh = Dvec[h];
#pragma unroll
    for (int mt = 0; mt < 4; mt++) {
        int r = wm * 16 + mt * 64 + g;
#pragma unroll
        for (int nt = 0; nt < 4; nt++) {
            int p = wn * 32 + nt * 8 + tg * 2;
            float* a = acc[mt][nt];
#pragma unroll
            for (int q = 0; q < 4; q++) {
                int row = rowbase + r + (q >> 1) * 8;
                int pp = p + (q & 1);
                float xh = g_xbc[(size_t)row * CONVD + h * HD + pp];
                g_y[(size_t)row * DI + h * HD + pp] = a[q] + Dh * xh;
            }
        }
    }
}

// -------- K10: gated rmsnorm -> bf16 hi/lo --------
__global__ void gated_norm_kernel(const float* __restrict__ gw) {
    int row = blockIdx.x, tid = threadIdx.x;
    int d0 = tid * 8;
    const float* zr = &g_zx[(size_t)row * DPROJ + d0];
    const float* yr = &g_y[(size_t)row * DI + d0];
    float v[8];
    float local = 0.f;
#pragma unroll
    for (int q = 0; q < 2; q++) {
        float4 z4 = *(const float4*)(zr + q * 4);
        float4 y4 = *(const float4*)(yr + q * 4);
        float zz[4] = {z4.x, z4.y, z4.z, z4.w};
        float yy[4] = {y4.x, y4.y, y4.z, y4.w};
#pragma unroll
        for (int j = 0; j < 4; j++) {
            float t = yy[j] * (zz[j] / (1.f + __expf(-zz[j])));
            v[q * 4 + j] = t;
            local += t * t;
        }
    }
    float tot = blockReduceSum256(local);
    float r = rsqrtf(tot / (float)DI + 1e-5f);
    int o = row * (DI / 2) + tid * 4;
#pragma unroll
    for (int j = 0; j < 4; j++) {
        float a = v[2 * j] * r * gw[d0 + 2 * j];
        float b = v[2 * j + 1] * r * gw[d0 + 2 * j + 1];
        g_yh[o + j] = pack_bf16(a, b);
        g_yl[o + j] = pack_bf16(a - bf16r(a), b - bf16r(b));
    }
}

// ---------------- launch ----------------
extern "C" void kernel_launch(void* const* d_in, const int* in_sizes, int n_in,
                              void* d_out, int out_size) {
    const float* x         = (const float*)d_in[0];
    const float* norm_w    = (const float*)d_in[1];
    const float* in_proj_w = (const float*)d_in[2];
    const float* conv_w    = (const float*)d_in[3];
    const float* conv_b    = (const float*)d_in[4];
    const float* dt_bias   = (const float*)d_in[5];
    const float* A_log     = (const float*)d_in[6];
    const float* Dv        = (const float*)d_in[7];
    const float* gnorm_w   = (const float*)d_in[8];
    const float* out_proj_w= (const float*)d_in[9];
    float* out = (float*)d_out;

    float *pzx;
    uint32_t *puh, *pul, *pyh, *pyl, *pwih, *pwil, *pwoh, *pwol;
    cudaGetSymbolAddress((void**)&pzx, g_zx);
    cudaGetSymbolAddress((void**)&puh, g_uh);
    cudaGetSymbolAddress((void**)&pul, g_ul);
    cudaGetSymbolAddress((void**)&pyh, g_yh);
    cudaGetSymbolAddress((void**)&pyl, g_yl);
    cudaGetSymbolAddress((void**)&pwih, g_wih);
    cudaGetSymbolAddress((void**)&pwil, g_wil);
    cudaGetSymbolAddress((void**)&pwoh, g_woh);
    cudaGetSymbolAddress((void**)&pwol, g_wol);

    cudaFuncSetAttribute(mma_nt_pre, cudaFuncAttributeMaxDynamicSharedMemorySize, GSMEM);
    cudaFuncSetAttribute(y_tc_kernel, cudaFuncAttributeMaxDynamicSharedMemorySize, YSMEM);
    cudaFuncSetAttribute(xdt_kernel, cudaFuncAttributeMaxDynamicSharedMemorySize, XDT_SMEM);
    cudaFuncSetAttribute(bmt_kernel, cudaFuncAttributeMaxDynamicSharedMemorySize, BMT_SMEM);

    cvt_pairs_kernel<<<(DPROJ * DM / 2 + 255) / 256, 256>>>(in_proj_w, pwih, pwil,
                                                            DPROJ * DM / 2);
    cvt_pairs_kernel<<<(DM * DI / 2 + 255) / 256, 256>>>(out_proj_w, pwoh, pwol,
                                                         DM * DI / 2);

    rmsnorm_x_kernel<<<ROWS, 256>>>(x, norm_w);
    mma_nt_pre<<<dim3((DPROJ + 127) / 128, ROWS / 128), 256, GSMEM>>>(
        puh, pul, pwih, pwil, pzx, nullptr, ROWS, DPROJ, DM, 0);
    conv_dt_kernel<<<(ROWS * CONVD + ROWS * NH) / 256, 256>>>(conv_w, conv_b, dt_bias);
    acs_kernel<<<B_ * NH * NCH, 256>>>(A_log);
    cvt_bc_kernel<<<ROWS, 128>>>();
    xdt_kernel<<<NBID, 256, XDT_SMEM>>>();
    bmt_kernel<<<dim3(2, B_ * NCH), 256, BMT_SMEM>>>();
    states_tc_kernel<<<NBID, 256>>>();
    recur_kernel<<<(B_ * NH * HD * DS) / 256, 256>>>();
    cb_tc_kernel<<<dim3(2, 2, B_ * NCH), 256>>>();
    y_tc_kernel<<<NBID, 256, YSMEM>>>(Dv);
    gated_norm_kernel<<<ROWS, 256>>>(gnorm_w);
    mma_nt_pre<<<dim3(DM / 128, ROWS / 128), 256, GSMEM>>>(
        pyh, pyl, pwoh, pwol, out, x, ROWS, DM, DI, 1);
}

// round 14
// speedup vs baseline: 1.0557x; 1.0214x over previous
#include <cuda_runtime.h>
#include <cuda_bf16.h>
#include <math.h>
#include <stdint.h>

// ---------------- problem constants ----------------
#define B_    2
#define L_    2048
#define DM    1024
#define DI    2048
#define NH    32
#define HD    64
#define DS    128
#define CONVD 2304
#define DPROJ 4384
#define NCH   8
#define CH    256
#define ROWS  4096
#define NBID  (B_ * NCH * NH)   // 512

// ---------------- scratch (device globals) ----------------
__device__ float g_zx[(size_t)ROWS * DPROJ];
__device__ float g_xbc[(size_t)ROWS * CONVD];
__device__ float g_dt[ROWS * NH];
__device__ float g_acs[B_ * NH * NCH * CH];
__device__ float g_states[(size_t)B_ * NCH * NH * HD * DS];
__device__ float g_init[(size_t)B_ * NCH * NH * HD * DS];
__device__ float g_cb[(size_t)B_ * NCH * CH * CH];
__device__ float g_y[(size_t)ROWS * DI];

// packed bf16x2 hi/lo operand arrays
__device__ uint32_t g_uh[ROWS * DM / 2];
__device__ uint32_t g_ul[ROWS * DM / 2];
__device__ uint32_t g_yh[(size_t)ROWS * DI / 2];
__device__ uint32_t g_yl[(size_t)ROWS * DI / 2];
__device__ uint32_t g_wih[(size_t)DPROJ * DM / 2];
__device__ uint32_t g_wil[(size_t)DPROJ * DM / 2];
__device__ uint32_t g_woh[(size_t)DM * DI / 2];
__device__ uint32_t g_wol[(size_t)DM * DI / 2];

// SSD precomputed operands (bf16x2 packed)
__device__ uint32_t g_xdp_h[(size_t)NBID * HD * (CH / 2)];
__device__ uint32_t g_xdp_l[(size_t)NBID * HD * (CH / 2)];
__device__ uint32_t g_xds_h[(size_t)NBID * HD * (CH / 2)];
__device__ uint32_t g_xds_l[(size_t)NBID * HD * (CH / 2)];
__device__ uint32_t g_bmt_h[(size_t)B_ * NCH * DS * (CH / 2)];
__device__ uint32_t g_bmt_l[(size_t)B_ * NCH * DS * (CH / 2)];
// row-major Bm/Cm bf16 hi/lo for CB gemm: [row][n/2]
__device__ uint32_t g_bm2_h[(size_t)ROWS * 64];
__device__ uint32_t g_bm2_l[(size_t)ROWS * 64];
__device__ uint32_t g_cm2_h[(size_t)ROWS * 64];
__device__ uint32_t g_cm2_l[(size_t)ROWS * 64];

// ---------------- helpers ----------------
__device__ __forceinline__ float blockReduceSum256(float v) {
    __shared__ float ws[8];
    __shared__ float tot;
    int lane = threadIdx.x & 31, wid = threadIdx.x >> 5;
#pragma unroll
    for (int o = 16; o; o >>= 1) v += __shfl_xor_sync(0xffffffffu, v, o);
    if (lane == 0) ws[wid] = v;
    __syncthreads();
    if (threadIdx.x == 0) {
        float s = 0.f;
#pragma unroll
        for (int i = 0; i < 8; i++) s += ws[i];
        tot = s;
    }
    __syncthreads();
    return tot;
}

__device__ __forceinline__ uint32_t pack_bf16(float a, float b) {
    __nv_bfloat162 h = __floats2bfloat162_rn(a, b);
    return *(uint32_t*)&h;
}

__device__ __forceinline__ float bf16r(float v) {
    return __bfloat162float(__float2bfloat16(v));
}

__device__ __forceinline__ uint32_t smem_u32(const void* p) {
    uint32_t a;
    asm("{ .reg .u64 t; cvta.to.shared.u64 t, %1; cvt.u32.u64 %0, t; }"
        : "=r"(a) : "l"(p));
    return a;
}

__device__ __forceinline__ void mma_bf16(float* d, const uint32_t* a, const uint32_t* b) {
    asm volatile(
        "mma.sync.aligned.m16n8k16.row.col.f32.bf16.bf16.f32 "
        "{%0,%1,%2,%3}, {%4,%5,%6,%7}, {%8,%9}, {%0,%1,%2,%3};"
        : "+f"(d[0]), "+f"(d[1]), "+f"(d[2]), "+f"(d[3])
        : "r"(a[0]), "r"(a[1]), "r"(a[2]), "r"(a[3]), "r"(b[0]), "r"(b[1]));
}

__device__ __forceinline__ void ldsm4(uint32_t* r, uint32_t addr) {
    asm volatile("ldmatrix.sync.aligned.m8n8.x4.shared.b16 {%0,%1,%2,%3}, [%4];"
                 : "=r"(r[0]), "=r"(r[1]), "=r"(r[2]), "=r"(r[3]) : "r"(addr));
}

__device__ __forceinline__ void cp16(uint32_t dst, const void* src, bool ok) {
    if (ok)
        asm volatile("cp.async.cg.shared.global [%0], [%1], 16;"
                     :: "r"(dst), "l"(src) : "memory");
    else
        asm volatile("cp.async.cg.shared.global [%0], [%1], 16, 0;"
                     :: "r"(dst), "l"(src) : "memory");
}

// ---------------- K0: split fp32 pairs -> bf16 hi/lo packed ----------
__global__ void cvt_pairs_kernel(const float* __restrict__ W,
                                 uint32_t* __restrict__ Wh,
                                 uint32_t* __restrict__ Wl, int npairs) {
    int i = blockIdx.x * blockDim.x + threadIdx.x;
    if (i < npairs) {
        float2 v = ((const float2*)W)[i];
        Wh[i] = pack_bf16(v.x, v.y);
        Wl[i] = pack_bf16(v.x - bf16r(v.x), v.y - bf16r(v.y));
    }
}

// ---------------- K1: rmsnorm(x) -> bf16 hi/lo ----------------
__global__ void rmsnorm_x_kernel(const float* __restrict__ x,
                                 const float* __restrict__ w) {
    int row = blockIdx.x, tid = threadIdx.x;
    const float4 v = ((const float4*)(x + (size_t)row * DM))[tid];
    const float4 wv = ((const float4*)w)[tid];
    float local = v.x * v.x + v.y * v.y + v.z * v.z + v.w * v.w;
    float tot = blockReduceSum256(local);
    float r = rsqrtf(tot / (float)DM + 1e-5f);
    float u0 = v.x * r * wv.x, u1 = v.y * r * wv.y;
    float u2 = v.z * r * wv.z, u3 = v.w * r * wv.w;
    int o = row * (DM / 2) + tid * 2;
    g_uh[o] = pack_bf16(u0, u1);
    g_uh[o + 1] = pack_bf16(u2, u3);
    g_ul[o] = pack_bf16(u0 - bf16r(u0), u1 - bf16r(u1));
    g_ul[o + 1] = pack_bf16(u2 - bf16r(u2), u3 - bf16r(u3));
}

// ------- tensor-core NT GEMM, preconverted bf16 hi/lo, cp.async 2-stage -------
#define UPS   (4 * 128 * 20)
#define GSMEM (2 * UPS * 4)
__global__ __launch_bounds__(256) void mma_nt_pre(const uint32_t* __restrict__ Ahg,
                                                  const uint32_t* __restrict__ Alg,
                                                  const uint32_t* __restrict__ Bhg,
                                                  const uint32_t* __restrict__ Blg,
                                                  float* __restrict__ C,
                                                  const float* __restrict__ resid,
                                                  int M, int N, int K, int addRes) {
    extern __shared__ __align__(16) uint32_t S[];
    uint32_t sbase = smem_u32(S);
    int tid = threadIdx.x;
    int warp = tid >> 5, lane = tid & 31;
    int wm = warp & 1, wn = warp >> 1;
    int bm = blockIdx.y * 128, bn = blockIdx.x * 128;
    int g = lane >> 2, tg = lane & 3;
    int K2 = K >> 1;

    int lrow = tid >> 1, lhalf = tid & 1;
    const uint32_t* pA[2] = {Ahg + (size_t)(bm + lrow) * K2 + lhalf * 8,
                             Alg + (size_t)(bm + lrow) * K2 + lhalf * 8};
    bool okB = (bn + lrow) < N;
    int brow = okB ? (bn + lrow) : 0;
    const uint32_t* pB[2] = {Bhg + (size_t)brow * K2 + lhalf * 8,
                             Blg + (size_t)brow * K2 + lhalf * 8};
    uint32_t dto = (uint32_t)(lrow * 20 + lhalf * 8) * 4;

    int mat = lane >> 3, mrow = lane & 7;
    uint32_t a_ad[4], b_ad[2];
#pragma unroll
    for (int mt = 0; mt < 4; mt++) {
        int r = wm * 64 + mt * 16 + (mat & 1) * 8 + mrow;
        a_ad[mt] = sbase + (uint32_t)(r * 20 + (mat >> 1) * 4) * 4;
    }
#pragma unroll
    for (int p = 0; p < 2; p++) {
        int n = wn * 32 + p * 16 + (mat >> 1) * 8 + mrow;
        b_ad[p] = sbase + (uint32_t)(n * 20 + (mat & 1) * 4) * 4;
    }

    float acc[4][4][4];
#pragma unroll
    for (int mt = 0; mt < 4; mt++)
#pragma unroll
        for (int nt = 0; nt < 4; nt++)
#pragma unroll
            for (int q = 0; q < 4; q++) acc[mt][nt][q] = 0.f;

    int nslab = K >> 5;

    auto issue = [&](int st, int sl) {
        int ko = sl * 16;
        uint32_t db = sbase + (uint32_t)(st * UPS) * 4 + dto;
#pragma unroll
        for (int t = 0; t < 2; t++) {
            cp16(db + (uint32_t)(t * 2560 * 4), pA[t] + ko, true);
            cp16(db + (uint32_t)(t * 2560 * 4) + 16, pA[t] + ko + 4, true);
            cp16(db + (uint32_t)((2 + t) * 2560 * 4), pB[t] + ko, okB);
            cp16(db + (uint32_t)((2 + t) * 2560 * 4) + 16, pB[t] + ko + 4, okB);
        }
        asm volatile("cp.async.commit_group;" ::: "memory");
    };

    issue(0, 0);
    int st = 0;
    for (int i = 0; i < nslab; i++) {
        if (i + 1 < nslab) {
            issue(st ^ 1, i + 1);
            asm volatile("cp.async.wait_group 1;" ::: "memory");
        } else {
            asm volatile("cp.async.wait_group 0;" ::: "memory");
        }
        __syncthreads();
        uint32_t so = (uint32_t)(st * UPS) * 4;
#pragma unroll
        for (int kk = 0; kk < 2; kk++) {
            uint32_t kb = so + kk * 32;
            uint32_t ahi[4][4], alo[4][4];
#pragma unroll
            for (int mt = 0; mt < 4; mt++) {
                ldsm4(ahi[mt], a_ad[mt] + kb);
                ldsm4(alo[mt], a_ad[mt] + kb + 2560 * 4);
            }
            uint32_t bhi[4][2], blo[4][2];
#pragma unroll
            for (int p = 0; p < 2; p++) {
                uint32_t t4[4];
                ldsm4(t4, b_ad[p] + kb + 2 * 2560 * 4);
                bhi[p * 2][0] = t4[0]; bhi[p * 2][1] = t4[1];
                bhi[p * 2 + 1][0] = t4[2]; bhi[p * 2 + 1][1] = t4[3];
                ldsm4(t4, b_ad[p] + kb + 3 * 2560 * 4);
                blo[p * 2][0] = t4[0]; blo[p * 2][1] = t4[1];
                blo[p * 2 + 1][0] = t4[2]; blo[p * 2 + 1][1] = t4[3];
            }
#pragma unroll
            for (int mt = 0; mt < 4; mt++)
#pragma unroll
                for (int nt = 0; nt < 4; nt++) {
                    mma_bf16(acc[mt][nt], ahi[mt], bhi[nt]);
                    mma_bf16(acc[mt][nt], ahi[mt], blo[nt]);
                    mma_bf16(acc[mt][nt], alo[mt], bhi[nt]);
                }
        }
        __syncthreads();
        st ^= 1;
    }

#pragma unroll
    for (int mt = 0; mt < 4; mt++) {
        int row = bm + wm * 64 + mt * 16 + g;
#pragma unroll
        for (int nt = 0; nt < 4; nt++) {
            int col = bn + wn * 32 + nt * 8 + tg * 2;
            if (col < N) {
                float* a = acc[mt][nt];
                size_t i0 = (size_t)row * N + col;
                size_t i1 = (size_t)(row + 8) * N + col;
                if (addRes) {
                    a[0] += resid[i0]; a[1] += resid[i0 + 1];
                    a[2] += resid[i1]; a[3] += resid[i1 + 1];
                }
                C[i0] = a[0]; C[i0 + 1] = a[1];
                C[i1] = a[2]; C[i1 + 1] = a[3];
            }
        }
    }
}

// ------ K3+K4: conv+silu (4 rows per thread, tap reuse) AND dt softplus ------
#define NCONV ((ROWS / 4) * CONVD)
__global__ void conv_dt_kernel(const float* __restrict__ conv_w,
                               const float* __restrict__ conv_b,
                               const float* __restrict__ dt_bias) {
    int idx = blockIdx.x * blockDim.x + threadIdx.x;
    if (idx < NCONV) {
        int c = idx % CONVD;
        int r4 = idx / CONVD;
        int R = r4 * 4;
        int l0 = R & (L_ - 1);
        const float* w = conv_w + c * 4;
        float w0 = w[0], w1 = w[1], w2 = w[2], w3 = w[3];
        float v[7];
#pragma unroll
        for (int j = 0; j < 7; j++) {
            int lj = l0 - 3 + j;
            v[j] = (lj >= 0) ? g_zx[(size_t)(R - 3 + j) * DPROJ + DI + c] : 0.f;
        }
        float bias = conv_b[c];
#pragma unroll
        for (int i = 0; i < 4; i++) {
            float acc = bias + w0 * v[i] + w1 * v[i + 1] + w2 * v[i + 2] + w3 * v[i + 3];
            float s = acc / (1.f + __expf(-acc));
            g_xbc[(size_t)(R + i) * CONVD + c] = s;
        }
    } else {
        int j = idx - NCONV;  // < ROWS*NH
        int h = j & (NH - 1);
        int row = j >> 5;
        float v = g_zx[(size_t)row * DPROJ + (DI + CONVD) + h] + dt_bias[h];
        float sp = (v > 20.f) ? v : log1pf(__expf(v));
        g_dt[row * NH + h] = sp;
    }
}

// ----- K5b: xdT precompute WITH fused acs scan -----
#define XDT_SMEM (256 * 68 * 4)
__global__ __launch_bounds__(256) void xdt_kernel(const float* __restrict__ A_log) {
    extern __shared__ float sx[];
    __shared__ float sdt[CH], sdec[CH], sacs[CH];
    int bid = blockIdx.x;
    int b = bid >> 8, c = (bid >> 5) & 7, h = bid & 31;
    int tid = threadIdx.x;
    int rowbase = b * L_ + c * CH;
    int base = ((b * NH + h) * NCH + c) * CH;
    float A = -__expf(A_log[h]);
    {
        int l = tid, row = rowbase + l;
        const float* xr = &g_xbc[(size_t)row * CONVD + h * HD];
#pragma unroll
        for (int p4 = 0; p4 < 16; p4++) {
            float4 v = ((const float4*)xr)[p4];
            *(float4*)&sx[l * 68 + p4 * 4] = v;
        }
        float dtv = g_dt[row * NH + h];
        sdt[l] = dtv;
        sacs[l] = dtv * A;
    }
    __syncthreads();
    // Hillis-Steele scan (identical to old acs_kernel)
#pragma unroll
    for (int off = 1; off < CH; off <<= 1) {
        float v = (tid >= off) ? sacs[tid - off] : 0.f;
        __syncthreads();
        sacs[tid] += v;
        __syncthreads();
    }
    float acs255 = sacs[CH - 1];
    sdec[tid] = __expf(acs255 - sacs[tid]);
    g_acs[base + tid] = sacs[tid];
    __syncthreads();

    int warp = tid >> 5, lane = tid & 31;
    size_t ob = (size_t)bid * HD * (CH / 2);
#pragma unroll
    for (int pp = 0; pp < 8; pp++) {
        int p = warp * 8 + pp;
        uint32_t oh[4], ol[4], osh[4], osl[4];
#pragma unroll
        for (int k = 0; k < 4; k++) {
            int cu = lane * 4 + k;
            int l = cu * 2;
            float va = sx[l * 68 + p] * sdt[l];
            float vb = sx[(l + 1) * 68 + p] * sdt[l + 1];
            oh[k] = pack_bf16(va, vb);
            ol[k] = pack_bf16(va - bf16r(va), vb - bf16r(vb));
            float wa = va * sdec[l], wb = vb * sdec[l + 1];
            osh[k] = pack_bf16(wa, wb);
            osl[k] = pack_bf16(wa - bf16r(wa), wb - bf16r(wb));
        }
        size_t o = ob + (size_t)p * (CH / 2) + lane * 4;
        *(uint4*)&g_xdp_h[o] = *(uint4*)oh;
        *(uint4*)&g_xdp_l[o] = *(uint4*)ol;
        *(uint4*)&g_xds_h[o] = *(uint4*)osh;
        *(uint4*)&g_xds_l[o] = *(uint4*)osl;
    }
}

// ----- K5c: Bm^T precompute -----
#define BMT_SMEM (128 * 132 * 4)
__global__ __launch_bounds__(256) void bmt_kernel() {
    extern __shared__ float sx[];
    int z = blockIdx.y, pass = blockIdx.x;
    int b = z >> 3, c = z & 7;
    int tid = threadIdx.x;
    int rowbase = b * L_ + c * CH + pass * 128;
    {
        int l = tid & 127, half = tid >> 7;
        const float* br = &g_xbc[(size_t)(rowbase + l) * CONVD + DI + half * 64];
#pragma unroll
        for (int k4 = 0; k4 < 16; k4++) {
            float4 v = ((const float4*)br)[k4];
            *(float4*)&sx[l * 132 + half * 64 + k4 * 4] = v;
        }
    }
    __syncthreads();
    int warp = tid >> 5, lane = tid & 31;
#pragma unroll
    for (int nn = 0; nn < 16; nn++) {
        int n = warp * 16 + nn;
        uint32_t h2[2], l2[2];
#pragma unroll
        for (int k = 0; k < 2; k++) {
            int cu = lane * 2 + k;
            float va = sx[(2 * cu) * 132 + n];
            float vb = sx[(2 * cu + 1) * 132 + n];
            h2[k] = pack_bf16(va, vb);
            l2[k] = pack_bf16(va - bf16r(va), vb - bf16r(vb));
        }
        size_t o = ((size_t)z * DS + n) * (CH / 2) + pass * 64 + lane * 2;
        *(uint2*)&g_bmt_h[o] = *(uint2*)h2;
        *(uint2*)&g_bmt_l[o] = *(uint2*)l2;
    }
}

// ----- K5d: row-major Bm/Cm bf16 hi/lo (for CB gemm) -----
__global__ void cvt_bc_kernel() {
    int row = blockIdx.x;
    int tid = threadIdx.x;  // 128
    int which = tid >> 6, n2 = tid & 63;
    float2 v = *(const float2*)&g_xbc[(size_t)row * CONVD + DI + which * DS + n2 * 2];
    uint32_t hh = pack_bf16(v.x, v.y);
    uint32_t ll = pack_bf16(v.x - bf16r(v.x), v.y - bf16r(v.y));
    size_t o = (size_t)row * 64 + n2;
    if (which == 0) { g_bm2_h[o] = hh; g_bm2_l[o] = ll; }
    else            { g_cm2_h[o] = hh; g_cm2_l[o] = ll; }
}

// ------ K6 (tensorized): states[n,p] ------
#define SSW 20
#define S_AH 0
#define S_AL (128 * SSW)
#define S_BH (2 * 128 * SSW)
#define S_BL (2 * 128 * SSW + 64 * SSW)
__global__ __launch_bounds__(256) void states_tc_kernel() {
    __shared__ __align__(16) uint32_t S[2 * 128 * SSW + 2 * 64 * SSW];
    uint32_t sb = smem_u32(S);
    int bid = blockIdx.x;
    int b = bid >> 8, c = (bid >> 5) & 7;
    int z = b * NCH + c;
    int tid = threadIdx.x, warp = tid >> 5, lane = tid & 31;
    int wm = warp & 3, wn = warp >> 2;
    int g = lane >> 2, tg = lane & 3;
    int mat = lane >> 3, mrow = lane & 7;

    uint32_t a_adh[2], a_adl[2], b_adh[2], b_adl[2];
#pragma unroll
    for (int mt = 0; mt < 2; mt++) {
        int r = wm * 32 + mt * 16 + (mat & 1) * 8 + mrow;
        uint32_t off = (uint32_t)(r * SSW + (mat >> 1) * 4) * 4;
        a_adh[mt] = sb + S_AH * 4 + off;
        a_adl[mt] = sb + S_AL * 4 + off;
    }
#pragma unroll
    for (int p = 0; p < 2; p++) {
        int n = wn * 32 + p * 16 + (mat >> 1) * 8 + mrow;
        uint32_t off = (uint32_t)(n * SSW + (mat & 1) * 4) * 4;
        b_adh[p] = sb + S_BH * 4 + off;
        b_adl[p] = sb + S_BL * 4 + off;
    }

    float acc[2][4][4];
#pragma unroll
    for (int mt = 0; mt < 2; mt++)
#pragma unroll
        for (int nt = 0; nt < 4; nt++)
#pragma unroll
            for (int q = 0; q < 4; q++) acc[mt][nt][q] = 0.f;

    for (int j = 0; j < 8; j++) {
        __syncthreads();
        {
            int n = tid >> 1, half = tid & 1;
            size_t src = ((size_t)z * DS + n) * (CH / 2) + j * 16 + half * 8;
            uint32_t d = sb + (uint32_t)(S_AH + n * SSW + half * 8) * 4;
            cp16(d, &g_bmt_h[src], true);
            cp16(d + 16, &g_bmt_h[src + 4], true);
            uint32_t d2 = sb + (uint32_t)(S_AL + n * SSW + half * 8) * 4;
            cp16(d2, &g_bmt_l[src], true);
            cp16(d2 + 16, &g_bmt_l[src + 4], true);
        }
        {
            int p = tid >> 2, q = tid & 3;
            size_t src = ((size_t)bid * HD + p) * (CH / 2) + j * 16 + q * 4;
            cp16(sb + (uint32_t)(S_BH + p * SSW + q * 4) * 4, &g_xds_h[src], true);
            cp16(sb + (uint32_t)(S_BL + p * SSW + q * 4) * 4, &g_xds_l[src], true);
        }
        asm volatile("cp.async.commit_group;" ::: "memory");
        asm volatile("cp.async.wait_group 0;" ::: "memory");
        __syncthreads();
#pragma unroll
        for (int kk = 0; kk < 2; kk++) {
            uint32_t kb = kk * 32;
            uint32_t ahi[2][4], alo[2][4];
#pragma unroll
            for (int mt = 0; mt < 2; mt++) {
                ldsm4(ahi[mt], a_adh[mt] + kb);
                ldsm4(alo[mt], a_adl[mt] + kb);
            }
            uint32_t bhi[4][2], blo[4][2];
#pragma unroll
            for (int p = 0; p < 2; p++) {
                uint32_t t4[4];
                ldsm4(t4, b_adh[p] + kb);
                bhi[p * 2][0] = t4[0]; bhi[p * 2][1] = t4[1];
                bhi[p * 2 + 1][0] = t4[2]; bhi[p * 2 + 1][1] = t4[3];
                ldsm4(t4, b_adl[p] + kb);
                blo[p * 2][0] = t4[0]; blo[p * 2][1] = t4[1];
                blo[p * 2 + 1][0] = t4[2]; blo[p * 2 + 1][1] = t4[3];
            }
#pragma unroll
            for (int mt = 0; mt < 2; mt++)
#pragma unroll
                for (int nt = 0; nt < 4; nt++) {
                    mma_bf16(acc[mt][nt], ahi[mt], bhi[nt]);
                    mma_bf16(acc[mt][nt], ahi[mt], blo[nt]);
                    mma_bf16(acc[mt][nt], alo[mt], bhi[nt]);
                }
        }
    }

    size_t out = (size_t)bid * HD * DS;
#pragma unroll
    for (int mt = 0; mt < 2; mt++) {
#pragma unroll
        for (int nt = 0; nt < 4; nt++) {
            float* a = acc[mt][nt];
#pragma unroll
            for (int q = 0; q < 4; q++) {
                int n = wm * 32 + mt * 16 + g + (q >> 1) * 8;
                int p = wn * 32 + nt * 8 + tg * 2 + (q & 1);
                g_states[out + (size_t)p * DS + n] = a[q];
            }
        }
    }
}

// ---------------- K7: chunk recurrence ----------
__global__ void recur_kernel() {
    int idx = blockIdx.x * blockDim.x + threadIdx.x;
    int n = idx & 127;
    int p = (idx >> 7) & 63;
    int h = (idx >> 13) & 31;
    int b = idx >> 18;
    float run = 0.f;
#pragma unroll
    for (int c = 0; c < NCH; c++) {
        size_t sidx = ((size_t)((b * NCH + c) * NH + h) * HD + p) * DS + n;
        g_init[sidx] = run;
        float cs = g_acs[((b * NH + h) * NCH + c) * CH + CH - 1];
        run = run * __expf(cs) + g_states[sidx];
    }
}

// ------ K8 (tensorized): CB[l,s] = Cm[l]·Bm[s], 128x128x128 tiles ------
#define CBW 20
#define C_AH 0
#define C_AL (128 * CBW)
#define C_BH (2 * 128 * CBW)
#define C_BL (3 * 128 * CBW)
__global__ __launch_bounds__(256) void cb_tc_kernel() {
    __shared__ __align__(16) uint32_t S[4 * 128 * CBW];
    uint32_t sb = smem_u32(S);
    int z = blockIdx.z;
    int b = z >> 3, c = z & 7;
    int l0 = blockIdx.y * 128, s0 = blockIdx.x * 128;
    int rowbase = b * L_ + c * CH;
    int tid = threadIdx.x, warp = tid >> 5, lane = tid & 31;
    int wm = warp & 1, wn = warp >> 1;
    int g = lane >> 2, tg = lane & 3;
    int mat = lane >> 3, mrow = lane & 7;

    uint32_t a_adh[4], a_adl[4], b_adh[2], b_adl[2];
#pragma unroll
    for (int mt = 0; mt < 4; mt++) {
        int r = wm * 64 + mt * 16 + (mat & 1) * 8 + mrow;
        uint32_t off = (uint32_t)(r * CBW + (mat >> 1) * 4) * 4;
        a_adh[mt] = sb + C_AH * 4 + off;
        a_adl[mt] = sb + C_AL * 4 + off;
    }
#pragma unroll
    for (int p = 0; p < 2; p++) {
        int n = wn * 32 + p * 16 + (mat >> 1) * 8 + mrow;
        uint32_t off = (uint32_t)(n * CBW + (mat & 1) * 4) * 4;
        b_adh[p] = sb + C_BH * 4 + off;
        b_adl[p] = sb + C_BL * 4 + off;
    }

    float acc[4][4][4];
#pragma unroll
    for (int mt = 0; mt < 4; mt++)
#pragma unroll
        for (int nt = 0; nt < 4; nt++)
#pragma unroll
            for (int q = 0; q < 4; q++) acc[mt][nt][q] = 0.f;

    for (int ks = 0; ks < 4; ks++) {
        __syncthreads();
        {
            int r = tid >> 1, half = tid & 1;
            size_t asrc = (size_t)(rowbase + l0 + r) * 64 + ks * 16 + half * 8;
            uint32_t d = sb + (uint32_t)(C_AH + r * CBW + half * 8) * 4;
            cp16(d, &g_cm2_h[asrc], true);
            cp16(d + 16, &g_cm2_h[asrc + 4], true);
            uint32_t d2 = sb + (uint32_t)(C_AL + r * CBW + half * 8) * 4;
            cp16(d2, &g_cm2_l[asrc], true);
            cp16(d2 + 16, &g_cm2_l[asrc + 4], true);
            size_t bsrc = (size_t)(rowbase + s0 + r) * 64 + ks * 16 + half * 8;
            uint32_t d3 = sb + (uint32_t)(C_BH + r * CBW + half * 8) * 4;
            cp16(d3, &g_bm2_h[bsrc], true);
            cp16(d3 + 16, &g_bm2_h[bsrc + 4], true);
            uint32_t d4 = sb + (uint32_t)(C_BL + r * CBW + half * 8) * 4;
            cp16(d4, &g_bm2_l[bsrc], true);
            cp16(d4 + 16, &g_bm2_l[bsrc + 4], true);
        }
        asm volatile("cp.async.commit_group;" ::: "memory");
        asm volatile("cp.async.wait_group 0;" ::: "memory");
        __syncthreads();
#pragma unroll
        for (int kk = 0; kk < 2; kk++) {
            uint32_t kb = kk * 32;
            uint32_t ahi[4][4], alo[4][4];
#pragma unroll
            for (int mt = 0; mt < 4; mt++) {
                ldsm4(ahi[mt], a_adh[mt] + kb);
                ldsm4(alo[mt], a_adl[mt] + kb);
            }
            uint32_t bhi[4][2], blo[4][2];
#pragma unroll
            for (int p = 0; p < 2; p++) {
                uint32_t t4[4];
                ldsm4(t4, b_adh[p] + kb);
                bhi[p * 2][0] = t4[0]; bhi[p * 2][1] = t4[1];
                bhi[p * 2 + 1][0] = t4[2]; bhi[p * 2 + 1][1] = t4[3];
                ldsm4(t4, b_adl[p] + kb);
                blo[p * 2][0] = t4[0]; blo[p * 2][1] = t4[1];
                blo[p * 2 + 1][0] = t4[2]; blo[p * 2 + 1][1] = t4[3];
            }
#pragma unroll
            for (int mt = 0; mt < 4; mt++)
#pragma unroll
                for (int nt = 0; nt < 4; nt++) {
                    mma_bf16(acc[mt][nt], ahi[mt], bhi[nt]);
                    mma_bf16(acc[mt][nt], ahi[mt], blo[nt]);
                    mma_bf16(acc[mt][nt], alo[mt], bhi[nt]);
                }
        }
    }

#pragma unroll
    for (int mt = 0; mt < 4; mt++) {
        int row = l0 + wm * 64 + mt * 16 + g;
#pragma unroll
        for (int nt = 0; nt < 4; nt++) {
            int col = s0 + wn * 32 + nt * 8 + tg * 2;
            float* a = acc[mt][nt];
            size_t i0 = ((size_t)z * CH + row) * CH + col;
            size_t i1 = ((size_t)z * CH + row + 8) * CH + col;
            g_cb[i0] = a[0]; g_cb[i0 + 1] = a[1];
            g_cb[i1] = a[2]; g_cb[i1 + 1] = a[3];
        }
    }
}

// ------ K9: Y[256,64]; interleaved causal tile mapping ------
#define YW 20
#define YA_H 0
#define YA_L (256 * YW)
#define YB_H (2 * 256 * YW)
#define YB_L (2 * 256 * YW + 64 * YW)
#define YACS (2 * 256 * YW + 2 * 64 * YW)
#define YCF  (YACS + 256)
#define YRF  (YCF + 256)
#define YSMEM ((YRF + 8 * 256) * 4)
__global__ __launch_bounds__(256) void y_tc_kernel(const float* __restrict__ Dvec) {
    extern __shared__ __align__(16) uint32_t S[];
    uint32_t* Ah = S + YA_H;
    uint32_t* Al = S + YA_L;
    uint32_t* Bh = S + YB_H;
    uint32_t* Bl = S + YB_L;
    float* acs_s = (float*)(S + YACS);
    float* cf_s = (float*)(S + YCF);
    float* rfv = (float*)(S + YRF);
    uint32_t sb = smem_u32(S);

    int bid = blockIdx.x;
    int b = bid >> 8, c = (bid >> 5) & 7, h = bid & 31;
    int z = b * NCH + c;
    int tid = threadIdx.x, warp = tid >> 5, lane = tid & 31;
    int wm = warp & 3, wn = warp >> 2;
    int g = lane >> 2, tg = lane & 3;
    int base = ((b * NH + h) * NCH + c) * CH;
    acs_s[tid] = g_acs[base + tid];
    int rowbase = b * L_ + c * CH;
    size_t initbase = (size_t)bid * HD * DS;
    int lr = tid >> 3, cg = tid & 7;

    int mat = lane >> 3, mrow = lane & 7;
    uint32_t a_adh[4], a_adl[4], b_adh[2], b_adl[2];
#pragma unroll
    for (int mt = 0; mt < 4; mt++) {
        int r = wm * 16 + mt * 64 + (mat & 1) * 8 + mrow;   // interleaved
        uint32_t off = (uint32_t)(r * YW + (mat >> 1) * 4) * 4;
        a_adh[mt] = sb + YA_H * 4 + off;
        a_adl[mt] = sb + YA_L * 4 + off;
    }
#pragma unroll
    for (int p = 0; p < 2; p++) {
        int n = wn * 32 + p * 16 + (mat >> 1) * 8 + mrow;
        uint32_t off = (uint32_t)(n * YW + (mat & 1) * 4) * 4;
        b_adh[p] = sb + YB_H * 4 + off;
        b_adl[p] = sb + YB_L * 4 + off;
    }

    float acc[4][4][4];
#pragma unroll
    for (int mt = 0; mt < 4; mt++)
#pragma unroll
        for (int nt = 0; nt < 4; nt++)
#pragma unroll
            for (int q = 0; q < 4; q++) acc[mt][nt][q] = 0.f;

    auto do_mma = [&](int s0) {
        bool act[4];
#pragma unroll
        for (int mt = 0; mt < 4; mt++) act[mt] = (wm * 16 + mt * 64 + 15 >= s0);
        if (!act[3]) return;
#pragma unroll
        for (int kk = 0; kk < 2; kk++) {
            uint32_t kb = kk * 32;
            uint32_t ahi[4][4], alo[4][4];
#pragma unroll
            for (int mt = 0; mt < 4; mt++)
                if (act[mt]) {
                    ldsm4(ahi[mt], a_adh[mt] + kb);
                    ldsm4(alo[mt], a_adl[mt] + kb);
                }
            uint32_t bhi[4][2], blo[4][2];
#pragma unroll
            for (int p = 0; p < 2; p++) {
                uint32_t t4[4];
                ldsm4(t4, b_adh[p] + kb);
                bhi[p * 2][0] = t4[0]; bhi[p * 2][1] = t4[1];
                bhi[p * 2 + 1][0] = t4[2]; bhi[p * 2 + 1][1] = t4[3];
                ldsm4(t4, b_adl[p] + kb);
                blo[p * 2][0] = t4[0]; blo[p * 2][1] = t4[1];
                blo[p * 2 + 1][0] = t4[2]; blo[p * 2 + 1][1] = t4[3];
            }
#pragma unroll
            for (int mt = 0; mt < 4; mt++)
                if (act[mt])
#pragma unroll
                    for (int nt = 0; nt < 4; nt++) {
                        mma_bf16(acc[mt][nt], ahi[mt], bhi[nt]);
                        mma_bf16(acc[mt][nt], ahi[mt], blo[nt]);
                        mma_bf16(acc[mt][nt], alo[mt], bhi[nt]);
                    }
        }
    };

    // ---------------- Phase 1: Cm @ init^T (coalesced fills) ----------
    for (int ks = 0; ks < 4; ks++) {
        __syncthreads();
        {
#pragma unroll
            for (int it = 0; it < 8; it++) {
                int l = it * 32 + lr;
                float4 v = *(const float4*)&g_xbc[(size_t)(rowbase + l) * CONVD +
                                                  DI + DS + ks * 32 + cg * 4];
                uint32_t* dah = &Ah[l * YW + cg * 2];
                uint32_t* dal = &Al[l * YW + cg * 2];
                dah[0] = pack_bf16(v.x, v.y);
                dah[1] = pack_bf16(v.z, v.w);
                dal[0] = pack_bf16(v.x - bf16r(v.x), v.y - bf16r(v.y));
                dal[1] = pack_bf16(v.z - bf16r(v.z), v.w - bf16r(v.w));
            }
        }
        {
            int p = tid >> 2, q0 = tid & 3;
            const float* ir = &g_init[initbase + (size_t)p * DS + ks * 32 + q0 * 8];
            float4 v0 = ((const float4*)ir)[0];
            float4 v1 = ((const float4*)ir)[1];
            uint32_t* dbh = &Bh[p * YW + q0 * 4];
            uint32_t* dbl = &Bl[p * YW + q0 * 4];
            dbh[0] = pack_bf16(v0.x, v0.y);
            dbh[1] = pack_bf16(v0.z, v0.w);
            dbh[2] = pack_bf16(v1.x, v1.y);
            dbh[3] = pack_bf16(v1.z, v1.w);
            dbl[0] = pack_bf16(v0.x - bf16r(v0.x), v0.y - bf16r(v0.y));
            dbl[1] = pack_bf16(v0.z - bf16r(v0.z), v0.w - bf16r(v0.w));
            dbl[2] = pack_bf16(v1.x - bf16r(v1.x), v1.y - bf16r(v1.y));
            dbl[3] = pack_bf16(v1.z - bf16r(v1.z), v1.w - bf16r(v1.w));
        }
        __syncthreads();
        do_mma(0);
    }

#pragma unroll
    for (int mt = 0; mt < 4; mt++) {
        int r0 = wm * 16 + mt * 64 + g;
        float e0 = __expf(acs_s[r0]);
        float e1 = __expf(acs_s[r0 + 8]);
#pragma unroll
        for (int nt = 0; nt < 4; nt++) {
            acc[mt][nt][0] *= e0; acc[mt][nt][1] *= e0;
            acc[mt][nt][2] *= e1; acc[mt][nt][3] *= e1;
        }
    }

    cf_s[tid] = __expf(acs_s[tid | 31] - acs_s[tid]);
#pragma unroll
    for (int ss = 0; ss < 8; ss++) {
        float v = 0.f;
        if (tid >= ss * 32 + 32) v = __expf(acs_s[tid] - acs_s[ss * 32 + 31]);
        rfv[ss * 256 + tid] = v;
    }

    // ---------------- Phase 2: (CB ∘ L) @ xd^T ----------
    for (int ss = 0; ss < 8; ss++) {
        int s0 = ss * 32;
        __syncthreads();
        {
            int p = tid >> 2, q = tid & 3;
            size_t src = ((size_t)bid * HD + p) * (CH / 2) + ss * 16 + q * 4;
            cp16(sb + (uint32_t)(YB_H + p * YW + q * 4) * 4, &g_xdp_h[src], true);
            cp16(sb + (uint32_t)(YB_L + p * YW + q * 4) * 4, &g_xdp_l[src], true);
            asm volatile("cp.async.commit_group;" ::: "memory");
        }
        {
            const float* rfs = &rfv[ss * 256];
#pragma unroll
            for (int it = 0; it < 8; it++) {
                int l = it * 32 + lr;
                uint32_t* dah = &Ah[l * YW + cg * 2];
                uint32_t* dal = &Al[l * YW + cg * 2];
                if (l < s0) {
                    dah[0] = 0u; dah[1] = 0u; dal[0] = 0u; dal[1] = 0u;
                    continue;
                }
                float4 cb4 = *(const float4*)&g_cb[((size_t)z * CH + l) * CH + s0 + cg * 4];
                float va, vb, vc, vd;
                int s = s0 + cg * 4;
                if (l < s0 + 32) {
                    float al = acs_s[l];
                    va = (s <= l) ? cb4.x * __expf(al - acs_s[s]) : 0.f;
                    vb = (s + 1 <= l) ? cb4.y * __expf(al - acs_s[s + 1]) : 0.f;
                    vc = (s + 2 <= l) ? cb4.z * __expf(al - acs_s[s + 2]) : 0.f;
                    vd = (s + 3 <= l) ? cb4.w * __expf(al - acs_s[s + 3]) : 0.f;
                } else {
                    float rf = rfs[l];
                    va = cb4.x * (rf * cf_s[s]);
                    vb = cb4.y * (rf * cf_s[s + 1]);
                    vc = cb4.z * (rf * cf_s[s + 2]);
                    vd = cb4.w * (rf * cf_s[s + 3]);
                }
                dah[0] = pack_bf16(va, vb);
                dah[1] = pack_bf16(vc, vd);
                dal[0] = pack_bf16(va - bf16r(va), vb - bf16r(vb));
                dal[1] = pack_bf16(vc - bf16r(vc), vd - bf16r(vd));
            }
        }
        asm volatile("cp.async.wait_group 0;" ::: "memory");
        __syncthreads();
        do_mma(s0);
    }

    // epilogue: + D*xh, write y (fp32)
    float Dh = Dvec[h];
#pragma unroll
    for (int mt = 0; mt < 4; mt++) {
        int r = wm * 16 + mt * 64 + g;
#pragma unroll
        for (int nt = 0; nt < 4; nt++) {
            int p = wn * 32 + nt * 8 + tg * 2;
            float* a = acc[mt][nt];
#pragma unroll
            for (int q = 0; q < 4; q++) {
                int row = rowbase + r + (q >> 1) * 8;
                int pp = p + (q & 1);
                float xh = g_xbc[(size_t)row * CONVD + h * HD + pp];
                g_y[(size_t)row * DI + h * HD + pp] = a[q] + Dh * xh;
            }
        }
    }
}

// -------- K10: gated rmsnorm -> bf16 hi/lo --------
__global__ void gated_norm_kernel(const float* __restrict__ gw) {
    int row = blockIdx.x, tid = threadIdx.x;
    int d0 = tid * 8;
    const float* zr = &g_zx[(size_t)row * DPROJ + d0];
    const float* yr = &g_y[(size_t)row * DI + d0];
    float v[8];
    float local = 0.f;
#pragma unroll
    for (int q = 0; q < 2; q++) {
        float4 z4 = *(const float4*)(zr + q * 4);
        float4 y4 = *(const float4*)(yr + q * 4);
        float zz[4] = {z4.x, z4.y, z4.z, z4.w};
        float yy[4] = {y4.x, y4.y, y4.z, y4.w};
#pragma unroll
        for (int j = 0; j < 4; j++) {
            float t = yy[j] * (zz[j] / (1.f + __expf(-zz[j])));
            v[q * 4 + j] = t;
            local += t * t;
        }
    }
    float tot = blockReduceSum256(local);
    float r = rsqrtf(tot / (float)DI + 1e-5f);
    int o = row * (DI / 2) + tid * 4;
#pragma unroll
    for (int j = 0; j < 4; j++) {
        float a = v[2 * j] * r * gw[d0 + 2 * j];
        float b = v[2 * j + 1] * r * gw[d0 + 2 * j + 1];
        g_yh[o + j] = pack_bf16(a, b);
        g_yl[o + j] = pack_bf16(a - bf16r(a), b - bf16r(b));
    }
}

// ---------------- launch ----------------
extern "C" void kernel_launch(void* const* d_in, const int* in_sizes, int n_in,
                              void* d_out, int out_size) {
    const float* x         = (const float*)d_in[0];
    const float* norm_w    = (const float*)d_in[1];
    const float* in_proj_w = (const float*)d_in[2];
    const float* conv_w    = (const float*)d_in[3];
    const float* conv_b    = (const float*)d_in[4];
    const float* dt_bias   = (const float*)d_in[5];
    const float* A_log     = (const float*)d_in[6];
    const float* Dv        = (const float*)d_in[7];
    const float* gnorm_w   = (const float*)d_in[8];
    const float* out_proj_w= (const float*)d_in[9];
    float* out = (float*)d_out;

    float *pzx;
    uint32_t *puh, *pul, *pyh, *pyl, *pwih, *pwil, *pwoh, *pwol;
    cudaGetSymbolAddress((void**)&pzx, g_zx);
    cudaGetSymbolAddress((void**)&puh, g_uh);
    cudaGetSymbolAddress((void**)&pul, g_ul);
    cudaGetSymbolAddress((void**)&pyh, g_yh);
    cudaGetSymbolAddress((void**)&pyl, g_yl);
    cudaGetSymbolAddress((void**)&pwih, g_wih);
    cudaGetSymbolAddress((void**)&pwil, g_wil);
    cudaGetSymbolAddress((void**)&pwoh, g_woh);
    cudaGetSymbolAddress((void**)&pwol, g_wol);

    cudaFuncSetAttribute(mma_nt_pre, cudaFuncAttributeMaxDynamicSharedMemorySize, GSMEM);
    cudaFuncSetAttribute(y_tc_kernel, cudaFuncAttributeMaxDynamicSharedMemorySize, YSMEM);
    cudaFuncSetAttribute(xdt_kernel, cudaFuncAttributeMaxDynamicSharedMemorySize, XDT_SMEM);
    cudaFuncSetAttribute(bmt_kernel, cudaFuncAttributeMaxDynamicSharedMemorySize, BMT_SMEM);

    cvt_pairs_kernel<<<(DPROJ * DM / 2 + 255) / 256, 256>>>(in_proj_w, pwih, pwil,
                                                            DPROJ * DM / 2);
    cvt_pairs_kernel<<<(DM * DI / 2 + 255) / 256, 256>>>(out_proj_w, pwoh, pwol,
                                                         DM * DI / 2);

    rmsnorm_x_kernel<<<ROWS, 256>>>(x, norm_w);
    mma_nt_pre<<<dim3((DPROJ + 127) / 128, ROWS / 128), 256, GSMEM>>>(
        puh, pul, pwih, pwil, pzx, nullptr, ROWS, DPROJ, DM, 0);
    conv_dt_kernel<<<(NCONV + ROWS * NH) / 256, 256>>>(conv_w, conv_b, dt_bias);
    cvt_bc_kernel<<<ROWS, 128>>>();
    xdt_kernel<<<NBID, 256, XDT_SMEM>>>(A_log);
    bmt_kernel<<<dim3(2, B_ * NCH), 256, BMT_SMEM>>>();
    states_tc_kernel<<<NBID, 256>>>();
    recur_kernel<<<(B_ * NH * HD * DS) / 256, 256>>>();
    cb_tc_kernel<<<dim3(2, 2, B_ * NCH), 256>>>();
    y_tc_kernel<<<NBID, 256, YSMEM>>>(Dv);
    gated_norm_kernel<<<ROWS, 256>>>(gnorm_w);
    mma_nt_pre<<<dim3(DM / 128, ROWS / 128), 256, GSMEM>>>(
        pyh, pyl, pwoh, pwol, out, x, ROWS, DM, DI, 1);
}

// round 15
// speedup vs baseline: 1.0631x; 1.0070x over previous
#include <cuda_runtime.h>
#include <cuda_bf16.h>
#include <math.h>
#include <stdint.h>

// ---------------- problem constants ----------------
#define B_    2
#define L_    2048
#define DM    1024
#define DI    2048
#define NH    32
#define HD    64
#define DS    128
#define CONVD 2304
#define DPROJ 4384
#define NCH   8
#define CH    256
#define ROWS  4096
#define NBID  (B_ * NCH * NH)   // 512

// ---------------- scratch (device globals) ----------------
__device__ float g_zx[(size_t)ROWS * DPROJ];
__device__ float g_xbc[(size_t)ROWS * CONVD];
__device__ float g_dt[ROWS * NH];
__device__ float g_acs[B_ * NH * NCH * CH];
__device__ float g_states[(size_t)B_ * NCH * NH * HD * DS];
__device__ float g_init[(size_t)B_ * NCH * NH * HD * DS];
__device__ float g_cb[(size_t)B_ * NCH * CH * CH];
__device__ float g_y[(size_t)ROWS * DI];

// packed bf16x2 hi/lo operand arrays
__device__ uint32_t g_uh[ROWS * DM / 2];
__device__ uint32_t g_ul[ROWS * DM / 2];
__device__ uint32_t g_yh[(size_t)ROWS * DI / 2];
__device__ uint32_t g_yl[(size_t)ROWS * DI / 2];
__device__ uint32_t g_wih[(size_t)DPROJ * DM / 2];
__device__ uint32_t g_wil[(size_t)DPROJ * DM / 2];
__device__ uint32_t g_woh[(size_t)DM * DI / 2];
__device__ uint32_t g_wol[(size_t)DM * DI / 2];

// SSD precomputed operands (bf16x2 packed)
__device__ uint32_t g_xdp_h[(size_t)NBID * HD * (CH / 2)];
__device__ uint32_t g_xdp_l[(size_t)NBID * HD * (CH / 2)];
__device__ uint32_t g_xds_h[(size_t)NBID * HD * (CH / 2)];
__device__ uint32_t g_xds_l[(size_t)NBID * HD * (CH / 2)];
__device__ uint32_t g_bmt_h[(size_t)B_ * NCH * DS * (CH / 2)];
__device__ uint32_t g_bmt_l[(size_t)B_ * NCH * DS * (CH / 2)];
// row-major Bm/Cm bf16 hi/lo for CB gemm: [row][n/2]
__device__ uint32_t g_bm2_h[(size_t)ROWS * 64];
__device__ uint32_t g_bm2_l[(size_t)ROWS * 64];
__device__ uint32_t g_cm2_h[(size_t)ROWS * 64];
__device__ uint32_t g_cm2_l[(size_t)ROWS * 64];

// ---------------- helpers ----------------
__device__ __forceinline__ float blockReduceSum256(float v) {
    __shared__ float ws[8];
    __shared__ float tot;
    int lane = threadIdx.x & 31, wid = threadIdx.x >> 5;
#pragma unroll
    for (int o = 16; o; o >>= 1) v += __shfl_xor_sync(0xffffffffu, v, o);
    if (lane == 0) ws[wid] = v;
    __syncthreads();
    if (threadIdx.x == 0) {
        float s = 0.f;
#pragma unroll
        for (int i = 0; i < 8; i++) s += ws[i];
        tot = s;
    }
    __syncthreads();
    return tot;
}

__device__ __forceinline__ uint32_t pack_bf16(float a, float b) {
    __nv_bfloat162 h = __floats2bfloat162_rn(a, b);
    return *(uint32_t*)&h;
}

__device__ __forceinline__ float bf16r(float v) {
    return __bfloat162float(__float2bfloat16(v));
}

// silu via single-MUFU tanh.approx: x*sigmoid(x) = 0.5*x*(1+tanh(x/2))
__device__ __forceinline__ float silu_f(float x) {
    float t;
    asm("tanh.approx.f32 %0, %1;" : "=f"(t) : "f"(x * 0.5f));
    return 0.5f * x * (1.f + t);
}

__device__ __forceinline__ uint32_t smem_u32(const void* p) {
    uint32_t a;
    asm("{ .reg .u64 t; cvta.to.shared.u64 t, %1; cvt.u32.u64 %0, t; }"
        : "=r"(a) : "l"(p));
    return a;
}

__device__ __forceinline__ void mma_bf16(float* d, const uint32_t* a, const uint32_t* b) {
    asm volatile(
        "mma.sync.aligned.m16n8k16.row.col.f32.bf16.bf16.f32 "
        "{%0,%1,%2,%3}, {%4,%5,%6,%7}, {%8,%9}, {%0,%1,%2,%3};"
        : "+f"(d[0]), "+f"(d[1]), "+f"(d[2]), "+f"(d[3])
        : "r"(a[0]), "r"(a[1]), "r"(a[2]), "r"(a[3]), "r"(b[0]), "r"(b[1]));
}

__device__ __forceinline__ void ldsm4(uint32_t* r, uint32_t addr) {
    asm volatile("ldmatrix.sync.aligned.m8n8.x4.shared.b16 {%0,%1,%2,%3}, [%4];"
                 : "=r"(r[0]), "=r"(r[1]), "=r"(r[2]), "=r"(r[3]) : "r"(addr));
}

__device__ __forceinline__ void cp16(uint32_t dst, const void* src, bool ok) {
    if (ok)
        asm volatile("cp.async.cg.shared.global [%0], [%1], 16;"
                     :: "r"(dst), "l"(src) : "memory");
    else
        asm volatile("cp.async.cg.shared.global [%0], [%1], 16, 0;"
                     :: "r"(dst), "l"(src) : "memory");
}

// ---------------- K0: split fp32 pairs -> bf16 hi/lo packed ----------
__global__ void cvt_pairs_kernel(const float* __restrict__ W,
                                 uint32_t* __restrict__ Wh,
                                 uint32_t* __restrict__ Wl, int npairs) {
    int i = blockIdx.x * blockDim.x + threadIdx.x;
    if (i < npairs) {
        float2 v = ((const float2*)W)[i];
        Wh[i] = pack_bf16(v.x, v.y);
        Wl[i] = pack_bf16(v.x - bf16r(v.x), v.y - bf16r(v.y));
    }
}

// ---------------- K1: rmsnorm(x) -> bf16 hi/lo ----------------
__global__ void rmsnorm_x_kernel(const float* __restrict__ x,
                                 const float* __restrict__ w) {
    int row = blockIdx.x, tid = threadIdx.x;
    const float4 v = ((const float4*)(x + (size_t)row * DM))[tid];
    const float4 wv = ((const float4*)w)[tid];
    float local = v.x * v.x + v.y * v.y + v.z * v.z + v.w * v.w;
    float tot = blockReduceSum256(local);
    float r = rsqrtf(tot / (float)DM + 1e-5f);
    float u0 = v.x * r * wv.x, u1 = v.y * r * wv.y;
    float u2 = v.z * r * wv.z, u3 = v.w * r * wv.w;
    int o = row * (DM / 2) + tid * 2;
    g_uh[o] = pack_bf16(u0, u1);
    g_uh[o + 1] = pack_bf16(u2, u3);
    g_ul[o] = pack_bf16(u0 - bf16r(u0), u1 - bf16r(u1));
    g_ul[o + 1] = pack_bf16(u2 - bf16r(u2), u3 - bf16r(u3));
}

// ------- tensor-core NT GEMM, preconverted bf16 hi/lo, cp.async 2-stage -------
#define UPS   (4 * 128 * 20)
#define GSMEM (2 * UPS * 4)
__global__ __launch_bounds__(256) void mma_nt_pre(const uint32_t* __restrict__ Ahg,
                                                  const uint32_t* __restrict__ Alg,
                                                  const uint32_t* __restrict__ Bhg,
                                                  const uint32_t* __restrict__ Blg,
                                                  float* __restrict__ C,
                                                  const float* __restrict__ resid,
                                                  int M, int N, int K, int addRes) {
    extern __shared__ __align__(16) uint32_t S[];
    uint32_t sbase = smem_u32(S);
    int tid = threadIdx.x;
    int warp = tid >> 5, lane = tid & 31;
    int wm = warp & 1, wn = warp >> 1;
    int bm = blockIdx.y * 128, bn = blockIdx.x * 128;
    int g = lane >> 2, tg = lane & 3;
    int K2 = K >> 1;

    int lrow = tid >> 1, lhalf = tid & 1;
    const uint32_t* pA[2] = {Ahg + (size_t)(bm + lrow) * K2 + lhalf * 8,
                             Alg + (size_t)(bm + lrow) * K2 + lhalf * 8};
    bool okB = (bn + lrow) < N;
    int brow = okB ? (bn + lrow) : 0;
    const uint32_t* pB[2] = {Bhg + (size_t)brow * K2 + lhalf * 8,
                             Blg + (size_t)brow * K2 + lhalf * 8};
    uint32_t dto = (uint32_t)(lrow * 20 + lhalf * 8) * 4;

    int mat = lane >> 3, mrow = lane & 7;
    uint32_t a_ad[4], b_ad[2];
#pragma unroll
    for (int mt = 0; mt < 4; mt++) {
        int r = wm * 64 + mt * 16 + (mat & 1) * 8 + mrow;
        a_ad[mt] = sbase + (uint32_t)(r * 20 + (mat >> 1) * 4) * 4;
    }
#pragma unroll
    for (int p = 0; p < 2; p++) {
        int n = wn * 32 + p * 16 + (mat >> 1) * 8 + mrow;
        b_ad[p] = sbase + (uint32_t)(n * 20 + (mat & 1) * 4) * 4;
    }

    float acc[4][4][4];
#pragma unroll
    for (int mt = 0; mt < 4; mt++)
#pragma unroll
        for (int nt = 0; nt < 4; nt++)
#pragma unroll
            for (int q = 0; q < 4; q++) acc[mt][nt][q] = 0.f;

    int nslab = K >> 5;

    auto issue = [&](int st, int sl) {
        int ko = sl * 16;
        uint32_t db = sbase + (uint32_t)(st * UPS) * 4 + dto;
#pragma unroll
        for (int t = 0; t < 2; t++) {
            cp16(db + (uint32_t)(t * 2560 * 4), pA[t] + ko, true);
            cp16(db + (uint32_t)(t * 2560 * 4) + 16, pA[t] + ko + 4, true);
            cp16(db + (uint32_t)((2 + t) * 2560 * 4), pB[t] + ko, okB);
            cp16(db + (uint32_t)((2 + t) * 2560 * 4) + 16, pB[t] + ko + 4, okB);
        }
        asm volatile("cp.async.commit_group;" ::: "memory");
    };

    issue(0, 0);
    int st = 0;
    for (int i = 0; i < nslab; i++) {
        if (i + 1 < nslab) {
            issue(st ^ 1, i + 1);
            asm volatile("cp.async.wait_group 1;" ::: "memory");
        } else {
            asm volatile("cp.async.wait_group 0;" ::: "memory");
        }
        __syncthreads();
        uint32_t so = (uint32_t)(st * UPS) * 4;
#pragma unroll
        for (int kk = 0; kk < 2; kk++) {
            uint32_t kb = so + kk * 32;
            uint32_t ahi[4][4], alo[4][4];
#pragma unroll
            for (int mt = 0; mt < 4; mt++) {
                ldsm4(ahi[mt], a_ad[mt] + kb);
                ldsm4(alo[mt], a_ad[mt] + kb + 2560 * 4);
            }
            uint32_t bhi[4][2], blo[4][2];
#pragma unroll
            for (int p = 0; p < 2; p++) {
                uint32_t t4[4];
                ldsm4(t4, b_ad[p] + kb + 2 * 2560 * 4);
                bhi[p * 2][0] = t4[0]; bhi[p * 2][1] = t4[1];
                bhi[p * 2 + 1][0] = t4[2]; bhi[p * 2 + 1][1] = t4[3];
                ldsm4(t4, b_ad[p] + kb + 3 * 2560 * 4);
                blo[p * 2][0] = t4[0]; blo[p * 2][1] = t4[1];
                blo[p * 2 + 1][0] = t4[2]; blo[p * 2 + 1][1] = t4[3];
            }
#pragma unroll
            for (int mt = 0; mt < 4; mt++)
#pragma unroll
                for (int nt = 0; nt < 4; nt++) {
                    mma_bf16(acc[mt][nt], ahi[mt], bhi[nt]);
                    mma_bf16(acc[mt][nt], ahi[mt], blo[nt]);
                    mma_bf16(acc[mt][nt], alo[mt], bhi[nt]);
                }
        }
        __syncthreads();
        st ^= 1;
    }

#pragma unroll
    for (int mt = 0; mt < 4; mt++) {
        int row = bm + wm * 64 + mt * 16 + g;
#pragma unroll
        for (int nt = 0; nt < 4; nt++) {
            int col = bn + wn * 32 + nt * 8 + tg * 2;
            if (col < N) {
                float* a = acc[mt][nt];
                size_t i0 = (size_t)row * N + col;
                size_t i1 = (size_t)(row + 8) * N + col;
                if (addRes) {
                    a[0] += resid[i0]; a[1] += resid[i0 + 1];
                    a[2] += resid[i1]; a[3] += resid[i1 + 1];
                }
                C[i0] = a[0]; C[i0 + 1] = a[1];
                C[i1] = a[2]; C[i1 + 1] = a[3];
            }
        }
    }
}

// ------ K3+K4: conv+silu (4 rows per thread, tap reuse) AND dt softplus ------
#define NCONV ((ROWS / 4) * CONVD)
__global__ void conv_dt_kernel(const float* __restrict__ conv_w,
                               const float* __restrict__ conv_b,
                               const float* __restrict__ dt_bias) {
    int idx = blockIdx.x * blockDim.x + threadIdx.x;
    if (idx < NCONV) {
        int c = idx % CONVD;
        int r4 = idx / CONVD;
        int R = r4 * 4;
        int l0 = R & (L_ - 1);
        const float* w = conv_w + c * 4;
        float w0 = w[0], w1 = w[1], w2 = w[2], w3 = w[3];
        float v[7];
#pragma unroll
        for (int j = 0; j < 7; j++) {
            int lj = l0 - 3 + j;
            v[j] = (lj >= 0) ? g_zx[(size_t)(R - 3 + j) * DPROJ + DI + c] : 0.f;
        }
        float bias = conv_b[c];
#pragma unroll
        for (int i = 0; i < 4; i++) {
            float acc = bias + w0 * v[i] + w1 * v[i + 1] + w2 * v[i + 2] + w3 * v[i + 3];
            g_xbc[(size_t)(R + i) * CONVD + c] = silu_f(acc);
        }
    } else {
        int j = idx - NCONV;  // < ROWS*NH
        int h = j & (NH - 1);
        int row = j >> 5;
        float v = g_zx[(size_t)row * DPROJ + (DI + CONVD) + h] + dt_bias[h];
        float sp = (v > 20.f) ? v : log1pf(__expf(v));
        g_dt[row * NH + h] = sp;
    }
}

// ----- K5b: xdT precompute WITH fused acs scan -----
#define XDT_SMEM (256 * 68 * 4)
__global__ __launch_bounds__(256) void xdt_kernel(const float* __restrict__ A_log) {
    extern __shared__ float sx[];
    __shared__ float sdt[CH], sdec[CH], sacs[CH];
    int bid = blockIdx.x;
    int b = bid >> 8, c = (bid >> 5) & 7, h = bid & 31;
    int tid = threadIdx.x;
    int rowbase = b * L_ + c * CH;
    int base = ((b * NH + h) * NCH + c) * CH;
    float A = -__expf(A_log[h]);
    {
        int l = tid, row = rowbase + l;
        const float* xr = &g_xbc[(size_t)row * CONVD + h * HD];
#pragma unroll
        for (int p4 = 0; p4 < 16; p4++) {
            float4 v = ((const float4*)xr)[p4];
            *(float4*)&sx[l * 68 + p4 * 4] = v;
        }
        float dtv = g_dt[row * NH + h];
        sdt[l] = dtv;
        sacs[l] = dtv * A;
    }
    __syncthreads();
#pragma unroll
    for (int off = 1; off < CH; off <<= 1) {
        float v = (tid >= off) ? sacs[tid - off] : 0.f;
        __syncthreads();
        sacs[tid] += v;
        __syncthreads();
    }
    float acs255 = sacs[CH - 1];
    sdec[tid] = __expf(acs255 - sacs[tid]);
    g_acs[base + tid] = sacs[tid];
    __syncthreads();

    int warp = tid >> 5, lane = tid & 31;
    size_t ob = (size_t)bid * HD * (CH / 2);
#pragma unroll
    for (int pp = 0; pp < 8; pp++) {
        int p = warp * 8 + pp;
        uint32_t oh[4], ol[4], osh[4], osl[4];
#pragma unroll
        for (int k = 0; k < 4; k++) {
            int cu = lane * 4 + k;
            int l = cu * 2;
            float va = sx[l * 68 + p] * sdt[l];
            float vb = sx[(l + 1) * 68 + p] * sdt[l + 1];
            oh[k] = pack_bf16(va, vb);
            ol[k] = pack_bf16(va - bf16r(va), vb - bf16r(vb));
            float wa = va * sdec[l], wb = vb * sdec[l + 1];
            osh[k] = pack_bf16(wa, wb);
            osl[k] = pack_bf16(wa - bf16r(wa), wb - bf16r(wb));
        }
        size_t o = ob + (size_t)p * (CH / 2) + lane * 4;
        *(uint4*)&g_xdp_h[o] = *(uint4*)oh;
        *(uint4*)&g_xdp_l[o] = *(uint4*)ol;
        *(uint4*)&g_xds_h[o] = *(uint4*)osh;
        *(uint4*)&g_xds_l[o] = *(uint4*)osl;
    }
}

// ----- K5c: Bm^T precompute -----
#define BMT_SMEM (128 * 132 * 4)
__global__ __launch_bounds__(256) void bmt_kernel() {
    extern __shared__ float sx[];
    int z = blockIdx.y, pass = blockIdx.x;
    int b = z >> 3, c = z & 7;
    int tid = threadIdx.x;
    int rowbase = b * L_ + c * CH + pass * 128;
    {
        int l = tid & 127, half = tid >> 7;
        const float* br = &g_xbc[(size_t)(rowbase + l) * CONVD + DI + half * 64];
#pragma unroll
        for (int k4 = 0; k4 < 16; k4++) {
            float4 v = ((const float4*)br)[k4];
            *(float4*)&sx[l * 132 + half * 64 + k4 * 4] = v;
        }
    }
    __syncthreads();
    int warp = tid >> 5, lane = tid & 31;
#pragma unroll
    for (int nn = 0; nn < 16; nn++) {
        int n = warp * 16 + nn;
        uint32_t h2[2], l2[2];
#pragma unroll
        for (int k = 0; k < 2; k++) {
            int cu = lane * 2 + k;
            float va = sx[(2 * cu) * 132 + n];
            float vb = sx[(2 * cu + 1) * 132 + n];
            h2[k] = pack_bf16(va, vb);
            l2[k] = pack_bf16(va - bf16r(va), vb - bf16r(vb));
        }
        size_t o = ((size_t)z * DS + n) * (CH / 2) + pass * 64 + lane * 2;
        *(uint2*)&g_bmt_h[o] = *(uint2*)h2;
        *(uint2*)&g_bmt_l[o] = *(uint2*)l2;
    }
}

// ----- K5d: row-major Bm/Cm bf16 hi/lo (for CB gemm) -----
__global__ void cvt_bc_kernel() {
    int row = blockIdx.x;
    int tid = threadIdx.x;  // 128
    int which = tid >> 6, n2 = tid & 63;
    float2 v = *(const float2*)&g_xbc[(size_t)row * CONVD + DI + which * DS + n2 * 2];
    uint32_t hh = pack_bf16(v.x, v.y);
    uint32_t ll = pack_bf16(v.x - bf16r(v.x), v.y - bf16r(v.y));
    size_t o = (size_t)row * 64 + n2;
    if (which == 0) { g_bm2_h[o] = hh; g_bm2_l[o] = ll; }
    else            { g_cm2_h[o] = hh; g_cm2_l[o] = ll; }
}

// ------ K6 (tensorized): states[n,p] ------
#define SSW 20
#define S_AH 0
#define S_AL (128 * SSW)
#define S_BH (2 * 128 * SSW)
#define S_BL (2 * 128 * SSW + 64 * SSW)
__global__ __launch_bounds__(256) void states_tc_kernel() {
    __shared__ __align__(16) uint32_t S[2 * 128 * SSW + 2 * 64 * SSW];
    uint32_t sb = smem_u32(S);
    int bid = blockIdx.x;
    int b = bid >> 8, c = (bid >> 5) & 7;
    int z = b * NCH + c;
    int tid = threadIdx.x, warp = tid >> 5, lane = tid & 31;
    int wm = warp & 3, wn = warp >> 2;
    int g = lane >> 2, tg = lane & 3;
    int mat = lane >> 3, mrow = lane & 7;

    uint32_t a_adh[2], a_adl[2], b_adh[2], b_adl[2];
#pragma unroll
    for (int mt = 0; mt < 2; mt++) {
        int r = wm * 32 + mt * 16 + (mat & 1) * 8 + mrow;
        uint32_t off = (uint32_t)(r * SSW + (mat >> 1) * 4) * 4;
        a_adh[mt] = sb + S_AH * 4 + off;
        a_adl[mt] = sb + S_AL * 4 + off;
    }
#pragma unroll
    for (int p = 0; p < 2; p++) {
        int n = wn * 32 + p * 16 + (mat >> 1) * 8 + mrow;
        uint32_t off = (uint32_t)(n * SSW + (mat & 1) * 4) * 4;
        b_adh[p] = sb + S_BH * 4 + off;
        b_adl[p] = sb + S_BL * 4 + off;
    }

    float acc[2][4][4];
#pragma unroll
    for (int mt = 0; mt < 2; mt++)
#pragma unroll
        for (int nt = 0; nt < 4; nt++)
#pragma unroll
            for (int q = 0; q < 4; q++) acc[mt][nt][q] = 0.f;

    for (int j = 0; j < 8; j++) {
        __syncthreads();
        {
            int n = tid >> 1, half = tid & 1;
            size_t src = ((size_t)z * DS + n) * (CH / 2) + j * 16 + half * 8;
            uint32_t d = sb + (uint32_t)(S_AH + n * SSW + half * 8) * 4;
            cp16(d, &g_bmt_h[src], true);
            cp16(d + 16, &g_bmt_h[src + 4], true);
            uint32_t d2 = sb + (uint32_t)(S_AL + n * SSW + half * 8) * 4;
            cp16(d2, &g_bmt_l[src], true);
            cp16(d2 + 16, &g_bmt_l[src + 4], true);
        }
        {
            int p = tid >> 2, q = tid & 3;
            size_t src = ((size_t)bid * HD + p) * (CH / 2) + j * 16 + q * 4;
            cp16(sb + (uint32_t)(S_BH + p * SSW + q * 4) * 4, &g_xds_h[src], true);
            cp16(sb + (uint32_t)(S_BL + p * SSW + q * 4) * 4, &g_xds_l[src], true);
        }
        asm volatile("cp.async.commit_group;" ::: "memory");
        asm volatile("cp.async.wait_group 0;" ::: "memory");
        __syncthreads();
#pragma unroll
        for (int kk = 0; kk < 2; kk++) {
            uint32_t kb = kk * 32;
            uint32_t ahi[2][4], alo[2][4];
#pragma unroll
            for (int mt = 0; mt < 2; mt++) {
                ldsm4(ahi[mt], a_adh[mt] + kb);
                ldsm4(alo[mt], a_adl[mt] + kb);
            }
            uint32_t bhi[4][2], blo[4][2];
#pragma unroll
            for (int p = 0; p < 2; p++) {
                uint32_t t4[4];
                ldsm4(t4, b_adh[p] + kb);
                bhi[p * 2][0] = t4[0]; bhi[p * 2][1] = t4[1];
                bhi[p * 2 + 1][0] = t4[2]; bhi[p * 2 + 1][1] = t4[3];
                ldsm4(t4, b_adl[p] + kb);
                blo[p * 2][0] = t4[0]; blo[p * 2][1] = t4[1];
                blo[p * 2 + 1][0] = t4[2]; blo[p * 2 + 1][1] = t4[3];
            }
#pragma unroll
            for (int mt = 0; mt < 2; mt++)
#pragma unroll
                for (int nt = 0; nt < 4; nt++) {
                    mma_bf16(acc[mt][nt], ahi[mt], bhi[nt]);
                    mma_bf16(acc[mt][nt], ahi[mt], blo[nt]);
                    mma_bf16(acc[mt][nt], alo[mt], bhi[nt]);
                }
        }
    }

    size_t out = (size_t)bid * HD * DS;
#pragma unroll
    for (int mt = 0; mt < 2; mt++) {
#pragma unroll
        for (int nt = 0; nt < 4; nt++) {
            float* a = acc[mt][nt];
#pragma unroll
            for (int q = 0; q < 4; q++) {
                int n = wm * 32 + mt * 16 + g + (q >> 1) * 8;
                int p = wn * 32 + nt * 8 + tg * 2 + (q & 1);
                g_states[out + (size_t)p * DS + n] = a[q];
            }
        }
    }
}

// ---------------- K7: chunk recurrence ----------
__global__ void recur_kernel() {
    int idx = blockIdx.x * blockDim.x + threadIdx.x;
    int n = idx & 127;
    int p = (idx >> 7) & 63;
    int h = (idx >> 13) & 31;
    int b = idx >> 18;
    float run = 0.f;
#pragma unroll
    for (int c = 0; c < NCH; c++) {
        size_t sidx = ((size_t)((b * NCH + c) * NH + h) * HD + p) * DS + n;
        g_init[sidx] = run;
        float cs = g_acs[((b * NH + h) * NCH + c) * CH + CH - 1];
        run = run * __expf(cs) + g_states[sidx];
    }
}

// ------ K8 (tensorized): CB[l,s] = Cm[l]·Bm[s], 128x128x128 tiles ------
#define CBW 20
#define C_AH 0
#define C_AL (128 * CBW)
#define C_BH (2 * 128 * CBW)
#define C_BL (3 * 128 * CBW)
__global__ __launch_bounds__(256) void cb_tc_kernel() {
    __shared__ __align__(16) uint32_t S[4 * 128 * CBW];
    uint32_t sb = smem_u32(S);
    int z = blockIdx.z;
    int b = z >> 3, c = z & 7;
    int l0 = blockIdx.y * 128, s0 = blockIdx.x * 128;
    int rowbase = b * L_ + c * CH;
    int tid = threadIdx.x, warp = tid >> 5, lane = tid & 31;
    int wm = warp & 1, wn = warp >> 1;
    int g = lane >> 2, tg = lane & 3;
    int mat = lane >> 3, mrow = lane & 7;

    uint32_t a_adh[4], a_adl[4], b_adh[2], b_adl[2];
#pragma unroll
    for (int mt = 0; mt < 4; mt++) {
        int r = wm * 64 + mt * 16 + (mat & 1) * 8 + mrow;
        uint32_t off = (uint32_t)(r * CBW + (mat >> 1) * 4) * 4;
        a_adh[mt] = sb + C_AH * 4 + off;
        a_adl[mt] = sb + C_AL * 4 + off;
    }
#pragma unroll
    for (int p = 0; p < 2; p++) {
        int n = wn * 32 + p * 16 + (mat >> 1) * 8 + mrow;
        uint32_t off = (uint32_t)(n * CBW + (mat & 1) * 4) * 4;
        b_adh[p] = sb + C_BH * 4 + off;
        b_adl[p] = sb + C_BL * 4 + off;
    }

    float acc[4][4][4];
#pragma unroll
    for (int mt = 0; mt < 4; mt++)
#pragma unroll
        for (int nt = 0; nt < 4; nt++)
#pragma unroll
            for (int q = 0; q < 4; q++) acc[mt][nt][q] = 0.f;

    for (int ks = 0; ks < 4; ks++) {
        __syncthreads();
        {
            int r = tid >> 1, half = tid & 1;
            size_t asrc = (size_t)(rowbase + l0 + r) * 64 + ks * 16 + half * 8;
            uint32_t d = sb + (uint32_t)(C_AH + r * CBW + half * 8) * 4;
            cp16(d, &g_cm2_h[asrc], true);
            cp16(d + 16, &g_cm2_h[asrc + 4], true);
            uint32_t d2 = sb + (uint32_t)(C_AL + r * CBW + half * 8) * 4;
            cp16(d2, &g_cm2_l[asrc], true);
            cp16(d2 + 16, &g_cm2_l[asrc + 4], true);
            size_t bsrc = (size_t)(rowbase + s0 + r) * 64 + ks * 16 + half * 8;
            uint32_t d3 = sb + (uint32_t)(C_BH + r * CBW + half * 8) * 4;
            cp16(d3, &g_bm2_h[bsrc], true);
            cp16(d3 + 16, &g_bm2_h[bsrc + 4], true);
            uint32_t d4 = sb + (uint32_t)(C_BL + r * CBW + half * 8) * 4;
            cp16(d4, &g_bm2_l[bsrc], true);
            cp16(d4 + 16, &g_bm2_l[bsrc + 4], true);
        }
        asm volatile("cp.async.commit_group;" ::: "memory");
        asm volatile("cp.async.wait_group 0;" ::: "memory");
        __syncthreads();
#pragma unroll
        for (int kk = 0; kk < 2; kk++) {
            uint32_t kb = kk * 32;
            uint32_t ahi[4][4], alo[4][4];
#pragma unroll
            for (int mt = 0; mt < 4; mt++) {
                ldsm4(ahi[mt], a_adh[mt] + kb);
                ldsm4(alo[mt], a_adl[mt] + kb);
            }
            uint32_t bhi[4][2], blo[4][2];
#pragma unroll
            for (int p = 0; p < 2; p++) {
                uint32_t t4[4];
                ldsm4(t4, b_adh[p] + kb);
                bhi[p * 2][0] = t4[0]; bhi[p * 2][1] = t4[1];
                bhi[p * 2 + 1][0] = t4[2]; bhi[p * 2 + 1][1] = t4[3];
                ldsm4(t4, b_adl[p] + kb);
                blo[p * 2][0] = t4[0]; blo[p * 2][1] = t4[1];
                blo[p * 2 + 1][0] = t4[2]; blo[p * 2 + 1][1] = t4[3];
            }
#pragma unroll
            for (int mt = 0; mt < 4; mt++)
#pragma unroll
                for (int nt = 0; nt < 4; nt++) {
                    mma_bf16(acc[mt][nt], ahi[mt], bhi[nt]);
                    mma_bf16(acc[mt][nt], ahi[mt], blo[nt]);
                    mma_bf16(acc[mt][nt], alo[mt], bhi[nt]);
                }
        }
    }

#pragma unroll
    for (int mt = 0; mt < 4; mt++) {
        int row = l0 + wm * 64 + mt * 16 + g;
#pragma unroll
        for (int nt = 0; nt < 4; nt++) {
            int col = s0 + wn * 32 + nt * 8 + tg * 2;
            float* a = acc[mt][nt];
            size_t i0 = ((size_t)z * CH + row) * CH + col;
            size_t i1 = ((size_t)z * CH + row + 8) * CH + col;
            g_cb[i0] = a[0]; g_cb[i0 + 1] = a[1];
            g_cb[i1] = a[2]; g_cb[i1 + 1] = a[3];
        }
    }
}

// ------ K9: Y[256,64]; interleaved causal tile mapping ------
#define YW 20
#define YA_H 0
#define YA_L (256 * YW)
#define YB_H (2 * 256 * YW)
#define YB_L (2 * 256 * YW + 64 * YW)
#define YACS (2 * 256 * YW + 2 * 64 * YW)
#define YCF  (YACS + 256)
#define YRF  (YCF + 256)
#define YSMEM ((YRF + 8 * 256) * 4)
__global__ __launch_bounds__(256) void y_tc_kernel(const float* __restrict__ Dvec) {
    extern __shared__ __align__(16) uint32_t S[];
    uint32_t* Ah = S + YA_H;
    uint32_t* Al = S + YA_L;
    uint32_t* Bh = S + YB_H;
    uint32_t* Bl = S + YB_L;
    float* acs_s = (float*)(S + YACS);
    float* cf_s = (float*)(S + YCF);
    float* rfv = (float*)(S + YRF);
    uint32_t sb = smem_u32(S);

    int bid = blockIdx.x;
    int b = bid >> 8, c = (bid >> 5) & 7, h = bid & 31;
    int z = b * NCH + c;
    int tid = threadIdx.x, warp = tid >> 5, lane = tid & 31;
    int wm = warp & 3, wn = warp >> 2;
    int g = lane >> 2, tg = lane & 3;
    int base = ((b * NH + h) * NCH + c) * CH;
    acs_s[tid] = g_acs[base + tid];
    int rowbase = b * L_ + c * CH;
    size_t initbase = (size_t)bid * HD * DS;
    int lr = tid >> 3, cg = tid & 7;

    int mat = lane >> 3, mrow = lane & 7;
    uint32_t a_adh[4], a_adl[4], b_adh[2], b_adl[2];
#pragma unroll
    for (int mt = 0; mt < 4; mt++) {
        int r = wm * 16 + mt * 64 + (mat & 1) * 8 + mrow;
        uint32_t off = (uint32_t)(r * YW + (mat >> 1) * 4) * 4;
        a_adh[mt] = sb + YA_H * 4 + off;
        a_adl[mt] = sb + YA_L * 4 + off;
    }
#pragma unroll
    for (int p = 0; p < 2; p++) {
        int n = wn * 32 + p * 16 + (mat >> 1) * 8 + mrow;
        uint32_t off = (uint32_t)(n * YW + (mat & 1) * 4) * 4;
        b_adh[p] = sb + YB_H * 4 + off;
        b_adl[p] = sb + YB_L * 4 + off;
    }

    float acc[4][4][4];
#pragma unroll
    for (int mt = 0; mt < 4; mt++)
#pragma unroll
        for (int nt = 0; nt < 4; nt++)
#pragma unroll
            for (int q = 0; q < 4; q++) acc[mt][nt][q] = 0.f;

    auto do_mma = [&](int s0) {
        bool act[4];
#pragma unroll
        for (int mt = 0; mt < 4; mt++) act[mt] = (wm * 16 + mt * 64 + 15 >= s0);
        if (!act[3]) return;
#pragma unroll
        for (int kk = 0; kk < 2; kk++) {
            uint32_t kb = kk * 32;
            uint32_t ahi[4][4], alo[4][4];
#pragma unroll
            for (int mt = 0; mt < 4; mt++)
                if (act[mt]) {
                    ldsm4(ahi[mt], a_adh[mt] + kb);
                    ldsm4(alo[mt], a_adl[mt] + kb);
                }
            uint32_t bhi[4][2], blo[4][2];
#pragma unroll
            for (int p = 0; p < 2; p++) {
                uint32_t t4[4];
                ldsm4(t4, b_adh[p] + kb);
                bhi[p * 2][0] = t4[0]; bhi[p * 2][1] = t4[1];
                bhi[p * 2 + 1][0] = t4[2]; bhi[p * 2 + 1][1] = t4[3];
                ldsm4(t4, b_adl[p] + kb);
                blo[p * 2][0] = t4[0]; blo[p * 2][1] = t4[1];
                blo[p * 2 + 1][0] = t4[2]; blo[p * 2 + 1][1] = t4[3];
            }
#pragma unroll
            for (int mt = 0; mt < 4; mt++)
                if (act[mt])
#pragma unroll
                    for (int nt = 0; nt < 4; nt++) {
                        mma_bf16(acc[mt][nt], ahi[mt], bhi[nt]);
                        mma_bf16(acc[mt][nt], ahi[mt], blo[nt]);
                        mma_bf16(acc[mt][nt], alo[mt], bhi[nt]);
                    }
        }
    };

    // ---------------- Phase 1: Cm @ init^T ----------
    for (int ks = 0; ks < 4; ks++) {
        __syncthreads();
        {
#pragma unroll
            for (int it = 0; it < 8; it++) {
                int l = it * 32 + lr;
                float4 v = *(const float4*)&g_xbc[(size_t)(rowbase + l) * CONVD +
                                                  DI + DS + ks * 32 + cg * 4];
                uint32_t* dah = &Ah[l * YW + cg * 2];
                uint32_t* dal = &Al[l * YW + cg * 2];
                dah[0] = pack_bf16(v.x, v.y);
                dah[1] = pack_bf16(v.z, v.w);
                dal[0] = pack_bf16(v.x - bf16r(v.x), v.y - bf16r(v.y));
                dal[1] = pack_bf16(v.z - bf16r(v.z), v.w - bf16r(v.w));
            }
        }
        {
            int p = tid >> 2, q0 = tid & 3;
            const float* ir = &g_init[initbase + (size_t)p * DS + ks * 32 + q0 * 8];
            float4 v0 = ((const float4*)ir)[0];
            float4 v1 = ((const float4*)ir)[1];
            uint32_t* dbh = &Bh[p * YW + q0 * 4];
            uint32_t* dbl = &Bl[p * YW + q0 * 4];
            dbh[0] = pack_bf16(v0.x, v0.y);
            dbh[1] = pack_bf16(v0.z, v0.w);
            dbh[2] = pack_bf16(v1.x, v1.y);
            dbh[3] = pack_bf16(v1.z, v1.w);
            dbl[0] = pack_bf16(v0.x - bf16r(v0.x), v0.y - bf16r(v0.y));
            dbl[1] = pack_bf16(v0.z - bf16r(v0.z), v0.w - bf16r(v0.w));
            dbl[2] = pack_bf16(v1.x - bf16r(v1.x), v1.y - bf16r(v1.y));
            dbl[3] = pack_bf16(v1.z - bf16r(v1.z), v1.w - bf16r(v1.w));
        }
        __syncthreads();
        do_mma(0);
    }

#pragma unroll
    for (int mt = 0; mt < 4; mt++) {
        int r0 = wm * 16 + mt * 64 + g;
        float e0 = __expf(acs_s[r0]);
        float e1 = __expf(acs_s[r0 + 8]);
#pragma unroll
        for (int nt = 0; nt < 4; nt++) {
            acc[mt][nt][0] *= e0; acc[mt][nt][1] *= e0;
            acc[mt][nt][2] *= e1; acc[mt][nt][3] *= e1;
        }
    }

    cf_s[tid] = __expf(acs_s[tid | 31] - acs_s[tid]);
#pragma unroll
    for (int ss = 0; ss < 8; ss++) {
        float v = 0.f;
        if (tid >= ss * 32 + 32) v = __expf(acs_s[tid] - acs_s[ss * 32 + 31]);
        rfv[ss * 256 + tid] = v;
    }

    // ---------------- Phase 2: (CB ∘ L) @ xd^T ----------
    for (int ss = 0; ss < 8; ss++) {
        int s0 = ss * 32;
        __syncthreads();
        {
            int p = tid >> 2, q = tid & 3;
            size_t src = ((size_t)bid * HD + p) * (CH / 2) + ss * 16 + q * 4;
            cp16(sb + (uint32_t)(YB_H + p * YW + q * 4) * 4, &g_xdp_h[src], true);
            cp16(sb + (uint32_t)(YB_L + p * YW + q * 4) * 4, &g_xdp_l[src], true);
            asm volatile("cp.async.commit_group;" ::: "memory");
        }
        {
            const float* rfs = &rfv[ss * 256];
#pragma unroll
            for (int it = 0; it < 8; it++) {
                int l = it * 32 + lr;
                uint32_t* dah = &Ah[l * YW + cg * 2];
                uint32_t* dal = &Al[l * YW + cg * 2];
                if (l < s0) {
                    dah[0] = 0u; dah[1] = 0u; dal[0] = 0u; dal[1] = 0u;
                    continue;
                }
                float4 cb4 = *(const float4*)&g_cb[((size_t)z * CH + l) * CH + s0 + cg * 4];
                float va, vb, vc, vd;
                int s = s0 + cg * 4;
                if (l < s0 + 32) {
                    float al = acs_s[l];
                    va = (s <= l) ? cb4.x * __expf(al - acs_s[s]) : 0.f;
                    vb = (s + 1 <= l) ? cb4.y * __expf(al - acs_s[s + 1]) : 0.f;
                    vc = (s + 2 <= l) ? cb4.z * __expf(al - acs_s[s + 2]) : 0.f;
                    vd = (s + 3 <= l) ? cb4.w * __expf(al - acs_s[s + 3]) : 0.f;
                } else {
                    float rf = rfs[l];
                    va = cb4.x * (rf * cf_s[s]);
                    vb = cb4.y * (rf * cf_s[s + 1]);
                    vc = cb4.z * (rf * cf_s[s + 2]);
                    vd = cb4.w * (rf * cf_s[s + 3]);
                }
                dah[0] = pack_bf16(va, vb);
                dah[1] = pack_bf16(vc, vd);
                dal[0] = pack_bf16(va - bf16r(va), vb - bf16r(vb));
                dal[1] = pack_bf16(vc - bf16r(vc), vd - bf16r(vd));
            }
        }
        asm volatile("cp.async.wait_group 0;" ::: "memory");
        __syncthreads();
        do_mma(s0);
    }

    // epilogue: + D*xh, write y (fp32)
    float Dh = Dvec[h];
#pragma unroll
    for (int mt = 0; mt < 4; mt++) {
        int r = wm * 16 + mt * 64 + g;
#pragma unroll
        for (int nt = 0; nt < 4; nt++) {
            int p = wn * 32 + nt * 8 + tg * 2;
            float* a = acc[mt][nt];
#pragma unroll
            for (int q = 0; q < 4; q++) {
                int row = rowbase + r + (q >> 1) * 8;
                int pp = p + (q & 1);
                float xh = g_xbc[(size_t)row * CONVD + h * HD + pp];
                g_y[(size_t)row * DI + h * HD + pp] = a[q] + Dh * xh;
            }
        }
    }
}

// -------- K10: gated rmsnorm -> bf16 hi/lo --------
__global__ void gated_norm_kernel(const float* __restrict__ gw) {
    int row = blockIdx.x, tid = threadIdx.x;
    int d0 = tid * 8;
    const float* zr = &g_zx[(size_t)row * DPROJ + d0];
    const float* yr = &g_y[(size_t)row * DI + d0];
    float v[8];
    float local = 0.f;
#pragma unroll
    for (int q = 0; q < 2; q++) {
        float4 z4 = *(const float4*)(zr + q * 4);
        float4 y4 = *(const float4*)(yr + q * 4);
        float zz[4] = {z4.x, z4.y, z4.z, z4.w};
        float yy[4] = {y4.x, y4.y, y4.z, y4.w};
#pragma unroll
        for (int j = 0; j < 4; j++) {
            float t = yy[j] * silu_f(zz[j]);
            v[q * 4 + j] = t;
            local += t * t;
        }
    }
    float tot = blockReduceSum256(local);
    float r = rsqrtf(tot / (float)DI + 1e-5f);
    int o = row * (DI / 2) + tid * 4;
#pragma unroll
    for (int j = 0; j < 4; j++) {
        float a = v[2 * j] * r * gw[d0 + 2 * j];
        float b = v[2 * j + 1] * r * gw[d0 + 2 * j + 1];
        g_yh[o + j] = pack_bf16(a, b);
        g_yl[o + j] = pack_bf16(a - bf16r(a), b - bf16r(b));
    }
}

// ---------------- launch ----------------
extern "C" void kernel_launch(void* const* d_in, const int* in_sizes, int n_in,
                              void* d_out, int out_size) {
    const float* x         = (const float*)d_in[0];
    const float* norm_w    = (const float*)d_in[1];
    const float* in_proj_w = (const float*)d_in[2];
    const float* conv_w    = (const float*)d_in[3];
    const float* conv_b    = (const float*)d_in[4];
    const float* dt_bias   = (const float*)d_in[5];
    const float* A_log     = (const float*)d_in[6];
    const float* Dv        = (const float*)d_in[7];
    const float* gnorm_w   = (const float*)d_in[8];
    const float* out_proj_w= (const float*)d_in[9];
    float* out = (float*)d_out;

    float *pzx;
    uint32_t *puh, *pul, *pyh, *pyl, *pwih, *pwil, *pwoh, *pwol;
    cudaGetSymbolAddress((void**)&pzx, g_zx);
    cudaGetSymbolAddress((void**)&puh, g_uh);
    cudaGetSymbolAddress((void**)&pul, g_ul);
    cudaGetSymbolAddress((void**)&pyh, g_yh);
    cudaGetSymbolAddress((void**)&pyl, g_yl);
    cudaGetSymbolAddress((void**)&pwih, g_wih);
    cudaGetSymbolAddress((void**)&pwil, g_wil);
    cudaGetSymbolAddress((void**)&pwoh, g_woh);
    cudaGetSymbolAddress((void**)&pwol, g_wol);

    cudaFuncSetAttribute(mma_nt_pre, cudaFuncAttributeMaxDynamicSharedMemorySize, GSMEM);
    cudaFuncSetAttribute(y_tc_kernel, cudaFuncAttributeMaxDynamicSharedMemorySize, YSMEM);
    cudaFuncSetAttribute(xdt_kernel, cudaFuncAttributeMaxDynamicSharedMemorySize, XDT_SMEM);
    cudaFuncSetAttribute(bmt_kernel, cudaFuncAttributeMaxDynamicSharedMemorySize, BMT_SMEM);

    cvt_pairs_kernel<<<(DPROJ * DM / 2 + 255) / 256, 256>>>(in_proj_w, pwih, pwil,
                                                            DPROJ * DM / 2);
    cvt_pairs_kernel<<<(DM * DI / 2 + 255) / 256, 256>>>(out_proj_w, pwoh, pwol,
                                                         DM * DI / 2);

    rmsnorm_x_kernel<<<ROWS, 256>>>(x, norm_w);
    mma_nt_pre<<<dim3((DPROJ + 127) / 128, ROWS / 128), 256, GSMEM>>>(
        puh, pul, pwih, pwil, pzx, nullptr, ROWS, DPROJ, DM, 0);
    conv_dt_kernel<<<(NCONV + ROWS * NH) / 256, 256>>>(conv_w, conv_b, dt_bias);
    cvt_bc_kernel<<<ROWS, 128>>>();
    xdt_kernel<<<NBID, 256, XDT_SMEM>>>(A_log);
    bmt_kernel<<<dim3(2, B_ * NCH), 256, BMT_SMEM>>>();
    states_tc_kernel<<<NBID, 256>>>();
    recur_kernel<<<(B_ * NH * HD * DS) / 256, 256>>>();
    cb_tc_kernel<<<dim3(2, 2, B_ * NCH), 256>>>();
    y_tc_kernel<<<NBID, 256, YSMEM>>>(Dv);
    gated_norm_kernel<<<ROWS, 256>>>(gnorm_w);
    mma_nt_pre<<<dim3(DM / 128, ROWS / 128), 256, GSMEM>>>(
        pyh, pyl, pwoh, pwol, out, x, ROWS, DM, DI, 1);
}

// round 16
// speedup vs baseline: 1.0728x; 1.0092x over previous
#include <cuda_runtime.h>
#include <cuda_bf16.h>
#include <math.h>
#include <stdint.h>

// ---------------- problem constants ----------------
#define B_    2
#define L_    2048
#define DM    1024
#define DI    2048
#define NH    32
#define HD    64
#define DS    128
#define CONVD 2304
#define DPROJ 4384
#define NCH   8
#define CH    256
#define ROWS  4096
#define NBID  (B_ * NCH * NH)   // 512

// ---------------- scratch (device globals) ----------------
__device__ float g_zx[(size_t)ROWS * DPROJ];
__device__ float g_xbc[(size_t)ROWS * CONVD];
__device__ float g_dt[ROWS * NH];
__device__ float g_acs[B_ * NH * NCH * CH];
__device__ float g_states[(size_t)B_ * NCH * NH * HD * DS];
__device__ float g_init[(size_t)B_ * NCH * NH * HD * DS];
__device__ float g_cb[(size_t)B_ * NCH * CH * CH];
__device__ float g_y[(size_t)ROWS * DI];

// packed bf16x2 hi/lo operand arrays
__device__ uint32_t g_uh[ROWS * DM / 2];
__device__ uint32_t g_ul[ROWS * DM / 2];
__device__ uint32_t g_yh[(size_t)ROWS * DI / 2];
__device__ uint32_t g_yl[(size_t)ROWS * DI / 2];
__device__ uint32_t g_wih[(size_t)DPROJ * DM / 2];
__device__ uint32_t g_wil[(size_t)DPROJ * DM / 2];
__device__ uint32_t g_woh[(size_t)DM * DI / 2];
__device__ uint32_t g_wol[(size_t)DM * DI / 2];

// SSD precomputed operands (bf16x2 packed)
__device__ uint32_t g_xdp_h[(size_t)NBID * HD * (CH / 2)];
__device__ uint32_t g_xdp_l[(size_t)NBID * HD * (CH / 2)];
__device__ uint32_t g_xds_h[(size_t)NBID * HD * (CH / 2)];
__device__ uint32_t g_xds_l[(size_t)NBID * HD * (CH / 2)];
__device__ uint32_t g_bmt_h[(size_t)B_ * NCH * DS * (CH / 2)];
__device__ uint32_t g_bmt_l[(size_t)B_ * NCH * DS * (CH / 2)];
// row-major Bm/Cm bf16 hi/lo for CB gemm: [row][n/2]
__device__ uint32_t g_bm2_h[(size_t)ROWS * 64];
__device__ uint32_t g_bm2_l[(size_t)ROWS * 64];
__device__ uint32_t g_cm2_h[(size_t)ROWS * 64];
__device__ uint32_t g_cm2_l[(size_t)ROWS * 64];

// ---------------- helpers ----------------
__device__ __forceinline__ float blockReduceSum256(float v) {
    __shared__ float ws[8];
    __shared__ float tot;
    int lane = threadIdx.x & 31, wid = threadIdx.x >> 5;
#pragma unroll
    for (int o = 16; o; o >>= 1) v += __shfl_xor_sync(0xffffffffu, v, o);
    if (lane == 0) ws[wid] = v;
    __syncthreads();
    if (threadIdx.x == 0) {
        float s = 0.f;
#pragma unroll
        for (int i = 0; i < 8; i++) s += ws[i];
        tot = s;
    }
    __syncthreads();
    return tot;
}

__device__ __forceinline__ uint32_t pack_bf16(float a, float b) {
    __nv_bfloat162 h = __floats2bfloat162_rn(a, b);
    return *(uint32_t*)&h;
}

__device__ __forceinline__ float bf16r(float v) {
    return __bfloat162float(__float2bfloat16(v));
}

// silu via single-MUFU tanh.approx
__device__ __forceinline__ float silu_f(float x) {
    float t;
    asm("tanh.approx.f32 %0, %1;" : "=f"(t) : "f"(x * 0.5f));
    return 0.5f * x * (1.f + t);
}

__device__ __forceinline__ uint32_t smem_u32(const void* p) {
    uint32_t a;
    asm("{ .reg .u64 t; cvta.to.shared.u64 t, %1; cvt.u32.u64 %0, t; }"
        : "=r"(a) : "l"(p));
    return a;
}

__device__ __forceinline__ void mma_bf16(float* d, const uint32_t* a, const uint32_t* b) {
    asm volatile(
        "mma.sync.aligned.m16n8k16.row.col.f32.bf16.bf16.f32 "
        "{%0,%1,%2,%3}, {%4,%5,%6,%7}, {%8,%9}, {%0,%1,%2,%3};"
        : "+f"(d[0]), "+f"(d[1]), "+f"(d[2]), "+f"(d[3])
        : "r"(a[0]), "r"(a[1]), "r"(a[2]), "r"(a[3]), "r"(b[0]), "r"(b[1]));
}

__device__ __forceinline__ void ldsm4(uint32_t* r, uint32_t addr) {
    asm volatile("ldmatrix.sync.aligned.m8n8.x4.shared.b16 {%0,%1,%2,%3}, [%4];"
                 : "=r"(r[0]), "=r"(r[1]), "=r"(r[2]), "=r"(r[3]) : "r"(addr));
}

__device__ __forceinline__ void cp16(uint32_t dst, const void* src, bool ok) {
    if (ok)
        asm volatile("cp.async.cg.shared.global [%0], [%1], 16;"
                     :: "r"(dst), "l"(src) : "memory");
    else
        asm volatile("cp.async.cg.shared.global [%0], [%1], 16, 0;"
                     :: "r"(dst), "l"(src) : "memory");
}

// ---------------- K0: split fp32 pairs -> bf16 hi/lo packed ----------
__global__ void cvt_pairs_kernel(const float* __restrict__ W,
                                 uint32_t* __restrict__ Wh,
                                 uint32_t* __restrict__ Wl, int npairs) {
    int i = blockIdx.x * blockDim.x + threadIdx.x;
    if (i < npairs) {
        float2 v = ((const float2*)W)[i];
        Wh[i] = pack_bf16(v.x, v.y);
        Wl[i] = pack_bf16(v.x - bf16r(v.x), v.y - bf16r(v.y));
    }
}

// ---------------- K1: rmsnorm(x) -> bf16 hi/lo ----------------
__global__ void rmsnorm_x_kernel(const float* __restrict__ x,
                                 const float* __restrict__ w) {
    int row = blockIdx.x, tid = threadIdx.x;
    const float4 v = ((const float4*)(x + (size_t)row * DM))[tid];
    const float4 wv = ((const float4*)w)[tid];
    float local = v.x * v.x + v.y * v.y + v.z * v.z + v.w * v.w;
    float tot = blockReduceSum256(local);
    float r = rsqrtf(tot / (float)DM + 1e-5f);
    float u0 = v.x * r * wv.x, u1 = v.y * r * wv.y;
    float u2 = v.z * r * wv.z, u3 = v.w * r * wv.w;
    int o = row * (DM / 2) + tid * 2;
    g_uh[o] = pack_bf16(u0, u1);
    g_uh[o + 1] = pack_bf16(u2, u3);
    g_ul[o] = pack_bf16(u0 - bf16r(u0), u1 - bf16r(u1));
    g_ul[o + 1] = pack_bf16(u2 - bf16r(u2), u3 - bf16r(u3));
}

// ------- tensor-core NT GEMM, preconverted bf16 hi/lo, cp.async 2-stage -------
#define UPS   (4 * 128 * 20)
#define GSMEM (2 * UPS * 4)
__global__ __launch_bounds__(256) void mma_nt_pre(const uint32_t* __restrict__ Ahg,
                                                  const uint32_t* __restrict__ Alg,
                                                  const uint32_t* __restrict__ Bhg,
                                                  const uint32_t* __restrict__ Blg,
                                                  float* __restrict__ C,
                                                  const float* __restrict__ resid,
                                                  int M, int N, int K, int addRes) {
    extern __shared__ __align__(16) uint32_t S[];
    uint32_t sbase = smem_u32(S);
    int tid = threadIdx.x;
    int warp = tid >> 5, lane = tid & 31;
    int wm = warp & 1, wn = warp >> 1;
    int bm = blockIdx.y * 128, bn = blockIdx.x * 128;
    int g = lane >> 2, tg = lane & 3;
    int K2 = K >> 1;

    int lrow = tid >> 1, lhalf = tid & 1;
    const uint32_t* pA[2] = {Ahg + (size_t)(bm + lrow) * K2 + lhalf * 8,
                             Alg + (size_t)(bm + lrow) * K2 + lhalf * 8};
    bool okB = (bn + lrow) < N;
    int brow = okB ? (bn + lrow) : 0;
    const uint32_t* pB[2] = {Bhg + (size_t)brow * K2 + lhalf * 8,
                             Blg + (size_t)brow * K2 + lhalf * 8};
    uint32_t dto = (uint32_t)(lrow * 20 + lhalf * 8) * 4;

    int mat = lane >> 3, mrow = lane & 7;
    uint32_t a_ad[4], b_ad[2];
#pragma unroll
    for (int mt = 0; mt < 4; mt++) {
        int r = wm * 64 + mt * 16 + (mat & 1) * 8 + mrow;
        a_ad[mt] = sbase + (uint32_t)(r * 20 + (mat >> 1) * 4) * 4;
    }
#pragma unroll
    for (int p = 0; p < 2; p++) {
        int n = wn * 32 + p * 16 + (mat >> 1) * 8 + mrow;
        b_ad[p] = sbase + (uint32_t)(n * 20 + (mat & 1) * 4) * 4;
    }

    float acc[4][4][4];
#pragma unroll
    for (int mt = 0; mt < 4; mt++)
#pragma unroll
        for (int nt = 0; nt < 4; nt++)
#pragma unroll
            for (int q = 0; q < 4; q++) acc[mt][nt][q] = 0.f;

    int nslab = K >> 5;

    auto issue = [&](int st, int sl) {
        int ko = sl * 16;
        uint32_t db = sbase + (uint32_t)(st * UPS) * 4 + dto;
#pragma unroll
        for (int t = 0; t < 2; t++) {
            cp16(db + (uint32_t)(t * 2560 * 4), pA[t] + ko, true);
            cp16(db + (uint32_t)(t * 2560 * 4) + 16, pA[t] + ko + 4, true);
            cp16(db + (uint32_t)((2 + t) * 2560 * 4), pB[t] + ko, okB);
            cp16(db + (uint32_t)((2 + t) * 2560 * 4) + 16, pB[t] + ko + 4, okB);
        }
        asm volatile("cp.async.commit_group;" ::: "memory");
    };

    issue(0, 0);
    int st = 0;
    for (int i = 0; i < nslab; i++) {
        if (i + 1 < nslab) {
            issue(st ^ 1, i + 1);
            asm volatile("cp.async.wait_group 1;" ::: "memory");
        } else {
            asm volatile("cp.async.wait_group 0;" ::: "memory");
        }
        __syncthreads();
        uint32_t so = (uint32_t)(st * UPS) * 4;
#pragma unroll
        for (int kk = 0; kk < 2; kk++) {
            uint32_t kb = so + kk * 32;
            uint32_t ahi[4][4], alo[4][4];
#pragma unroll
            for (int mt = 0; mt < 4; mt++) {
                ldsm4(ahi[mt], a_ad[mt] + kb);
                ldsm4(alo[mt], a_ad[mt] + kb + 2560 * 4);
            }
            uint32_t bhi[4][2], blo[4][2];
#pragma unroll
            for (int p = 0; p < 2; p++) {
                uint32_t t4[4];
                ldsm4(t4, b_ad[p] + kb + 2 * 2560 * 4);
                bhi[p * 2][0] = t4[0]; bhi[p * 2][1] = t4[1];
                bhi[p * 2 + 1][0] = t4[2]; bhi[p * 2 + 1][1] = t4[3];
                ldsm4(t4, b_ad[p] + kb + 3 * 2560 * 4);
                blo[p * 2][0] = t4[0]; blo[p * 2][1] = t4[1];
                blo[p * 2 + 1][0] = t4[2]; blo[p * 2 + 1][1] = t4[3];
            }
#pragma unroll
            for (int mt = 0; mt < 4; mt++)
#pragma unroll
                for (int nt = 0; nt < 4; nt++) {
                    mma_bf16(acc[mt][nt], ahi[mt], bhi[nt]);
                    mma_bf16(acc[mt][nt], ahi[mt], blo[nt]);
                    mma_bf16(acc[mt][nt], alo[mt], bhi[nt]);
                }
        }
        __syncthreads();
        st ^= 1;
    }

#pragma unroll
    for (int mt = 0; mt < 4; mt++) {
        int row = bm + wm * 64 + mt * 16 + g;
#pragma unroll
        for (int nt = 0; nt < 4; nt++) {
            int col = bn + wn * 32 + nt * 8 + tg * 2;
            if (col < N) {
                float* a = acc[mt][nt];
                size_t i0 = (size_t)row * N + col;
                size_t i1 = (size_t)(row + 8) * N + col;
                if (addRes) {
                    a[0] += resid[i0]; a[1] += resid[i0 + 1];
                    a[2] += resid[i1]; a[3] += resid[i1 + 1];
                }
                C[i0] = a[0]; C[i0 + 1] = a[1];
                C[i1] = a[2]; C[i1 + 1] = a[3];
            }
        }
    }
}

// ------ K3 fused: conv+silu (x: 1ch x 4rows), BC (2ch x 4rows + bmt/bm2/cm2
//        packing), dt softplus — one kernel, three segments ------
#define NSEG1 ((ROWS / 4) * DI)       // x channels
#define NSEG2 ((ROWS / 4) * DS)       // BC channel-pairs (128 pairs per r4)
#define NSEG3 (ROWS * NH)             // dt
__global__ void conv_dt_kernel(const float* __restrict__ conv_w,
                               const float* __restrict__ conv_b,
                               const float* __restrict__ dt_bias) {
    int idx = blockIdx.x * blockDim.x + threadIdx.x;
    if (idx < NSEG1) {
        // ---- segment 1: x channels (conv channel c in [0, DI)) ----
        int c = idx % DI;
        int r4 = idx / DI;
        int R = r4 * 4;
        int l0 = R & (L_ - 1);
        const float* w = conv_w + c * 4;
        float w0 = w[0], w1 = w[1], w2 = w[2], w3 = w[3];
        float v[7];
#pragma unroll
        for (int j = 0; j < 7; j++) {
            int lj = l0 - 3 + j;
            v[j] = (lj >= 0) ? g_zx[(size_t)(R - 3 + j) * DPROJ + DI + c] : 0.f;
        }
        float bias = conv_b[c];
#pragma unroll
        for (int i = 0; i < 4; i++) {
            float acc = bias + w0 * v[i] + w1 * v[i + 1] + w2 * v[i + 2] + w3 * v[i + 3];
            g_xbc[(size_t)(R + i) * CONVD + c] = silu_f(acc);
        }
    } else if (idx < NSEG1 + NSEG2) {
        // ---- segment 2: Bm/Cm channels (pairs), writes xbc + bmt + bm2/cm2 ----
        int t = idx - NSEG1;
        int c2 = t & 127;            // channel-pair index 0..127
        int r4 = t >> 7;
        int R = r4 * 4;
        int l0 = R & (L_ - 1);
        int cc = DI + c2 * 2;        // conv channel base (even)
        const float* wp = conv_w + cc * 4;
        float wa[4], wb[4];
#pragma unroll
        for (int j = 0; j < 4; j++) { wa[j] = wp[j]; wb[j] = wp[4 + j]; }
        float2 v[7];
#pragma unroll
        for (int j = 0; j < 7; j++) {
            int lj = l0 - 3 + j;
            v[j] = (lj >= 0)
                ? *(const float2*)&g_zx[(size_t)(R - 3 + j) * DPROJ + DI + cc]
                : make_float2(0.f, 0.f);
        }
        float ba = conv_b[cc], bb = conv_b[cc + 1];
        float s[4][2];
#pragma unroll
        for (int i = 0; i < 4; i++) {
            float a0 = ba + wa[0] * v[i].x + wa[1] * v[i + 1].x + wa[2] * v[i + 2].x + wa[3] * v[i + 3].x;
            float a1 = bb + wb[0] * v[i].y + wb[1] * v[i + 1].y + wb[2] * v[i + 2].y + wb[3] * v[i + 3].y;
            s[i][0] = silu_f(a0);
            s[i][1] = silu_f(a1);
        }
        // xbc (fp32) for downstream consumers (xdt, y_tc Cm fill)
#pragma unroll
        for (int i = 0; i < 4; i++)
            *(float2*)&g_xbc[(size_t)(R + i) * CONVD + cc] = make_float2(s[i][0], s[i][1]);
        // row-major packed bm2/cm2: [row][pair]
        bool isB = (c2 < 64);
        int col = isB ? c2 : (c2 - 64);
        uint32_t* H2 = isB ? g_bm2_h : g_cm2_h;
        uint32_t* L2 = isB ? g_bm2_l : g_cm2_l;
#pragma unroll
        for (int i = 0; i < 4; i++) {
            float a = s[i][0], b = s[i][1];
            H2[(size_t)(R + i) * 64 + col] = pack_bf16(a, b);
            L2[(size_t)(R + i) * 64 + col] = pack_bf16(a - bf16r(a), b - bf16r(b));
        }
        // transposed bmt (Bm only): [z][n][l/2]
        if (isB) {
            int z = R >> 8;           // global row / CH
            int lp = (R & 255) >> 1;  // pair base
#pragma unroll
            for (int k = 0; k < 2; k++) {
                int n = c2 * 2 + k;
                size_t o = ((size_t)z * DS + n) * (CH / 2) + lp;
                float p0 = s[0][k], p1 = s[1][k], p2 = s[2][k], p3 = s[3][k];
                g_bmt_h[o] = pack_bf16(p0, p1);
                g_bmt_h[o + 1] = pack_bf16(p2, p3);
                g_bmt_l[o] = pack_bf16(p0 - bf16r(p0), p1 - bf16r(p1));
                g_bmt_l[o + 1] = pack_bf16(p2 - bf16r(p2), p3 - bf16r(p3));
            }
        }
    } else {
        // ---- segment 3: dt softplus ----
        int j = idx - NSEG1 - NSEG2;
        int h = j & (NH - 1);
        int row = j >> 5;
        float v = g_zx[(size_t)row * DPROJ + (DI + CONVD) + h] + dt_bias[h];
        float sp = (v > 20.f) ? v : log1pf(__expf(v));
        g_dt[row * NH + h] = sp;
    }
}

// ----- K5b: xdT precompute WITH fused acs scan -----
#define XDT_SMEM (256 * 68 * 4)
__global__ __launch_bounds__(256) void xdt_kernel(const float* __restrict__ A_log) {
    extern __shared__ float sx[];
    __shared__ float sdt[CH], sdec[CH], sacs[CH];
    int bid = blockIdx.x;
    int b = bid >> 8, c = (bid >> 5) & 7, h = bid & 31;
    int tid = threadIdx.x;
    int rowbase = b * L_ + c * CH;
    int base = ((b * NH + h) * NCH + c) * CH;
    float A = -__expf(A_log[h]);
    {
        int l = tid, row = rowbase + l;
        const float* xr = &g_xbc[(size_t)row * CONVD + h * HD];
#pragma unroll
        for (int p4 = 0; p4 < 16; p4++) {
            float4 v = ((const float4*)xr)[p4];
            *(float4*)&sx[l * 68 + p4 * 4] = v;
        }
        float dtv = g_dt[row * NH + h];
        sdt[l] = dtv;
        sacs[l] = dtv * A;
    }
    __syncthreads();
#pragma unroll
    for (int off = 1; off < CH; off <<= 1) {
        float v = (tid >= off) ? sacs[tid - off] : 0.f;
        __syncthreads();
        sacs[tid] += v;
        __syncthreads();
    }
    float acs255 = sacs[CH - 1];
    sdec[tid] = __expf(acs255 - sacs[tid]);
    g_acs[base + tid] = sacs[tid];
    __syncthreads();

    int warp = tid >> 5, lane = tid & 31;
    size_t ob = (size_t)bid * HD * (CH / 2);
#pragma unroll
    for (int pp = 0; pp < 8; pp++) {
        int p = warp * 8 + pp;
        uint32_t oh[4], ol[4], osh[4], osl[4];
#pragma unroll
        for (int k = 0; k < 4; k++) {
            int cu = lane * 4 + k;
            int l = cu * 2;
            float va = sx[l * 68 + p] * sdt[l];
            float vb = sx[(l + 1) * 68 + p] * sdt[l + 1];
            oh[k] = pack_bf16(va, vb);
            ol[k] = pack_bf16(va - bf16r(va), vb - bf16r(vb));
            float wa = va * sdec[l], wb = vb * sdec[l + 1];
            osh[k] = pack_bf16(wa, wb);
            osl[k] = pack_bf16(wa - bf16r(wa), wb - bf16r(wb));
        }
        size_t o = ob + (size_t)p * (CH / 2) + lane * 4;
        *(uint4*)&g_xdp_h[o] = *(uint4*)oh;
        *(uint4*)&g_xdp_l[o] = *(uint4*)ol;
        *(uint4*)&g_xds_h[o] = *(uint4*)osh;
        *(uint4*)&g_xds_l[o] = *(uint4*)osl;
    }
}

// ------ K6 (tensorized): states[n,p] ------
#define SSW 20
#define S_AH 0
#define S_AL (128 * SSW)
#define S_BH (2 * 128 * SSW)
#define S_BL (2 * 128 * SSW + 64 * SSW)
__global__ __launch_bounds__(256) void states_tc_kernel() {
    __shared__ __align__(16) uint32_t S[2 * 128 * SSW + 2 * 64 * SSW];
    uint32_t sb = smem_u32(S);
    int bid = blockIdx.x;
    int b = bid >> 8, c = (bid >> 5) & 7;
    int z = b * NCH + c;
    int tid = threadIdx.x, warp = tid >> 5, lane = tid & 31;
    int wm = warp & 3, wn = warp >> 2;
    int g = lane >> 2, tg = lane & 3;
    int mat = lane >> 3, mrow = lane & 7;

    uint32_t a_adh[2], a_adl[2], b_adh[2], b_adl[2];
#pragma unroll
    for (int mt = 0; mt < 2; mt++) {
        int r = wm * 32 + mt * 16 + (mat & 1) * 8 + mrow;
        uint32_t off = (uint32_t)(r * SSW + (mat >> 1) * 4) * 4;
        a_adh[mt] = sb + S_AH * 4 + off;
        a_adl[mt] = sb + S_AL * 4 + off;
    }
#pragma unroll
    for (int p = 0; p < 2; p++) {
        int n = wn * 32 + p * 16 + (mat >> 1) * 8 + mrow;
        uint32_t off = (uint32_t)(n * SSW + (mat & 1) * 4) * 4;
        b_adh[p] = sb + S_BH * 4 + off;
        b_adl[p] = sb + S_BL * 4 + off;
    }

    float acc[2][4][4];
#pragma unroll
    for (int mt = 0; mt < 2; mt++)
#pragma unroll
        for (int nt = 0; nt < 4; nt++)
#pragma unroll
            for (int q = 0; q < 4; q++) acc[mt][nt][q] = 0.f;

    for (int j = 0; j < 8; j++) {
        __syncthreads();
        {
            int n = tid >> 1, half = tid & 1;
            size_t src = ((size_t)z * DS + n) * (CH / 2) + j * 16 + half * 8;
            uint32_t d = sb + (uint32_t)(S_AH + n * SSW + half * 8) * 4;
            cp16(d, &g_bmt_h[src], true);
            cp16(d + 16, &g_bmt_h[src + 4], true);
            uint32_t d2 = sb + (uint32_t)(S_AL + n * SSW + half * 8) * 4;
            cp16(d2, &g_bmt_l[src], true);
            cp16(d2 + 16, &g_bmt_l[src + 4], true);
        }
        {
            int p = tid >> 2, q = tid & 3;
            size_t src = ((size_t)bid * HD + p) * (CH / 2) + j * 16 + q * 4;
            cp16(sb + (uint32_t)(S_BH + p * SSW + q * 4) * 4, &g_xds_h[src], true);
            cp16(sb + (uint32_t)(S_BL + p * SSW + q * 4) * 4, &g_xds_l[src], true);
        }
        asm volatile("cp.async.commit_group;" ::: "memory");
        asm volatile("cp.async.wait_group 0;" ::: "memory");
        __syncthreads();
#pragma unroll
        for (int kk = 0; kk < 2; kk++) {
            uint32_t kb = kk * 32;
            uint32_t ahi[2][4], alo[2][4];
#pragma unroll
            for (int mt = 0; mt < 2; mt++) {
                ldsm4(ahi[mt], a_adh[mt] + kb);
                ldsm4(alo[mt], a_adl[mt] + kb);
            }
            uint32_t bhi[4][2], blo[4][2];
#pragma unroll
            for (int p = 0; p < 2; p++) {
                uint32_t t4[4];
                ldsm4(t4, b_adh[p] + kb);
                bhi[p * 2][0] = t4[0]; bhi[p * 2][1] = t4[1];
                bhi[p * 2 + 1][0] = t4[2]; bhi[p * 2 + 1][1] = t4[3];
                ldsm4(t4, b_adl[p] + kb);
                blo[p * 2][0] = t4[0]; blo[p * 2][1] = t4[1];
                blo[p * 2 + 1][0] = t4[2]; blo[p * 2 + 1][1] = t4[3];
            }
#pragma unroll
            for (int mt = 0; mt < 2; mt++)
#pragma unroll
                for (int nt = 0; nt < 4; nt++) {
                    mma_bf16(acc[mt][nt], ahi[mt], bhi[nt]);
                    mma_bf16(acc[mt][nt], ahi[mt], blo[nt]);
                    mma_bf16(acc[mt][nt], alo[mt], bhi[nt]);
                }
        }
    }

    size_t out = (size_t)bid * HD * DS;
#pragma unroll
    for (int mt = 0; mt < 2; mt++) {
#pragma unroll
        for (int nt = 0; nt < 4; nt++) {
            float* a = acc[mt][nt];
#pragma unroll
            for (int q = 0; q < 4; q++) {
                int n = wm * 32 + mt * 16 + g + (q >> 1) * 8;
                int p = wn * 32 + nt * 8 + tg * 2 + (q & 1);
                g_states[out + (size_t)p * DS + n] = a[q];
            }
        }
    }
}

// ---------------- K7: chunk recurrence ----------
__global__ void recur_kernel() {
    int idx = blockIdx.x * blockDim.x + threadIdx.x;
    int n = idx & 127;
    int p = (idx >> 7) & 63;
    int h = (idx >> 13) & 31;
    int b = idx >> 18;
    float run = 0.f;
#pragma unroll
    for (int c = 0; c < NCH; c++) {
        size_t sidx = ((size_t)((b * NCH + c) * NH + h) * HD + p) * DS + n;
        g_init[sidx] = run;
        float cs = g_acs[((b * NH + h) * NCH + c) * CH + CH - 1];
        run = run * __expf(cs) + g_states[sidx];
    }
}

// ------ K8 (tensorized): CB[l,s] = Cm[l]·Bm[s], 128x128x128 tiles ------
#define CBW 20
#define C_AH 0
#define C_AL (128 * CBW)
#define C_BH (2 * 128 * CBW)
#define C_BL (3 * 128 * CBW)
__global__ __launch_bounds__(256) void cb_tc_kernel() {
    __shared__ __align__(16) uint32_t S[4 * 128 * CBW];
    uint32_t sb = smem_u32(S);
    int z = blockIdx.z;
    int b = z >> 3, c = z & 7;
    int l0 = blockIdx.y * 128, s0 = blockIdx.x * 128;
    int rowbase = b * L_ + c * CH;
    int tid = threadIdx.x, warp = tid >> 5, lane = tid & 31;
    int wm = warp & 1, wn = warp >> 1;
    int g = lane >> 2, tg = lane & 3;
    int mat = lane >> 3, mrow = lane & 7;

    uint32_t a_adh[4], a_adl[4], b_adh[2], b_adl[2];
#pragma unroll
    for (int mt = 0; mt < 4; mt++) {
        int r = wm * 64 + mt * 16 + (mat & 1) * 8 + mrow;
        uint32_t off = (uint32_t)(r * CBW + (mat >> 1) * 4) * 4;
        a_adh[mt] = sb + C_AH * 4 + off;
        a_adl[mt] = sb + C_AL * 4 + off;
    }
#pragma unroll
    for (int p = 0; p < 2; p++) {
        int n = wn * 32 + p * 16 + (mat >> 1) * 8 + mrow;
        uint32_t off = (uint32_t)(n * CBW + (mat & 1) * 4) * 4;
        b_adh[p] = sb + C_BH * 4 + off;
        b_adl[p] = sb + C_BL * 4 + off;
    }

    float acc[4][4][4];
#pragma unroll
    for (int mt = 0; mt < 4; mt++)
#pragma unroll
        for (int nt = 0; nt < 4; nt++)
#pragma unroll
            for (int q = 0; q < 4; q++) acc[mt][nt][q] = 0.f;

    for (int ks = 0; ks < 4; ks++) {
        __syncthreads();
        {
            int r = tid >> 1, half = tid & 1;
            size_t asrc = (size_t)(rowbase + l0 + r) * 64 + ks * 16 + half * 8;
            uint32_t d = sb + (uint32_t)(C_AH + r * CBW + half * 8) * 4;
            cp16(d, &g_cm2_h[asrc], true);
            cp16(d + 16, &g_cm2_h[asrc + 4], true);
            uint32_t d2 = sb + (uint32_t)(C_AL + r * CBW + half * 8) * 4;
            cp16(d2, &g_cm2_l[asrc], true);
            cp16(d2 + 16, &g_cm2_l[asrc + 4], true);
            size_t bsrc = (size_t)(rowbase + s0 + r) * 64 + ks * 16 + half * 8;
            uint32_t d3 = sb + (uint32_t)(C_BH + r * CBW + half * 8) * 4;
            cp16(d3, &g_bm2_h[bsrc], true);
            cp16(d3 + 16, &g_bm2_h[bsrc + 4], true);
            uint32_t d4 = sb + (uint32_t)(C_BL + r * CBW + half * 8) * 4;
            cp16(d4, &g_bm2_l[bsrc], true);
            cp16(d4 + 16, &g_bm2_l[bsrc + 4], true);
        }
        asm volatile("cp.async.commit_group;" ::: "memory");
        asm volatile("cp.async.wait_group 0;" ::: "memory");
        __syncthreads();
#pragma unroll
        for (int kk = 0; kk < 2; kk++) {
            uint32_t kb = kk * 32;
            uint32_t ahi[4][4], alo[4][4];
#pragma unroll
            for (int mt = 0; mt < 4; mt++) {
                ldsm4(ahi[mt], a_adh[mt] + kb);
                ldsm4(alo[mt], a_adl[mt] + kb);
            }
            uint32_t bhi[4][2], blo[4][2];
#pragma unroll
            for (int p = 0; p < 2; p++) {
                uint32_t t4[4];
                ldsm4(t4, b_adh[p] + kb);
                bhi[p * 2][0] = t4[0]; bhi[p * 2][1] = t4[1];
                bhi[p * 2 + 1][0] = t4[2]; bhi[p * 2 + 1][1] = t4[3];
                ldsm4(t4, b_adl[p] + kb);
                blo[p * 2][0] = t4[0]; blo[p * 2][1] = t4[1];
                blo[p * 2 + 1][0] = t4[2]; blo[p * 2 + 1][1] = t4[3];
            }
#pragma unroll
            for (int mt = 0; mt < 4; mt++)
#pragma unroll
                for (int nt = 0; nt < 4; nt++) {
                    mma_bf16(acc[mt][nt], ahi[mt], bhi[nt]);
                    mma_bf16(acc[mt][nt], ahi[mt], blo[nt]);
                    mma_bf16(acc[mt][nt], alo[mt], bhi[nt]);
                }
        }
    }

#pragma unroll
    for (int mt = 0; mt < 4; mt++) {
        int row = l0 + wm * 64 + mt * 16 + g;
#pragma unroll
        for (int nt = 0; nt < 4; nt++) {
            int col = s0 + wn * 32 + nt * 8 + tg * 2;
            float* a = acc[mt][nt];
            size_t i0 = ((size_t)z * CH + row) * CH + col;
            size_t i1 = ((size_t)z * CH + row + 8) * CH + col;
            g_cb[i0] = a[0]; g_cb[i0 + 1] = a[1];
            g_cb[i1] = a[2]; g_cb[i1 + 1] = a[3];
        }
    }
}

// ------ K9: Y[256,64]; interleaved causal tile mapping ------
#define YW 20
#define YA_H 0
#define YA_L (256 * YW)
#define YB_H (2 * 256 * YW)
#define YB_L (2 * 256 * YW + 64 * YW)
#define YACS (2 * 256 * YW + 2 * 64 * YW)
#define YCF  (YACS + 256)
#define YRF  (YCF + 256)
#define YSMEM ((YRF + 8 * 256) * 4)
__global__ __launch_bounds__(256) void y_tc_kernel(const float* __restrict__ Dvec) {
    extern __shared__ __align__(16) uint32_t S[];
    uint32_t* Ah = S + YA_H;
    uint32_t* Al = S + YA_L;
    uint32_t* Bh = S + YB_H;
    uint32_t* Bl = S + YB_L;
    float* acs_s = (float*)(S + YACS);
    float* cf_s = (float*)(S + YCF);
    float* rfv = (float*)(S + YRF);
    uint32_t sb = smem_u32(S);

    int bid = blockIdx.x;
    int b = bid >> 8, c = (bid >> 5) & 7, h = bid & 31;
    int z = b * NCH + c;
    int tid = threadIdx.x, warp = tid >> 5, lane = tid & 31;
    int wm = warp & 3, wn = warp >> 2;
    int g = lane >> 2, tg = lane & 3;
    int base = ((b * NH + h) * NCH + c) * CH;
    acs_s[tid] = g_acs[base + tid];
    int rowbase = b * L_ + c * CH;
    size_t initbase = (size_t)bid * HD * DS;
    int lr = tid >> 3, cg = tid & 7;

    int mat = lane >> 3, mrow = lane & 7;
    uint32_t a_adh[4], a_adl[4], b_adh[2], b_adl[2];
#pragma unroll
    for (int mt = 0; mt < 4; mt++) {
        int r = wm * 16 + mt * 64 + (mat & 1) * 8 + mrow;
        uint32_t off = (uint32_t)(r * YW + (mat >> 1) * 4) * 4;
        a_adh[mt] = sb + YA_H * 4 + off;
        a_adl[mt] = sb + YA_L * 4 + off;
    }
#pragma unroll
    for (int p = 0; p < 2; p++) {
        int n = wn * 32 + p * 16 + (mat >> 1) * 8 + mrow;
        uint32_t off = (uint32_t)(n * YW + (mat & 1) * 4) * 4;
        b_adh[p] = sb + YB_H * 4 + off;
        b_adl[p] = sb + YB_L * 4 + off;
    }

    float acc[4][4][4];
#pragma unroll
    for (int mt = 0; mt < 4; mt++)
#pragma unroll
        for (int nt = 0; nt < 4; nt++)
#pragma unroll
            for (int q = 0; q < 4; q++) acc[mt][nt][q] = 0.f;

    auto do_mma = [&](int s0) {
        bool act[4];
#pragma unroll
        for (int mt = 0; mt < 4; mt++) act[mt] = (wm * 16 + mt * 64 + 15 >= s0);
        if (!act[3]) return;
#pragma unroll
        for (int kk = 0; kk < 2; kk++) {
            uint32_t kb = kk * 32;
            uint32_t ahi[4][4], alo[4][4];
#pragma unroll
            for (int mt = 0; mt < 4; mt++)
                if (act[mt]) {
                    ldsm4(ahi[mt], a_adh[mt] + kb);
                    ldsm4(alo[mt], a_adl[mt] + kb);
                }
            uint32_t bhi[4][2], blo[4][2];
#pragma unroll
            for (int p = 0; p < 2; p++) {
                uint32_t t4[4];
                ldsm4(t4, b_adh[p] + kb);
                bhi[p * 2][0] = t4[0]; bhi[p * 2][1] = t4[1];
                bhi[p * 2 + 1][0] = t4[2]; bhi[p * 2 + 1][1] = t4[3];
                ldsm4(t4, b_adl[p] + kb);
                blo[p * 2][0] = t4[0]; blo[p * 2][1] = t4[1];
                blo[p * 2 + 1][0] = t4[2]; blo[p * 2 + 1][1] = t4[3];
            }
#pragma unroll
            for (int mt = 0; mt < 4; mt++)
                if (act[mt])
#pragma unroll
                    for (int nt = 0; nt < 4; nt++) {
                        mma_bf16(acc[mt][nt], ahi[mt], bhi[nt]);
                        mma_bf16(acc[mt][nt], ahi[mt], blo[nt]);
                        mma_bf16(acc[mt][nt], alo[mt], bhi[nt]);
                    }
        }
    };

    // ---------------- Phase 1: Cm @ init^T ----------
    for (int ks = 0; ks < 4; ks++) {
        __syncthreads();
        {
#pragma unroll
            for (int it = 0; it < 8; it++) {
                int l = it * 32 + lr;
                float4 v = *(const float4*)&g_xbc[(size_t)(rowbase + l) * CONVD +
                                                  DI + DS + ks * 32 + cg * 4];
                uint32_t* dah = &Ah[l * YW + cg * 2];
                uint32_t* dal = &Al[l * YW + cg * 2];
                dah[0] = pack_bf16(v.x, v.y);
                dah[1] = pack_bf16(v.z, v.w);
                dal[0] = pack_bf16(v.x - bf16r(v.x), v.y - bf16r(v.y));
                dal[1] = pack_bf16(v.z - bf16r(v.z), v.w - bf16r(v.w));
            }
        }
        {
            int p = tid >> 2, q0 = tid & 3;
            const float* ir = &g_init[initbase + (size_t)p * DS + ks * 32 + q0 * 8];
            float4 v0 = ((const float4*)ir)[0];
            float4 v1 = ((const float4*)ir)[1];
            uint32_t* dbh = &Bh[p * YW + q0 * 4];
            uint32_t* dbl = &Bl[p * YW + q0 * 4];
            dbh[0] = pack_bf16(v0.x, v0.y);
            dbh[1] = pack_bf16(v0.z, v0.w);
            dbh[2] = pack_bf16(v1.x, v1.y);
            dbh[3] = pack_bf16(v1.z, v1.w);
            dbl[0] = pack_bf16(v0.x - bf16r(v0.x), v0.y - bf16r(v0.y));
            dbl[1] = pack_bf16(v0.z - bf16r(v0.z), v0.w - bf16r(v0.w));
            dbl[2] = pack_bf16(v1.x - bf16r(v1.x), v1.y - bf16r(v1.y));
            dbl[3] = pack_bf16(v1.z - bf16r(v1.z), v1.w - bf16r(v1.w));
        }
        __syncthreads();
        do_mma(0);
    }

#pragma unroll
    for (int mt = 0; mt < 4; mt++) {
        int r0 = wm * 16 + mt * 64 + g;
        float e0 = __expf(acs_s[r0]);
        float e1 = __expf(acs_s[r0 + 8]);
#pragma unroll
        for (int nt = 0; nt < 4; nt++) {
            acc[mt][nt][0] *= e0; acc[mt][nt][1] *= e0;
            acc[mt][nt][2] *= e1; acc[mt][nt][3] *= e1;
        }
    }

    cf_s[tid] = __expf(acs_s[tid | 31] - acs_s[tid]);
#pragma unroll
    for (int ss = 0; ss < 8; ss++) {
        float v = 0.f;
        if (tid >= ss * 32 + 32) v = __expf(acs_s[tid] - acs_s[ss * 32 + 31]);
        rfv[ss * 256 + tid] = v;
    }

    // ---------------- Phase 2: (CB ∘ L) @ xd^T ----------
    for (int ss = 0; ss < 8; ss++) {
        int s0 = ss * 32;
        __syncthreads();
        {
            int p = tid >> 2, q = tid & 3;
            size_t src = ((size_t)bid * HD + p) * (CH / 2) + ss * 16 + q * 4;
            cp16(sb + (uint32_t)(YB_H + p * YW + q * 4) * 4, &g_xdp_h[src], true);
            cp16(sb + (uint32_t)(YB_L + p * YW + q * 4) * 4, &g_xdp_l[src], true);
            asm volatile("cp.async.commit_group;" ::: "memory");
        }
        {
            const float* rfs = &rfv[ss * 256];
#pragma unroll
            for (int it = 0; it < 8; it++) {
                int l = it * 32 + lr;
                uint32_t* dah = &Ah[l * YW + cg * 2];
                uint32_t* dal = &Al[l * YW + cg * 2];
                if (l < s0) {
                    dah[0] = 0u; dah[1] = 0u; dal[0] = 0u; dal[1] = 0u;
                    continue;
                }
                float4 cb4 = *(const float4*)&g_cb[((size_t)z * CH + l) * CH + s0 + cg * 4];
                float va, vb, vc, vd;
                int s = s0 + cg * 4;
                if (l < s0 + 32) {
                    float al = acs_s[l];
                    va = (s <= l) ? cb4.x * __expf(al - acs_s[s]) : 0.f;
                    vb = (s + 1 <= l) ? cb4.y * __expf(al - acs_s[s + 1]) : 0.f;
                    vc = (s + 2 <= l) ? cb4.z * __expf(al - acs_s[s + 2]) : 0.f;
                    vd = (s + 3 <= l) ? cb4.w * __expf(al - acs_s[s + 3]) : 0.f;
                } else {
                    float rf = rfs[l];
                    va = cb4.x * (rf * cf_s[s]);
                    vb = cb4.y * (rf * cf_s[s + 1]);
                    vc = cb4.z * (rf * cf_s[s + 2]);
                    vd = cb4.w * (rf * cf_s[s + 3]);
                }
                dah[0] = pack_bf16(va, vb);
                dah[1] = pack_bf16(vc, vd);
                dal[0] = pack_bf16(va - bf16r(va), vb - bf16r(vb));
                dal[1] = pack_bf16(vc - bf16r(vc), vd - bf16r(vd));
            }
        }
        asm volatile("cp.async.wait_group 0;" ::: "memory");
        __syncthreads();
        do_mma(s0);
    }

    // epilogue: + D*xh, write y (fp32)
    float Dh = Dvec[h];
#pragma unroll
    for (int mt = 0; mt < 4; mt++) {
        int r = wm * 16 + mt * 64 + g;
#pragma unroll
        for (int nt = 0; nt < 4; nt++) {
            int p = wn * 32 + nt * 8 + tg * 2;
            float* a = acc[mt][nt];
#pragma unroll
            for (int q = 0; q < 4; q++) {
                int row = rowbase + r + (q >> 1) * 8;
                int pp = p + (q & 1);
                float xh = g_xbc[(size_t)row * CONVD + h * HD + pp];
                g_y[(size_t)row * DI + h * HD + pp] = a[q] + Dh * xh;
            }
        }
    }
}

// -------- K10: gated rmsnorm -> bf16 hi/lo --------
__global__ void gated_norm_kernel(const float* __restrict__ gw) {
    int row = blockIdx.x, tid = threadIdx.x;
    int d0 = tid * 8;
    const float* zr = &g_zx[(size_t)row * DPROJ + d0];
    const float* yr = &g_y[(size_t)row * DI + d0];
    float v[8];
    float local = 0.f;
#pragma unroll
    for (int q = 0; q < 2; q++) {
        float4 z4 = *(const float4*)(zr + q * 4);
        float4 y4 = *(const float4*)(yr + q * 4);
        float zz[4] = {z4.x, z4.y, z4.z, z4.w};
        float yy[4] = {y4.x, y4.y, y4.z, y4.w};
#pragma unroll
        for (int j = 0; j < 4; j++) {
            float t = yy[j] * silu_f(zz[j]);
            v[q * 4 + j] = t;
            local += t * t;
        }
    }
    float tot = blockReduceSum256(local);
    float r = rsqrtf(tot / (float)DI + 1e-5f);
    int o = row * (DI / 2) + tid * 4;
#pragma unroll
    for (int j = 0; j < 4; j++) {
        float a = v[2 * j] * r * gw[d0 + 2 * j];
        float b = v[2 * j + 1] * r * gw[d0 + 2 * j + 1];
        g_yh[o + j] = pack_bf16(a, b);
        g_yl[o + j] = pack_bf16(a - bf16r(a), b - bf16r(b));
    }
}

// ---------------- launch ----------------
extern "C" void kernel_launch(void* const* d_in, const int* in_sizes, int n_in,
                              void* d_out, int out_size) {
    const float* x         = (const float*)d_in[0];
    const float* norm_w    = (const float*)d_in[1];
    const float* in_proj_w = (const float*)d_in[2];
    const float* conv_w    = (const float*)d_in[3];
    const float* conv_b    = (const float*)d_in[4];
    const float* dt_bias   = (const float*)d_in[5];
    const float* A_log     = (const float*)d_in[6];
    const float* Dv        = (const float*)d_in[7];
    const float* gnorm_w   = (const float*)d_in[8];
    const float* out_proj_w= (const float*)d_in[9];
    float* out = (float*)d_out;

    float *pzx;
    uint32_t *puh, *pul, *pyh, *pyl, *pwih, *pwil, *pwoh, *pwol;
    cudaGetSymbolAddress((void**)&pzx, g_zx);
    cudaGetSymbolAddress((void**)&puh, g_uh);
    cudaGetSymbolAddress((void**)&pul, g_ul);
    cudaGetSymbolAddress((void**)&pyh, g_yh);
    cudaGetSymbolAddress((void**)&pyl, g_yl);
    cudaGetSymbolAddress((void**)&pwih, g_wih);
    cudaGetSymbolAddress((void**)&pwil, g_wil);
    cudaGetSymbolAddress((void**)&pwoh, g_woh);
    cudaGetSymbolAddress((void**)&pwol, g_wol);

    cudaFuncSetAttribute(mma_nt_pre, cudaFuncAttributeMaxDynamicSharedMemorySize, GSMEM);
    cudaFuncSetAttribute(y_tc_kernel, cudaFuncAttributeMaxDynamicSharedMemorySize, YSMEM);
    cudaFuncSetAttribute(xdt_kernel, cudaFuncAttributeMaxDynamicSharedMemorySize, XDT_SMEM);

    cvt_pairs_kernel<<<(DPROJ * DM / 2 + 255) / 256, 256>>>(in_proj_w, pwih, pwil,
                                                            DPROJ * DM / 2);
    cvt_pairs_kernel<<<(DM * DI / 2 + 255) / 256, 256>>>(out_proj_w, pwoh, pwol,
                                                         DM * DI / 2);

    rmsnorm_x_kernel<<<ROWS, 256>>>(x, norm_w);
    mma_nt_pre<<<dim3((DPROJ + 127) / 128, ROWS / 128), 256, GSMEM>>>(
        puh, pul, pwih, pwil, pzx, nullptr, ROWS, DPROJ, DM, 0);
    conv_dt_kernel<<<(NSEG1 + NSEG2 + NSEG3) / 256, 256>>>(conv_w, conv_b, dt_bias);
    xdt_kernel<<<NBID, 256, XDT_SMEM>>>(A_log);
    states_tc_kernel<<<NBID, 256>>>();
    recur_kernel<<<(B_ * NH * HD * DS) / 256, 256>>>();
    cb_tc_kernel<<<dim3(2, 2, B_ * NCH), 256>>>();
    y_tc_kernel<<<NBID, 256, YSMEM>>>(Dv);
    gated_norm_kernel<<<ROWS, 256>>>(gnorm_w);
    mma_nt_pre<<<dim3(DM / 128, ROWS / 128), 256, GSMEM>>>(
        pyh, pyl, pwoh, pwol, out, x, ROWS, DM, DI, 1);
}